// round 2
// baseline (speedup 1.0000x reference)
#include <cuda_runtime.h>
#include <math.h>

#define BATCH   16
#define PSEQ    1024
#define NTOK    (BATCH*PSEQ)     // 16384
#define EMB     512
#define FFD     2048
#define NLAYER  4
#define NHEAD   8
#define DKH     64

// ---------------- scratch (static device globals; no runtime alloc) ----------
__device__ float g_x [NTOK*EMB];
__device__ float g_q [NTOK*EMB];
__device__ float g_k [NTOK*EMB];
__device__ float g_v [NTOK*EMB];
__device__ float g_a [NTOK*EMB];
__device__ float g_t [NTOK*EMB];
__device__ float g_h [NTOK*FFD];
__device__ float g_pe[PSEQ*EMB];

// ---------------- positional encoding table --------------------------------
// Mirrors the reference's rounding pipeline exactly:
//   freq  = fp32(exp(fp32(2*i2 * -ln(1e4)/512)))
//   angle = fp32(p * freq)
//   pe    = fp32(sin/cos(angle))   (sin/cos evaluated in fp64 of the fp32 angle)
__global__ void pe_kernel(float* __restrict__ pe) {
    int idx = blockIdx.x * blockDim.x + threadIdx.x;
    if (idx >= PSEQ*EMB) return;
    int p = idx >> 9;
    int e = idx & 511;
    int i2 = e >> 1;
    float c = (float)(2*i2) * (-0.017988946039015984f);   // -ln(10000)/512 (fp32)
    float freqf = (float)exp((double)c);
    float angf  = (float)p * freqf;
    double angle = (double)angf;
    pe[idx] = (e & 1) ? (float)cos(angle) : (float)sin(angle);
}

// ---------------- embedding: patch conv + Linear(1->E) + PE -----------------
__global__ void embed_kernel(const float* __restrict__ data,
                             const float* __restrict__ cw,
                             const float* __restrict__ cb,
                             const float* __restrict__ lw,
                             const float* __restrict__ lb,
                             const float* __restrict__ pe,
                             float* __restrict__ x) {
    int idx = blockIdx.x * blockDim.x + threadIdx.x;
    if (idx >= NTOK*EMB) return;
    int n = idx >> 9;
    int e = idx & 511;
    int b = n >> 10;
    int p = n & 1023;
    int pi = p >> 5, pj = p & 31;
    const float* dp = data + b*4096 + (pi*2)*64 + pj*2;
    float conv = dp[0]*cw[0] + dp[1]*cw[1] + dp[64]*cw[2] + dp[65]*cw[3] + cb[0];
    x[idx] = conv * lw[e] + lb[e] + pe[p*EMB + e];
}

// ---------------- NT GEMM: C[M,N] = A[M,K] @ W[N,K]^T + bias  ----------------
// BM=BN=128, BK=8, 256 threads, 8x8 register tile.
template<int RELU>
__global__ __launch_bounds__(256)
void gemm_nt(const float* __restrict__ A, const float* __restrict__ W,
             const float* __restrict__ bias, float* __restrict__ C,
             int M, int N, int K) {
    __shared__ float As[8][128];
    __shared__ float Bs[8][128];
    const int tid = threadIdx.x;
    const int tx = tid & 15;
    const int ty = tid >> 4;
    const int bx = blockIdx.x;   // N tile
    const int by = blockIdx.y;   // M tile
    const int lrow = tid >> 1;
    const int lcol = (tid & 1) * 4;

    const float* Ap = A + (size_t)(by*128 + lrow)*K + lcol;
    const float* Wp = W + (size_t)(bx*128 + lrow)*K + lcol;

    float acc[8][8];
#pragma unroll
    for (int i = 0; i < 8; i++)
#pragma unroll
        for (int j = 0; j < 8; j++) acc[i][j] = 0.f;

    float4 av = *(const float4*)(Ap);
    float4 wv = *(const float4*)(Wp);

    for (int k0 = 0; k0 < K; k0 += 8) {
        As[lcol+0][lrow] = av.x; As[lcol+1][lrow] = av.y;
        As[lcol+2][lrow] = av.z; As[lcol+3][lrow] = av.w;
        Bs[lcol+0][lrow] = wv.x; Bs[lcol+1][lrow] = wv.y;
        Bs[lcol+2][lrow] = wv.z; Bs[lcol+3][lrow] = wv.w;
        __syncthreads();

        if (k0 + 8 < K) {
            av = *(const float4*)(Ap + k0 + 8);
            wv = *(const float4*)(Wp + k0 + 8);
        }

#pragma unroll
        for (int kk = 0; kk < 8; kk++) {
            float4 a0 = *(const float4*)&As[kk][ty*8];
            float4 a1 = *(const float4*)&As[kk][ty*8+4];
            float4 b0 = *(const float4*)&Bs[kk][tx*8];
            float4 b1 = *(const float4*)&Bs[kk][tx*8+4];
            float a[8] = {a0.x,a0.y,a0.z,a0.w,a1.x,a1.y,a1.z,a1.w};
            float b[8] = {b0.x,b0.y,b0.z,b0.w,b1.x,b1.y,b1.z,b1.w};
#pragma unroll
            for (int i = 0; i < 8; i++)
#pragma unroll
                for (int j = 0; j < 8; j++)
                    acc[i][j] += a[i]*b[j];
        }
        __syncthreads();
    }

    const int colbase = bx*128 + tx*8;
#pragma unroll
    for (int i = 0; i < 8; i++) {
        int row = by*128 + ty*8 + i;
        float* Cp = C + (size_t)row*N + colbase;
        float4 o0, o1;
        o0.x = acc[i][0] + bias[colbase+0];
        o0.y = acc[i][1] + bias[colbase+1];
        o0.z = acc[i][2] + bias[colbase+2];
        o0.w = acc[i][3] + bias[colbase+3];
        o1.x = acc[i][4] + bias[colbase+4];
        o1.y = acc[i][5] + bias[colbase+5];
        o1.z = acc[i][6] + bias[colbase+6];
        o1.w = acc[i][7] + bias[colbase+7];
        if (RELU) {
            o0.x = fmaxf(o0.x, 0.f); o0.y = fmaxf(o0.y, 0.f);
            o0.z = fmaxf(o0.z, 0.f); o0.w = fmaxf(o0.w, 0.f);
            o1.x = fmaxf(o1.x, 0.f); o1.y = fmaxf(o1.y, 0.f);
            o1.z = fmaxf(o1.z, 0.f); o1.w = fmaxf(o1.w, 0.f);
        }
        *(float4*)(Cp)     = o0;
        *(float4*)(Cp + 4) = o1;
    }
}

// ---------------- fused flash attention ------------------------------------
// grid: (P/64, NH, B); 256 threads; 64-query tile, 64-key chunks.
// Q,K,V layout: [NTOK, EMB], head h occupies cols [h*64, h*64+64).
__global__ __launch_bounds__(256)
void attn_kernel(const float* __restrict__ Q, const float* __restrict__ Kt,
                 const float* __restrict__ V, float* __restrict__ O) {
    extern __shared__ float sm[];
    float* Qs   = sm;               // [64][64]
    float* KsT  = Qs  + 64*64;      // [64][65]  (d-major, padded)
    float* Vs   = KsT + 64*65;      // [64][64]
    float* Ss   = Vs  + 64*64;      // [64][65]
    float* mrow = Ss  + 64*65;      // [64]
    float* lrow = mrow + 64;        // [64]
    float* arow = lrow + 64;        // [64]

    const int tid = threadIdx.x;
    const int tx = tid & 15;
    const int ty = tid >> 4;
    const int qt = blockIdx.x, hh = blockIdx.y, bb = blockIdx.z;
    const int nbase = bb * PSEQ;
    const int hoff  = hh * DKH;
    const float scale = 0.125f;   // 1/sqrt(64)

    // load Q tile (natural layout)
#pragma unroll
    for (int it = 0; it < 4; it++) {
        int idx = tid + it*256;
        int r = idx >> 4;
        int c = (idx & 15) * 4;
        float4 qv = *(const float4*)(Q + (size_t)(nbase + qt*64 + r)*EMB + hoff + c);
        *(float4*)&Qs[r*64 + c] = qv;
    }
    if (tid < 64) { mrow[tid] = -1e30f; lrow[tid] = 0.f; }

    float o[4][4];
#pragma unroll
    for (int i = 0; i < 4; i++)
#pragma unroll
        for (int j = 0; j < 4; j++) o[i][j] = 0.f;

    for (int kc = 0; kc < 16; kc++) {
        __syncthreads();   // previous chunk's reads done / Q tile visible
        // load K chunk transposed, V natural
#pragma unroll
        for (int it = 0; it < 4; it++) {
            int idx = tid + it*256;
            int r = idx >> 4;
            int c = (idx & 15) * 4;
            const size_t roff = (size_t)(nbase + kc*64 + r)*EMB + hoff + c;
            float4 kv = *(const float4*)(Kt + roff);
            KsT[(c+0)*65 + r] = kv.x;
            KsT[(c+1)*65 + r] = kv.y;
            KsT[(c+2)*65 + r] = kv.z;
            KsT[(c+3)*65 + r] = kv.w;
            float4 vv = *(const float4*)(V + roff);
            *(float4*)&Vs[r*64 + c] = vv;
        }
        __syncthreads();

        // S tile = Q @ K^T (64x64), thread computes 4x4
        float s[4][4];
#pragma unroll
        for (int i = 0; i < 4; i++)
#pragma unroll
            for (int j = 0; j < 4; j++) s[i][j] = 0.f;
        for (int d = 0; d < 64; d++) {
            float a0 = Qs[(ty*4+0)*64 + d];
            float a1 = Qs[(ty*4+1)*64 + d];
            float a2 = Qs[(ty*4+2)*64 + d];
            float a3 = Qs[(ty*4+3)*64 + d];
            float b0 = KsT[d*65 + tx*4+0];
            float b1 = KsT[d*65 + tx*4+1];
            float b2 = KsT[d*65 + tx*4+2];
            float b3 = KsT[d*65 + tx*4+3];
            s[0][0] += a0*b0; s[0][1] += a0*b1; s[0][2] += a0*b2; s[0][3] += a0*b3;
            s[1][0] += a1*b0; s[1][1] += a1*b1; s[1][2] += a1*b2; s[1][3] += a1*b3;
            s[2][0] += a2*b0; s[2][1] += a2*b1; s[2][2] += a2*b2; s[2][3] += a2*b3;
            s[3][0] += a3*b0; s[3][1] += a3*b1; s[3][2] += a3*b2; s[3][3] += a3*b3;
        }
#pragma unroll
        for (int i = 0; i < 4; i++)
#pragma unroll
            for (int j = 0; j < 4; j++)
                Ss[(ty*4+i)*65 + tx*4+j] = s[i][j] * scale;
        __syncthreads();

        // online softmax per row (64 threads)
        if (tid < 64) {
            int r = tid;
            float mx = mrow[r];
            for (int k2 = 0; k2 < 64; k2++) mx = fmaxf(mx, Ss[r*65 + k2]);
            float ssum = 0.f;
            for (int k2 = 0; k2 < 64; k2++) {
                float pv = expf(Ss[r*65 + k2] - mx);
                Ss[r*65 + k2] = pv;
                ssum += pv;
            }
            float al = expf(mrow[r] - mx);
            lrow[r] = lrow[r]*al + ssum;
            mrow[r] = mx;
            arow[r] = al;
        }
        __syncthreads();

        // O = O*alpha + P @ V
        float al0 = arow[ty*4+0], al1 = arow[ty*4+1];
        float al2 = arow[ty*4+2], al3 = arow[ty*4+3];
#pragma unroll
        for (int j = 0; j < 4; j++) {
            o[0][j] *= al0; o[1][j] *= al1; o[2][j] *= al2; o[3][j] *= al3;
        }
        for (int k2 = 0; k2 < 64; k2++) {
            float a0 = Ss[(ty*4+0)*65 + k2];
            float a1 = Ss[(ty*4+1)*65 + k2];
            float a2 = Ss[(ty*4+2)*65 + k2];
            float a3 = Ss[(ty*4+3)*65 + k2];
            float b0 = Vs[k2*64 + tx*4+0];
            float b1 = Vs[k2*64 + tx*4+1];
            float b2 = Vs[k2*64 + tx*4+2];
            float b3 = Vs[k2*64 + tx*4+3];
            o[0][0] += a0*b0; o[0][1] += a0*b1; o[0][2] += a0*b2; o[0][3] += a0*b3;
            o[1][0] += a1*b0; o[1][1] += a1*b1; o[1][2] += a1*b2; o[1][3] += a1*b3;
            o[2][0] += a2*b0; o[2][1] += a2*b1; o[2][2] += a2*b2; o[2][3] += a2*b3;
            o[3][0] += a3*b0; o[3][1] += a3*b1; o[3][2] += a3*b2; o[3][3] += a3*b3;
        }
    }

    // epilogue: divide by l, write out
#pragma unroll
    for (int i = 0; i < 4; i++) {
        float inv = 1.f / lrow[ty*4+i];
        float4 ov;
        ov.x = o[i][0]*inv; ov.y = o[i][1]*inv;
        ov.z = o[i][2]*inv; ov.w = o[i][3]*inv;
        *(float4*)&O[(size_t)(nbase + qt*64 + ty*4+i)*EMB + hoff + tx*4] = ov;
    }
}

// ---------------- residual add + LayerNorm ----------------------------------
__global__ __launch_bounds__(128)
void add_ln_kernel(float* __restrict__ x, const float* __restrict__ y,
                   const float* __restrict__ gam, const float* __restrict__ bet) {
    const int row = blockIdx.x;
    const int tid = threadIdx.x;
    const int e = tid * 4;
    float4 xv = *(float4*)&x[(size_t)row*EMB + e];
    float4 yv = *(const float4*)&y[(size_t)row*EMB + e];
    float t0 = xv.x + yv.x, t1 = xv.y + yv.y, t2 = xv.z + yv.z, t3 = xv.w + yv.w;
    float s  = t0 + t1 + t2 + t3;
    float s2 = t0*t0 + t1*t1 + t2*t2 + t3*t3;
#pragma unroll
    for (int off = 16; off > 0; off >>= 1) {
        s  += __shfl_xor_sync(0xffffffffu, s,  off);
        s2 += __shfl_xor_sync(0xffffffffu, s2, off);
    }
    __shared__ float ws[4], ws2[4];
    int w = tid >> 5;
    if ((tid & 31) == 0) { ws[w] = s; ws2[w] = s2; }
    __syncthreads();
    float S  = ws[0] + ws[1] + ws[2] + ws[3];
    float S2 = ws2[0] + ws2[1] + ws2[2] + ws2[3];
    float mu  = S * (1.f/512.f);
    float var = S2 * (1.f/512.f) - mu*mu;
    float rs = rsqrtf(var + 1e-5f);
    float4 ov;
    ov.x = (t0 - mu)*rs*gam[e+0] + bet[e+0];
    ov.y = (t1 - mu)*rs*gam[e+1] + bet[e+1];
    ov.z = (t2 - mu)*rs*gam[e+2] + bet[e+2];
    ov.w = (t3 - mu)*rs*gam[e+3] + bet[e+3];
    *(float4*)&x[(size_t)row*EMB + e] = ov;
}

// ---------------- mean pool + final linear ----------------------------------
__global__ __launch_bounds__(512)
void pool_head_kernel(const float* __restrict__ x, const float* __restrict__ Wc,
                      const float* __restrict__ bc, float* __restrict__ out) {
    const int b = blockIdx.x;
    const int e = threadIdx.x;
    float s = 0.f;
    const float* xp = x + (size_t)b*PSEQ*EMB + e;
    for (int p = 0; p < PSEQ; p++) s += xp[(size_t)p*EMB];
    float pooled = s * (1.f/1024.f);
    __shared__ float red[512];
    red[e] = pooled * Wc[e];
    __syncthreads();
    for (int st = 256; st > 0; st >>= 1) {
        if (e < st) red[e] += red[e + st];
        __syncthreads();
    }
    if (e == 0) out[b] = red[0] + bc[0];
}

// ---------------- driver -----------------------------------------------------
extern "C" void kernel_launch(void* const* d_in, const int* in_sizes, int n_in,
                              void* d_out, int out_size) {
    const float* data   = (const float*)d_in[0];
    const float* conv_w = (const float*)d_in[1];
    const float* conv_b = (const float*)d_in[2];
    const float* lin_w  = (const float*)d_in[3];
    const float* lin_b  = (const float*)d_in[4];
    const float* Wq     = (const float*)d_in[5];
    const float* bq     = (const float*)d_in[6];
    const float* Wk     = (const float*)d_in[7];
    const float* bk     = (const float*)d_in[8];
    const float* Wv     = (const float*)d_in[9];
    const float* bv     = (const float*)d_in[10];
    const float* Wo     = (const float*)d_in[11];
    const float* bo     = (const float*)d_in[12];
    const float* ln1_g  = (const float*)d_in[13];
    const float* ln1_b  = (const float*)d_in[14];
    const float* ln2_g  = (const float*)d_in[15];
    const float* ln2_b  = (const float*)d_in[16];
    const float* W1     = (const float*)d_in[17];
    const float* b1     = (const float*)d_in[18];
    const float* W2     = (const float*)d_in[19];
    const float* b2     = (const float*)d_in[20];
    const float* Wc     = (const float*)d_in[21];
    const float* bc     = (const float*)d_in[22];
    float* out = (float*)d_out;

    float *px, *pq, *pk, *pv, *pa, *pt, *ph, *ppe;
    cudaGetSymbolAddress((void**)&px,  g_x);
    cudaGetSymbolAddress((void**)&pq,  g_q);
    cudaGetSymbolAddress((void**)&pk,  g_k);
    cudaGetSymbolAddress((void**)&pv,  g_v);
    cudaGetSymbolAddress((void**)&pa,  g_a);
    cudaGetSymbolAddress((void**)&pt,  g_t);
    cudaGetSymbolAddress((void**)&ph,  g_h);
    cudaGetSymbolAddress((void**)&ppe, g_pe);

    const int ATT_SMEM = (64*64 + 64*65 + 64*64 + 64*65 + 3*64) * 4;
    cudaFuncSetAttribute(attn_kernel, cudaFuncAttributeMaxDynamicSharedMemorySize, ATT_SMEM);

    pe_kernel<<<(PSEQ*EMB + 255)/256, 256>>>(ppe);
    embed_kernel<<<(NTOK*EMB + 255)/256, 256>>>(data, conv_w, conv_b, lin_w, lin_b, ppe, px);

    for (int l = 0; l < NLAYER; l++) {
        const float* wq = Wq + (size_t)l*EMB*EMB;
        const float* wk = Wk + (size_t)l*EMB*EMB;
        const float* wv = Wv + (size_t)l*EMB*EMB;
        const float* wo = Wo + (size_t)l*EMB*EMB;
        const float* w1 = W1 + (size_t)l*FFD*EMB;
        const float* w2 = W2 + (size_t)l*EMB*FFD;

        dim3 gE(EMB/128, NTOK/128);
        dim3 gF(FFD/128, NTOK/128);

        gemm_nt<0><<<gE, 256>>>(px, wq, bq + l*EMB, pq, NTOK, EMB, EMB);
        gemm_nt<0><<<gE, 256>>>(px, wk, bk + l*EMB, pk, NTOK, EMB, EMB);
        gemm_nt<0><<<gE, 256>>>(px, wv, bv + l*EMB, pv, NTOK, EMB, EMB);

        attn_kernel<<<dim3(PSEQ/64, NHEAD, BATCH), 256, ATT_SMEM>>>(pq, pk, pv, pa);

        gemm_nt<0><<<gE, 256>>>(pa, wo, bo + l*EMB, pt, NTOK, EMB, EMB);
        add_ln_kernel<<<NTOK, 128>>>(px, pt, ln1_g + l*EMB, ln1_b + l*EMB);

        gemm_nt<1><<<gF, 256>>>(px, w1, b1 + l*FFD, ph, NTOK, FFD, EMB);
        gemm_nt<0><<<gE, 256>>>(ph, w2, b2 + l*EMB, pt, NTOK, EMB, FFD);
        add_ln_kernel<<<NTOK, 128>>>(px, pt, ln2_g + l*EMB, ln2_b + l*EMB);
    }

    pool_head_kernel<<<BATCH, 512>>>(px, Wc, bc, out);
}

// round 4
// speedup vs baseline: 1.5465x; 1.5465x over previous
#include <cuda_runtime.h>
#include <cuda_bf16.h>
#include <math.h>
#include <stdint.h>

#define BATCH   16
#define PSEQ    1024
#define NTOK    (BATCH*PSEQ)     // 16384
#define EMB     512
#define FFD     2048
#define NLAYER  4
#define NHEAD   8
#define DKH     64

// ---------------- scratch (static device globals; no runtime alloc) ----------
__device__ float g_x [NTOK*EMB];
__device__ float g_q [NTOK*EMB];
__device__ float g_k [NTOK*EMB];
__device__ float g_v [NTOK*EMB];
__device__ float g_a [NTOK*EMB];
__device__ float g_t [NTOK*EMB];
__device__ float g_h [NTOK*FFD];
__device__ float g_pe[PSEQ*EMB];

// ============================================================================
// helpers
// ============================================================================
static __device__ __forceinline__ uint32_t smem_u32(const void* p) {
    uint32_t a;
    asm("{ .reg .u64 t; cvta.to.shared.u64 t, %1; cvt.u32.u64 %0, t; }"
        : "=r"(a) : "l"(p));
    return a;
}
static __device__ __forceinline__ uint32_t pack_hi(float a, float b, float& ra, float& rb) {
    __nv_bfloat16 ha = __float2bfloat16(a);
    __nv_bfloat16 hb = __float2bfloat16(b);
    ra = a - __bfloat162float(ha);
    rb = b - __bfloat162float(hb);
    return (uint32_t)__bfloat16_as_ushort(ha) | ((uint32_t)__bfloat16_as_ushort(hb) << 16);
}
static __device__ __forceinline__ uint32_t pack_lo(float a, float b) {
    return (uint32_t)__bfloat16_as_ushort(__float2bfloat16(a)) |
           ((uint32_t)__bfloat16_as_ushort(__float2bfloat16(b)) << 16);
}

#define MMA_BF16(d, a, b) \
    asm volatile("mma.sync.aligned.m16n8k16.row.col.f32.bf16.bf16.f32 " \
        "{%0,%1,%2,%3}, {%4,%5,%6,%7}, {%8,%9}, {%0,%1,%2,%3};" \
        : "+f"((d)[0]), "+f"((d)[1]), "+f"((d)[2]), "+f"((d)[3]) \
        : "r"((a)[0]), "r"((a)[1]), "r"((a)[2]), "r"((a)[3]), \
          "r"((b)[0]), "r"((b)[1]))

#define LDSM4(r, addr) \
    asm volatile("ldmatrix.sync.aligned.m8n8.x4.shared.b16 {%0,%1,%2,%3}, [%4];" \
        : "=r"((r)[0]), "=r"((r)[1]), "=r"((r)[2]), "=r"((r)[3]) : "r"(addr))

#define LDSM2(r, addr) \
    asm volatile("ldmatrix.sync.aligned.m8n8.x2.shared.b16 {%0,%1}, [%2];" \
        : "=r"((r)[0]), "=r"((r)[1]) : "r"(addr))

// ============================================================================
// HMMA bf16-split NT GEMM: C[M,N] = A[M,K] @ W[N,K]^T + bias
// BM=BN=128, BK=32. 256 threads = 4(M) x 2(N) warps; warp tile 32x64.
// Split x = hi + lo (bf16 each); accumulate hi*hi + hi*lo + lo*hi in fp32.
// Smem row stride 40 bf16 (80B) -> conflict-free ldmatrix.
// ============================================================================
#define SROW 20   // row stride in u32 (40 bf16)

template<int RELU>
__global__ __launch_bounds__(256, 1)
void gemm_mma(const float* __restrict__ A, const float* __restrict__ W,
              const float* __restrict__ bias, float* __restrict__ C,
              int M, int N, int K) {
    __shared__ __align__(16) uint32_t sAhi[128*SROW], sAlo[128*SROW];
    __shared__ __align__(16) uint32_t sWhi[128*SROW], sWlo[128*SROW];

    const int tid  = threadIdx.x;
    const int lane = tid & 31;
    const int wid  = tid >> 5;
    const int wm   = wid & 3;     // 0..3  (M)
    const int wn   = wid >> 2;    // 0..1  (N)
    const int bx   = blockIdx.x, by = blockIdx.y;

    // global load mapping: thread -> rows (tid/8 + 32*i), float4 col tid%8
    const int lr  = tid >> 3;
    const int lc4 = tid & 7;
    const float* Ap = A + (size_t)(by*128 + lr)*K + lc4*4;
    const float* Wp = W + (size_t)(bx*128 + lr)*K + lc4*4;

    float acc[2][8][4];
#pragma unroll
    for (int i = 0; i < 2; i++)
#pragma unroll
        for (int j = 0; j < 8; j++)
#pragma unroll
            for (int q = 0; q < 4; q++) acc[i][j][q] = 0.f;

    // ldmatrix per-lane addresses (bytes)
    const uint32_t aHiB = smem_u32(sAhi), aLoB = smem_u32(sAlo);
    const uint32_t wHiB = smem_u32(sWhi), wLoB = smem_u32(sWlo);
    const uint32_t offA = (uint32_t)((wm*32 + (lane & 15)) * 80 + (lane >> 4) * 16);
    const int l16 = lane & 15;
    const uint32_t offB = (uint32_t)((wn*64 + (l16 & 7)) * 80 + (l16 >> 3) * 16);

    const int KT = K >> 5;

    float4 av[4], wv[4];
#pragma unroll
    for (int i = 0; i < 4; i++) {
        av[i] = *(const float4*)(Ap + (size_t)(32*i)*K);
        wv[i] = *(const float4*)(Wp + (size_t)(32*i)*K);
    }

    for (int kt = 0; kt < KT; kt++) {
        // split + store to smem
#pragma unroll
        for (int i = 0; i < 4; i++) {
            const uint32_t o = (uint32_t)((lr + 32*i) * SROW + lc4 * 2);
            float r0, r1, r2, r3;
            uint32_t h01 = pack_hi(av[i].x, av[i].y, r0, r1);
            uint32_t h23 = pack_hi(av[i].z, av[i].w, r2, r3);
            sAhi[o] = h01; sAhi[o+1] = h23;
            sAlo[o] = pack_lo(r0, r1); sAlo[o+1] = pack_lo(r2, r3);
            h01 = pack_hi(wv[i].x, wv[i].y, r0, r1);
            h23 = pack_hi(wv[i].z, wv[i].w, r2, r3);
            sWhi[o] = h01; sWhi[o+1] = h23;
            sWlo[o] = pack_lo(r0, r1); sWlo[o+1] = pack_lo(r2, r3);
        }
        __syncthreads();

        if (kt + 1 < KT) {
            const int ko = (kt + 1) * 32;
#pragma unroll
            for (int i = 0; i < 4; i++) {
                av[i] = *(const float4*)(Ap + (size_t)(32*i)*K + ko);
                wv[i] = *(const float4*)(Wp + (size_t)(32*i)*K + ko);
            }
        }

#pragma unroll
        for (int kk = 0; kk < 2; kk++) {
            const uint32_t dk = (uint32_t)(kk * 32);
            uint32_t ah[2][4], al[2][4];
#pragma unroll
            for (int mt = 0; mt < 2; mt++) {
                LDSM4(ah[mt], aHiB + offA + (uint32_t)(mt * 16 * 80) + dk);
                LDSM4(al[mt], aLoB + offA + (uint32_t)(mt * 16 * 80) + dk);
            }
#pragma unroll
            for (int nt = 0; nt < 8; nt++) {
                uint32_t bh[2], bl[2];
                const uint32_t bo = offB + (uint32_t)(nt * 8 * 80) + dk;
                LDSM2(bh, wHiB + bo);
                LDSM2(bl, wLoB + bo);
#pragma unroll
                for (int mt = 0; mt < 2; mt++) {
                    MMA_BF16(acc[mt][nt], ah[mt], bh);
                    MMA_BF16(acc[mt][nt], ah[mt], bl);
                    MMA_BF16(acc[mt][nt], al[mt], bh);
                }
            }
        }
        __syncthreads();
    }

    // epilogue: c0,c1 -> (row, col..col+1); c2,c3 -> (row+8, col..col+1)
    const int rbase = by*128 + wm*32 + (lane >> 2);
    const int cbase = bx*128 + wn*64 + 2*(lane & 3);
#pragma unroll
    for (int mt = 0; mt < 2; mt++) {
#pragma unroll
        for (int nt = 0; nt < 8; nt++) {
            const int row = rbase + mt*16;
            const int col = cbase + nt*8;
            const float b0 = bias[col], b1 = bias[col+1];
            float2 v0, v1;
            v0.x = acc[mt][nt][0] + b0; v0.y = acc[mt][nt][1] + b1;
            v1.x = acc[mt][nt][2] + b0; v1.y = acc[mt][nt][3] + b1;
            if (RELU) {
                v0.x = fmaxf(v0.x, 0.f); v0.y = fmaxf(v0.y, 0.f);
                v1.x = fmaxf(v1.x, 0.f); v1.y = fmaxf(v1.y, 0.f);
            }
            *(float2*)(C + (size_t)row*N + col)       = v0;
            *(float2*)(C + (size_t)(row+8)*N + col)   = v1;
        }
    }
}

// ---------------- positional encoding table --------------------------------
__global__ void pe_kernel(float* __restrict__ pe) {
    int idx = blockIdx.x * blockDim.x + threadIdx.x;
    if (idx >= PSEQ*EMB) return;
    int p = idx >> 9;
    int e = idx & 511;
    int i2 = e >> 1;
    float c = (float)(2*i2) * (-0.017988946039015984f);   // -ln(10000)/512 (fp32)
    float freqf = (float)exp((double)c);
    float angf  = (float)p * freqf;
    double angle = (double)angf;
    pe[idx] = (e & 1) ? (float)cos(angle) : (float)sin(angle);
}

// ---------------- embedding: patch conv + Linear(1->E) + PE -----------------
__global__ void embed_kernel(const float* __restrict__ data,
                             const float* __restrict__ cw,
                             const float* __restrict__ cb,
                             const float* __restrict__ lw,
                             const float* __restrict__ lb,
                             const float* __restrict__ pe,
                             float* __restrict__ x) {
    int idx = blockIdx.x * blockDim.x + threadIdx.x;
    if (idx >= NTOK*EMB) return;
    int n = idx >> 9;
    int e = idx & 511;
    int b = n >> 10;
    int p = n & 1023;
    int pi = p >> 5, pj = p & 31;
    const float* dp = data + b*4096 + (pi*2)*64 + pj*2;
    float conv = dp[0]*cw[0] + dp[1]*cw[1] + dp[64]*cw[2] + dp[65]*cw[3] + cb[0];
    x[idx] = conv * lw[e] + lb[e] + pe[p*EMB + e];
}

// ---------------- fused flash attention (fp32) -------------------------------
__global__ __launch_bounds__(256)
void attn_kernel(const float* __restrict__ Q, const float* __restrict__ Kt,
                 const float* __restrict__ V, float* __restrict__ O) {
    extern __shared__ float sm[];
    float* Qs   = sm;               // [64][64]
    float* KsT  = Qs  + 64*64;      // [64][65]
    float* Vs   = KsT + 64*65;      // [64][64]
    float* Ss   = Vs  + 64*64;      // [64][65]
    float* mrow = Ss  + 64*65;
    float* lrow = mrow + 64;
    float* arow = lrow + 64;

    const int tid = threadIdx.x;
    const int tx = tid & 15;
    const int ty = tid >> 4;
    const int qt = blockIdx.x, hh = blockIdx.y, bb = blockIdx.z;
    const int nbase = bb * PSEQ;
    const int hoff  = hh * DKH;
    const float scale = 0.125f;

#pragma unroll
    for (int it = 0; it < 4; it++) {
        int idx = tid + it*256;
        int r = idx >> 4;
        int c = (idx & 15) * 4;
        float4 qv = *(const float4*)(Q + (size_t)(nbase + qt*64 + r)*EMB + hoff + c);
        *(float4*)&Qs[r*64 + c] = qv;
    }
    if (tid < 64) { mrow[tid] = -1e30f; lrow[tid] = 0.f; }

    float o[4][4];
#pragma unroll
    for (int i = 0; i < 4; i++)
#pragma unroll
        for (int j = 0; j < 4; j++) o[i][j] = 0.f;

    for (int kc = 0; kc < 16; kc++) {
        __syncthreads();
#pragma unroll
        for (int it = 0; it < 4; it++) {
            int idx = tid + it*256;
            int r = idx >> 4;
            int c = (idx & 15) * 4;
            const size_t roff = (size_t)(nbase + kc*64 + r)*EMB + hoff + c;
            float4 kv = *(const float4*)(Kt + roff);
            KsT[(c+0)*65 + r] = kv.x;
            KsT[(c+1)*65 + r] = kv.y;
            KsT[(c+2)*65 + r] = kv.z;
            KsT[(c+3)*65 + r] = kv.w;
            float4 vv = *(const float4*)(V + roff);
            *(float4*)&Vs[r*64 + c] = vv;
        }
        __syncthreads();

        float s[4][4];
#pragma unroll
        for (int i = 0; i < 4; i++)
#pragma unroll
            for (int j = 0; j < 4; j++) s[i][j] = 0.f;
        for (int d = 0; d < 64; d++) {
            float a0 = Qs[(ty*4+0)*64 + d];
            float a1 = Qs[(ty*4+1)*64 + d];
            float a2 = Qs[(ty*4+2)*64 + d];
            float a3 = Qs[(ty*4+3)*64 + d];
            float b0 = KsT[d*65 + tx*4+0];
            float b1 = KsT[d*65 + tx*4+1];
            float b2 = KsT[d*65 + tx*4+2];
            float b3 = KsT[d*65 + tx*4+3];
            s[0][0] += a0*b0; s[0][1] += a0*b1; s[0][2] += a0*b2; s[0][3] += a0*b3;
            s[1][0] += a1*b0; s[1][1] += a1*b1; s[1][2] += a1*b2; s[1][3] += a1*b3;
            s[2][0] += a2*b0; s[2][1] += a2*b1; s[2][2] += a2*b2; s[2][3] += a2*b3;
            s[3][0] += a3*b0; s[3][1] += a3*b1; s[3][2] += a3*b2; s[3][3] += a3*b3;
        }
#pragma unroll
        for (int i = 0; i < 4; i++)
#pragma unroll
            for (int j = 0; j < 4; j++)
                Ss[(ty*4+i)*65 + tx*4+j] = s[i][j] * scale;
        __syncthreads();

        if (tid < 64) {
            int r = tid;
            float mx = mrow[r];
            for (int k2 = 0; k2 < 64; k2++) mx = fmaxf(mx, Ss[r*65 + k2]);
            float ssum = 0.f;
            for (int k2 = 0; k2 < 64; k2++) {
                float pv = expf(Ss[r*65 + k2] - mx);
                Ss[r*65 + k2] = pv;
                ssum += pv;
            }
            float al = expf(mrow[r] - mx);
            lrow[r] = lrow[r]*al + ssum;
            mrow[r] = mx;
            arow[r] = al;
        }
        __syncthreads();

        float al0 = arow[ty*4+0], al1 = arow[ty*4+1];
        float al2 = arow[ty*4+2], al3 = arow[ty*4+3];
#pragma unroll
        for (int j = 0; j < 4; j++) {
            o[0][j] *= al0; o[1][j] *= al1; o[2][j] *= al2; o[3][j] *= al3;
        }
        for (int k2 = 0; k2 < 64; k2++) {
            float a0 = Ss[(ty*4+0)*65 + k2];
            float a1 = Ss[(ty*4+1)*65 + k2];
            float a2 = Ss[(ty*4+2)*65 + k2];
            float a3 = Ss[(ty*4+3)*65 + k2];
            float b0 = Vs[k2*64 + tx*4+0];
            float b1 = Vs[k2*64 + tx*4+1];
            float b2 = Vs[k2*64 + tx*4+2];
            float b3 = Vs[k2*64 + tx*4+3];
            o[0][0] += a0*b0; o[0][1] += a0*b1; o[0][2] += a0*b2; o[0][3] += a0*b3;
            o[1][0] += a1*b0; o[1][1] += a1*b1; o[1][2] += a1*b2; o[1][3] += a1*b3;
            o[2][0] += a2*b0; o[2][1] += a2*b1; o[2][2] += a2*b2; o[2][3] += a2*b3;
            o[3][0] += a3*b0; o[3][1] += a3*b1; o[3][2] += a3*b2; o[3][3] += a3*b3;
        }
    }

#pragma unroll
    for (int i = 0; i < 4; i++) {
        float inv = 1.f / lrow[ty*4+i];
        float4 ov;
        ov.x = o[i][0]*inv; ov.y = o[i][1]*inv;
        ov.z = o[i][2]*inv; ov.w = o[i][3]*inv;
        *(float4*)&O[(size_t)(nbase + qt*64 + ty*4+i)*EMB + hoff + tx*4] = ov;
    }
}

// ---------------- residual add + LayerNorm ----------------------------------
__global__ __launch_bounds__(128)
void add_ln_kernel(float* __restrict__ x, const float* __restrict__ y,
                   const float* __restrict__ gam, const float* __restrict__ bet) {
    const int row = blockIdx.x;
    const int tid = threadIdx.x;
    const int e = tid * 4;
    float4 xv = *(float4*)&x[(size_t)row*EMB + e];
    float4 yv = *(const float4*)&y[(size_t)row*EMB + e];
    float t0 = xv.x + yv.x, t1 = xv.y + yv.y, t2 = xv.z + yv.z, t3 = xv.w + yv.w;
    float s  = t0 + t1 + t2 + t3;
    float s2 = t0*t0 + t1*t1 + t2*t2 + t3*t3;
#pragma unroll
    for (int off = 16; off > 0; off >>= 1) {
        s  += __shfl_xor_sync(0xffffffffu, s,  off);
        s2 += __shfl_xor_sync(0xffffffffu, s2, off);
    }
    __shared__ float ws[4], ws2[4];
    int w = tid >> 5;
    if ((tid & 31) == 0) { ws[w] = s; ws2[w] = s2; }
    __syncthreads();
    float S  = ws[0] + ws[1] + ws[2] + ws[3];
    float S2 = ws2[0] + ws2[1] + ws2[2] + ws2[3];
    float mu  = S * (1.f/512.f);
    float var = S2 * (1.f/512.f) - mu*mu;
    float rs = rsqrtf(var + 1e-5f);
    float4 ov;
    ov.x = (t0 - mu)*rs*gam[e+0] + bet[e+0];
    ov.y = (t1 - mu)*rs*gam[e+1] + bet[e+1];
    ov.z = (t2 - mu)*rs*gam[e+2] + bet[e+2];
    ov.w = (t3 - mu)*rs*gam[e+3] + bet[e+3];
    *(float4*)&x[(size_t)row*EMB + e] = ov;
}

// ---------------- mean pool + final linear ----------------------------------
__global__ __launch_bounds__(512)
void pool_head_kernel(const float* __restrict__ x, const float* __restrict__ Wc,
                      const float* __restrict__ bc, float* __restrict__ out) {
    const int b = blockIdx.x;
    const int e = threadIdx.x;
    float s = 0.f;
    const float* xp = x + (size_t)b*PSEQ*EMB + e;
    for (int p = 0; p < PSEQ; p++) s += xp[(size_t)p*EMB];
    float pooled = s * (1.f/1024.f);
    __shared__ float red[512];
    red[e] = pooled * Wc[e];
    __syncthreads();
    for (int st = 256; st > 0; st >>= 1) {
        if (e < st) red[e] += red[e + st];
        __syncthreads();
    }
    if (e == 0) out[b] = red[0] + bc[0];
}

// ---------------- driver -----------------------------------------------------
extern "C" void kernel_launch(void* const* d_in, const int* in_sizes, int n_in,
                              void* d_out, int out_size) {
    const float* data   = (const float*)d_in[0];
    const float* conv_w = (const float*)d_in[1];
    const float* conv_b = (const float*)d_in[2];
    const float* lin_w  = (const float*)d_in[3];
    const float* lin_b  = (const float*)d_in[4];
    const float* Wq     = (const float*)d_in[5];
    const float* bq     = (const float*)d_in[6];
    const float* Wk     = (const float*)d_in[7];
    const float* bk     = (const float*)d_in[8];
    const float* Wv     = (const float*)d_in[9];
    const float* bv     = (const float*)d_in[10];
    const float* Wo     = (const float*)d_in[11];
    const float* bo     = (const float*)d_in[12];
    const float* ln1_g  = (const float*)d_in[13];
    const float* ln1_b  = (const float*)d_in[14];
    const float* ln2_g  = (const float*)d_in[15];
    const float* ln2_b  = (const float*)d_in[16];
    const float* W1     = (const float*)d_in[17];
    const float* b1     = (const float*)d_in[18];
    const float* W2     = (const float*)d_in[19];
    const float* b2     = (const float*)d_in[20];
    const float* Wc     = (const float*)d_in[21];
    const float* bc     = (const float*)d_in[22];
    float* out = (float*)d_out;

    float *px, *pq, *pk, *pv, *pa, *pt, *ph, *ppe;
    cudaGetSymbolAddress((void**)&px,  g_x);
    cudaGetSymbolAddress((void**)&pq,  g_q);
    cudaGetSymbolAddress((void**)&pk,  g_k);
    cudaGetSymbolAddress((void**)&pv,  g_v);
    cudaGetSymbolAddress((void**)&pa,  g_a);
    cudaGetSymbolAddress((void**)&pt,  g_t);
    cudaGetSymbolAddress((void**)&ph,  g_h);
    cudaGetSymbolAddress((void**)&ppe, g_pe);

    const int ATT_SMEM = (64*64 + 64*65 + 64*64 + 64*65 + 3*64) * 4;
    cudaFuncSetAttribute(attn_kernel, cudaFuncAttributeMaxDynamicSharedMemorySize, ATT_SMEM);

    pe_kernel<<<(PSEQ*EMB + 255)/256, 256>>>(ppe);
    embed_kernel<<<(NTOK*EMB + 255)/256, 256>>>(data, conv_w, conv_b, lin_w, lin_b, ppe, px);

    for (int l = 0; l < NLAYER; l++) {
        const float* wq = Wq + (size_t)l*EMB*EMB;
        const float* wk = Wk + (size_t)l*EMB*EMB;
        const float* wv = Wv + (size_t)l*EMB*EMB;
        const float* wo = Wo + (size_t)l*EMB*EMB;
        const float* w1 = W1 + (size_t)l*FFD*EMB;
        const float* w2 = W2 + (size_t)l*EMB*FFD;

        dim3 gE(EMB/128, NTOK/128);
        dim3 gF(FFD/128, NTOK/128);

        gemm_mma<0><<<gE, 256>>>(px, wq, bq + l*EMB, pq, NTOK, EMB, EMB);
        gemm_mma<0><<<gE, 256>>>(px, wk, bk + l*EMB, pk, NTOK, EMB, EMB);
        gemm_mma<0><<<gE, 256>>>(px, wv, bv + l*EMB, pv, NTOK, EMB, EMB);

        attn_kernel<<<dim3(PSEQ/64, NHEAD, BATCH), 256, ATT_SMEM>>>(pq, pk, pv, pa);

        gemm_mma<0><<<gE, 256>>>(pa, wo, bo + l*EMB, pt, NTOK, EMB, EMB);
        add_ln_kernel<<<NTOK, 128>>>(px, pt, ln1_g + l*EMB, ln1_b + l*EMB);

        gemm_mma<1><<<gF, 256>>>(px, w1, b1 + l*FFD, ph, NTOK, FFD, EMB);
        gemm_mma<0><<<gE, 256>>>(ph, w2, b2 + l*EMB, pt, NTOK, EMB, FFD);
        add_ln_kernel<<<NTOK, 128>>>(px, pt, ln2_g + l*EMB, ln2_b + l*EMB);
    }

    pool_head_kernel<<<BATCH, 512>>>(px, Wc, bc, out);
}

// round 5
// speedup vs baseline: 1.9863x; 1.2844x over previous
#include <cuda_runtime.h>
#include <cuda_bf16.h>
#include <math.h>
#include <stdint.h>

#define BATCH   16
#define PSEQ    1024
#define NTOK    (BATCH*PSEQ)     // 16384
#define EMB     512
#define FFD     2048
#define NLAYER  4
#define NHEAD   8
#define DKH     64

// ---------------- scratch (static device globals; no runtime alloc) ----------
__device__ float g_x [NTOK*EMB];
__device__ float g_q [NTOK*EMB];
__device__ float g_k [NTOK*EMB];
__device__ float g_v [NTOK*EMB];
__device__ float g_a [NTOK*EMB];
__device__ float g_t [NTOK*EMB];
__device__ float g_h [NTOK*FFD];
__device__ float g_pe[PSEQ*EMB];

// ============================================================================
// helpers
// ============================================================================
static __device__ __forceinline__ uint32_t smem_u32(const void* p) {
    uint32_t a;
    asm("{ .reg .u64 t; cvta.to.shared.u64 t, %1; cvt.u32.u64 %0, t; }"
        : "=r"(a) : "l"(p));
    return a;
}
static __device__ __forceinline__ uint32_t pack_hi(float a, float b, float& ra, float& rb) {
    __nv_bfloat16 ha = __float2bfloat16(a);
    __nv_bfloat16 hb = __float2bfloat16(b);
    ra = a - __bfloat162float(ha);
    rb = b - __bfloat162float(hb);
    return (uint32_t)__bfloat16_as_ushort(ha) | ((uint32_t)__bfloat16_as_ushort(hb) << 16);
}
static __device__ __forceinline__ uint32_t pack_lo(float a, float b) {
    return (uint32_t)__bfloat16_as_ushort(__float2bfloat16(a)) |
           ((uint32_t)__bfloat16_as_ushort(__float2bfloat16(b)) << 16);
}

#define MMA_BF16(d, a, b) \
    asm volatile("mma.sync.aligned.m16n8k16.row.col.f32.bf16.bf16.f32 " \
        "{%0,%1,%2,%3}, {%4,%5,%6,%7}, {%8,%9}, {%0,%1,%2,%3};" \
        : "+f"((d)[0]), "+f"((d)[1]), "+f"((d)[2]), "+f"((d)[3]) \
        : "r"((a)[0]), "r"((a)[1]), "r"((a)[2]), "r"((a)[3]), \
          "r"((b)[0]), "r"((b)[1]))

#define LDSM4(r, addr) \
    asm volatile("ldmatrix.sync.aligned.m8n8.x4.shared.b16 {%0,%1,%2,%3}, [%4];" \
        : "=r"((r)[0]), "=r"((r)[1]), "=r"((r)[2]), "=r"((r)[3]) : "r"(addr))

#define LDSM2(r, addr) \
    asm volatile("ldmatrix.sync.aligned.m8n8.x2.shared.b16 {%0,%1}, [%2];" \
        : "=r"((r)[0]), "=r"((r)[1]) : "r"(addr))

// ============================================================================
// HMMA bf16-split NT GEMM, double-buffered: C = A[M,K] @ W[N,K]^T + bias
// BM=BN=128, BK=32. 256 threads = 4(M) x 2(N) warps; warp tile 32x64.
// Dynamic smem: 2 buffers x (Ahi|Alo|Whi|Wlo), each 128x20 u32 (row stride 80B).
// ============================================================================
#define SROW 20                     // row stride in u32 (40 bf16 = 80B)
#define GBUF_U32 10240              // one buffer set in u32 (4 * 128*20)
#define GSMEM_BYTES (2*GBUF_U32*4)  // 81920

template<int RELU>
__global__ __launch_bounds__(256, 1)
void gemm_mma(const float* __restrict__ A, const float* __restrict__ W,
              const float* __restrict__ bias, float* __restrict__ C,
              int M, int N, int K) {
    extern __shared__ __align__(16) uint32_t dsm[];

    const int tid  = threadIdx.x;
    const int lane = tid & 31;
    const int wid  = tid >> 5;
    const int wm   = wid & 3;     // 0..3  (M)
    const int wn   = wid >> 2;    // 0..1  (N)
    const int bx   = blockIdx.x, by = blockIdx.y;

    const int lr  = tid >> 3;
    const int lc4 = tid & 7;
    const float* Ap = A + (size_t)(by*128 + lr)*K + lc4*4;
    const float* Wp = W + (size_t)(bx*128 + lr)*K + lc4*4;

    float acc[2][8][4];
#pragma unroll
    for (int i = 0; i < 2; i++)
#pragma unroll
        for (int j = 0; j < 8; j++)
#pragma unroll
            for (int q = 0; q < 4; q++) acc[i][j][q] = 0.f;

    const uint32_t dsmB = smem_u32(dsm);
    const uint32_t offA = (uint32_t)((wm*32 + (lane & 15)) * 80 + (lane >> 4) * 16);
    const int l16 = lane & 15;
    const uint32_t offB = (uint32_t)((wn*64 + (l16 & 7)) * 80 + (l16 >> 3) * 16);

    const int KT = K >> 5;

    float4 av[4], wv[4];
#pragma unroll
    for (int i = 0; i < 4; i++) {
        av[i] = *(const float4*)(Ap + (size_t)(32*i)*K);
        wv[i] = *(const float4*)(Wp + (size_t)(32*i)*K);
    }
    // store kt=0 into buffer 0
    {
        uint32_t* b = dsm;
#pragma unroll
        for (int i = 0; i < 4; i++) {
            const uint32_t o = (uint32_t)((lr + 32*i) * SROW + lc4 * 2);
            float r0, r1, r2, r3;
            uint32_t h01 = pack_hi(av[i].x, av[i].y, r0, r1);
            uint32_t h23 = pack_hi(av[i].z, av[i].w, r2, r3);
            b[o] = h01; b[o+1] = h23;
            b[2560+o] = pack_lo(r0, r1); b[2560+o+1] = pack_lo(r2, r3);
            h01 = pack_hi(wv[i].x, wv[i].y, r0, r1);
            h23 = pack_hi(wv[i].z, wv[i].w, r2, r3);
            b[5120+o] = h01; b[5120+o+1] = h23;
            b[7680+o] = pack_lo(r0, r1); b[7680+o+1] = pack_lo(r2, r3);
        }
    }
    __syncthreads();

    for (int kt = 0; kt < KT; kt++) {
        const uint32_t bb = (uint32_t)(kt & 1) * (GBUF_U32 * 4);   // bytes
        if (kt + 1 < KT) {
            const int ko = (kt + 1) * 32;
#pragma unroll
            for (int i = 0; i < 4; i++) {
                av[i] = *(const float4*)(Ap + (size_t)(32*i)*K + ko);
                wv[i] = *(const float4*)(Wp + (size_t)(32*i)*K + ko);
            }
        }
        const uint32_t aHiB = dsmB + bb;
        const uint32_t aLoB = aHiB + 10240u;
        const uint32_t wHiB = aHiB + 20480u;
        const uint32_t wLoB = aHiB + 30720u;

#pragma unroll
        for (int kk = 0; kk < 2; kk++) {
            const uint32_t dk = (uint32_t)(kk * 32);
            uint32_t ah[2][4], al[2][4];
#pragma unroll
            for (int mt = 0; mt < 2; mt++) {
                LDSM4(ah[mt], aHiB + offA + (uint32_t)(mt * 16 * 80) + dk);
                LDSM4(al[mt], aLoB + offA + (uint32_t)(mt * 16 * 80) + dk);
            }
#pragma unroll
            for (int nt = 0; nt < 8; nt++) {
                uint32_t bh[2], bl[2];
                const uint32_t bo = offB + (uint32_t)(nt * 8 * 80) + dk;
                LDSM2(bh, wHiB + bo);
                LDSM2(bl, wLoB + bo);
#pragma unroll
                for (int mt = 0; mt < 2; mt++) {
                    MMA_BF16(acc[mt][nt], ah[mt], bh);
                    MMA_BF16(acc[mt][nt], ah[mt], bl);
                    MMA_BF16(acc[mt][nt], al[mt], bh);
                }
            }
        }

        if (kt + 1 < KT) {
            uint32_t* b = dsm + ((kt + 1) & 1) * GBUF_U32;
#pragma unroll
            for (int i = 0; i < 4; i++) {
                const uint32_t o = (uint32_t)((lr + 32*i) * SROW + lc4 * 2);
                float r0, r1, r2, r3;
                uint32_t h01 = pack_hi(av[i].x, av[i].y, r0, r1);
                uint32_t h23 = pack_hi(av[i].z, av[i].w, r2, r3);
                b[o] = h01; b[o+1] = h23;
                b[2560+o] = pack_lo(r0, r1); b[2560+o+1] = pack_lo(r2, r3);
                h01 = pack_hi(wv[i].x, wv[i].y, r0, r1);
                h23 = pack_hi(wv[i].z, wv[i].w, r2, r3);
                b[5120+o] = h01; b[5120+o+1] = h23;
                b[7680+o] = pack_lo(r0, r1); b[7680+o+1] = pack_lo(r2, r3);
            }
        }
        __syncthreads();
    }

    const int rbase = by*128 + wm*32 + (lane >> 2);
    const int cbase = bx*128 + wn*64 + 2*(lane & 3);
#pragma unroll
    for (int mt = 0; mt < 2; mt++) {
#pragma unroll
        for (int nt = 0; nt < 8; nt++) {
            const int row = rbase + mt*16;
            const int col = cbase + nt*8;
            const float b0 = bias[col], b1 = bias[col+1];
            float2 v0, v1;
            v0.x = acc[mt][nt][0] + b0; v0.y = acc[mt][nt][1] + b1;
            v1.x = acc[mt][nt][2] + b0; v1.y = acc[mt][nt][3] + b1;
            if (RELU) {
                v0.x = fmaxf(v0.x, 0.f); v0.y = fmaxf(v0.y, 0.f);
                v1.x = fmaxf(v1.x, 0.f); v1.y = fmaxf(v1.y, 0.f);
            }
            *(float2*)(C + (size_t)row*N + col)       = v0;
            *(float2*)(C + (size_t)(row+8)*N + col)   = v1;
        }
    }
}

// ============================================================================
// HMMA bf16-split flash attention.
// grid (P/64, NH, B), 128 threads = 4 warps; warp = 16 query rows.
// smem (bf16, row stride 72): Qhi Qlo Khi Klo Vthi Vtlo (Vt = [d][key]).
// S = Q.K^T via NT pattern (K natural [key][d]); P frags rebuilt from S accums.
// ============================================================================
#define AST 72                       // bf16 row stride (144B)
#define ATT_SMEM_BYTES (6*64*AST*2)  // 55296

__global__ __launch_bounds__(128)
void attn_mma(const float* __restrict__ Q, const float* __restrict__ Kg,
              const float* __restrict__ Vg, float* __restrict__ O) {
    extern __shared__ __align__(16) char smx[];
    uint32_t* usm = (uint32_t*)smx;
    __nv_bfloat16* bsm = (__nv_bfloat16*)smx;
    // byte offsets: Qh 0, Ql 9216, Kh 18432, Kl 27648, Vh 36864, Vl 46080
    const uint32_t sb = smem_u32(smx);

    const int tid = threadIdx.x;
    const int lane = tid & 31;
    const int wid = tid >> 5;          // 0..3
    const int l16 = lane & 15;
    const int qt = blockIdx.x, hh = blockIdx.y, bb = blockIdx.z;
    const int nbase = bb * PSEQ;
    const int hoff  = hh * DKH;

    // ---- load Q tile (64x64), scale by 1/8, split, store [q][d] ----
#pragma unroll
    for (int it = 0; it < 8; it++) {
        int idx = tid + it*128;
        int r = idx >> 4;
        int c4 = (idx & 15) * 4;
        float4 qv = *(const float4*)(Q + (size_t)(nbase + qt*64 + r)*EMB + hoff + c4);
        qv.x *= 0.125f; qv.y *= 0.125f; qv.z *= 0.125f; qv.w *= 0.125f;
        const uint32_t o = (uint32_t)(r*36 + (c4 >> 1));
        float r0, r1, r2, r3;
        uint32_t h01 = pack_hi(qv.x, qv.y, r0, r1);
        uint32_t h23 = pack_hi(qv.z, qv.w, r2, r3);
        usm[o] = h01; usm[o+1] = h23;
        usm[2304+o] = pack_lo(r0, r1); usm[2304+o+1] = pack_lo(r2, r3);
    }

    float o_acc[8][4];
#pragma unroll
    for (int i = 0; i < 8; i++)
#pragma unroll
        for (int j = 0; j < 4; j++) o_acc[i][j] = 0.f;
    float m_g = -1e30f, m_g8 = -1e30f, l_g = 0.f, l_g8 = 0.f;

    uint32_t qh[4][4], ql[4][4];
    const uint32_t offA = (uint32_t)(((wid*16 + l16) * AST + (lane >> 4) * 8) * 2);
    const uint32_t offBr = (uint32_t)((((l16 & 7)) * AST + ((l16 >> 3)) * 8) * 2);

    for (int kc = 0; kc < 16; kc++) {
        __syncthreads();   // prior chunk consumed (and Q stores on kc=0)
        // ---- load K (natural, split) and V (transposed, split) ----
#pragma unroll
        for (int it = 0; it < 8; it++) {
            int idx = tid + it*128;
            int r = idx >> 4;
            int c4 = (idx & 15) * 4;
            const size_t roff = (size_t)(nbase + kc*64 + r)*EMB + hoff + c4;
            float4 kv = *(const float4*)(Kg + roff);
            const uint32_t o = (uint32_t)(r*36 + (c4 >> 1));
            float r0, r1, r2, r3;
            uint32_t h01 = pack_hi(kv.x, kv.y, r0, r1);
            uint32_t h23 = pack_hi(kv.z, kv.w, r2, r3);
            usm[4608+o] = h01; usm[4608+o+1] = h23;
            usm[6912+o] = pack_lo(r0, r1); usm[6912+o+1] = pack_lo(r2, r3);

            float4 vv = *(const float4*)(Vg + roff);
            float vals[4] = {vv.x, vv.y, vv.z, vv.w};
#pragma unroll
            for (int i = 0; i < 4; i++) {
                __nv_bfloat16 h = __float2bfloat16(vals[i]);
                __nv_bfloat16 l = __float2bfloat16(vals[i] - __bfloat162float(h));
                bsm[18432 + (c4+i)*AST + r] = h;
                bsm[23040 + (c4+i)*AST + r] = l;
            }
        }
        __syncthreads();

        if (kc == 0) {
#pragma unroll
            for (int ks = 0; ks < 4; ks++) {
                LDSM4(qh[ks], sb + offA + (uint32_t)(ks*32));
                LDSM4(ql[ks], sb + 9216u + offA + (uint32_t)(ks*32));
            }
        }

        // ---- S = Q @ K^T ----
        float s[8][4];
#pragma unroll
        for (int nt = 0; nt < 8; nt++)
#pragma unroll
            for (int j = 0; j < 4; j++) s[nt][j] = 0.f;
#pragma unroll
        for (int nt = 0; nt < 8; nt++) {
#pragma unroll
            for (int ks = 0; ks < 4; ks++) {
                uint32_t bh[2], bl[2];
                const uint32_t bo = offBr + (uint32_t)(nt*8*AST*2 + ks*32);
                LDSM2(bh, sb + 18432u + bo);
                LDSM2(bl, sb + 27648u + bo);
                MMA_BF16(s[nt], qh[ks], bh);
                MMA_BF16(s[nt], ql[ks], bh);
                MMA_BF16(s[nt], qh[ks], bl);
            }
        }

        // ---- online softmax (rows g = lane>>2, g+8) ----
        float cmg = -1e30f, cmg8 = -1e30f;
#pragma unroll
        for (int nt = 0; nt < 8; nt++) {
            cmg  = fmaxf(cmg,  fmaxf(s[nt][0], s[nt][1]));
            cmg8 = fmaxf(cmg8, fmaxf(s[nt][2], s[nt][3]));
        }
        cmg  = fmaxf(cmg,  __shfl_xor_sync(0xffffffffu, cmg, 1));
        cmg  = fmaxf(cmg,  __shfl_xor_sync(0xffffffffu, cmg, 2));
        cmg8 = fmaxf(cmg8, __shfl_xor_sync(0xffffffffu, cmg8, 1));
        cmg8 = fmaxf(cmg8, __shfl_xor_sync(0xffffffffu, cmg8, 2));
        const float mn  = fmaxf(m_g,  cmg);
        const float mn8 = fmaxf(m_g8, cmg8);
        const float alg  = __expf(m_g  - mn);
        const float alg8 = __expf(m_g8 - mn8);
        m_g = mn; m_g8 = mn8;
        float sum = 0.f, sum8 = 0.f;
#pragma unroll
        for (int nt = 0; nt < 8; nt++) {
            s[nt][0] = __expf(s[nt][0] - mn);
            s[nt][1] = __expf(s[nt][1] - mn);
            s[nt][2] = __expf(s[nt][2] - mn8);
            s[nt][3] = __expf(s[nt][3] - mn8);
            sum  += s[nt][0] + s[nt][1];
            sum8 += s[nt][2] + s[nt][3];
        }
        sum  += __shfl_xor_sync(0xffffffffu, sum, 1);
        sum  += __shfl_xor_sync(0xffffffffu, sum, 2);
        sum8 += __shfl_xor_sync(0xffffffffu, sum8, 1);
        sum8 += __shfl_xor_sync(0xffffffffu, sum8, 2);
        l_g  = l_g  * alg  + sum;
        l_g8 = l_g8 * alg8 + sum8;
#pragma unroll
        for (int dt = 0; dt < 8; dt++) {
            o_acc[dt][0] *= alg;  o_acc[dt][1] *= alg;
            o_acc[dt][2] *= alg8; o_acc[dt][3] *= alg8;
        }

        // ---- P fragments from S accums (A-frag layout identity) ----
        uint32_t ph[4][4], pl[4][4];
#pragma unroll
        for (int ks = 0; ks < 4; ks++) {
            float r0, r1;
            ph[ks][0] = pack_hi(s[2*ks][0],   s[2*ks][1],   r0, r1); pl[ks][0] = pack_lo(r0, r1);
            ph[ks][1] = pack_hi(s[2*ks][2],   s[2*ks][3],   r0, r1); pl[ks][1] = pack_lo(r0, r1);
            ph[ks][2] = pack_hi(s[2*ks+1][0], s[2*ks+1][1], r0, r1); pl[ks][2] = pack_lo(r0, r1);
            ph[ks][3] = pack_hi(s[2*ks+1][2], s[2*ks+1][3], r0, r1); pl[ks][3] = pack_lo(r0, r1);
        }

        // ---- O += P @ V  (B from Vt [d][key]) ----
#pragma unroll
        for (int dt = 0; dt < 8; dt++) {
#pragma unroll
            for (int ks = 0; ks < 4; ks++) {
                uint32_t vh2[2], vl2[2];
                const uint32_t vo = offBr + (uint32_t)(dt*8*AST*2 + ks*32);
                LDSM2(vh2, sb + 36864u + vo);
                LDSM2(vl2, sb + 46080u + vo);
                MMA_BF16(o_acc[dt], ph[ks], vh2);
                MMA_BF16(o_acc[dt], pl[ks], vh2);
                MMA_BF16(o_acc[dt], ph[ks], vl2);
            }
        }
    }

    // ---- epilogue ----
    const float ig  = 1.f / l_g;
    const float ig8 = 1.f / l_g8;
    const int g = lane >> 2;
    const int r0 = nbase + qt*64 + wid*16 + g;
    const int cb = hoff + 2*(lane & 3);
#pragma unroll
    for (int dt = 0; dt < 8; dt++) {
        float2 v0, v1;
        v0.x = o_acc[dt][0]*ig;  v0.y = o_acc[dt][1]*ig;
        v1.x = o_acc[dt][2]*ig8; v1.y = o_acc[dt][3]*ig8;
        *(float2*)(O + (size_t)r0*EMB + cb + dt*8)     = v0;
        *(float2*)(O + (size_t)(r0+8)*EMB + cb + dt*8) = v1;
    }
}

// ---------------- positional encoding table --------------------------------
__global__ void pe_kernel(float* __restrict__ pe) {
    int idx = blockIdx.x * blockDim.x + threadIdx.x;
    if (idx >= PSEQ*EMB) return;
    int p = idx >> 9;
    int e = idx & 511;
    int i2 = e >> 1;
    float c = (float)(2*i2) * (-0.017988946039015984f);
    float freqf = (float)exp((double)c);
    float angf  = (float)p * freqf;
    double angle = (double)angf;
    pe[idx] = (e & 1) ? (float)cos(angle) : (float)sin(angle);
}

// ---------------- embedding: patch conv + Linear(1->E) + PE -----------------
__global__ void embed_kernel(const float* __restrict__ data,
                             const float* __restrict__ cw,
                             const float* __restrict__ cb,
                             const float* __restrict__ lw,
                             const float* __restrict__ lb,
                             const float* __restrict__ pe,
                             float* __restrict__ x) {
    int idx = blockIdx.x * blockDim.x + threadIdx.x;
    if (idx >= NTOK*EMB) return;
    int n = idx >> 9;
    int e = idx & 511;
    int b = n >> 10;
    int p = n & 1023;
    int pi = p >> 5, pj = p & 31;
    const float* dp = data + b*4096 + (pi*2)*64 + pj*2;
    float conv = dp[0]*cw[0] + dp[1]*cw[1] + dp[64]*cw[2] + dp[65]*cw[3] + cb[0];
    x[idx] = conv * lw[e] + lb[e] + pe[p*EMB + e];
}

// ---------------- residual add + LayerNorm ----------------------------------
__global__ __launch_bounds__(128)
void add_ln_kernel(float* __restrict__ x, const float* __restrict__ y,
                   const float* __restrict__ gam, const float* __restrict__ bet) {
    const int row = blockIdx.x;
    const int tid = threadIdx.x;
    const int e = tid * 4;
    float4 xv = *(float4*)&x[(size_t)row*EMB + e];
    float4 yv = *(const float4*)&y[(size_t)row*EMB + e];
    float t0 = xv.x + yv.x, t1 = xv.y + yv.y, t2 = xv.z + yv.z, t3 = xv.w + yv.w;
    float s  = t0 + t1 + t2 + t3;
    float s2 = t0*t0 + t1*t1 + t2*t2 + t3*t3;
#pragma unroll
    for (int off = 16; off > 0; off >>= 1) {
        s  += __shfl_xor_sync(0xffffffffu, s,  off);
        s2 += __shfl_xor_sync(0xffffffffu, s2, off);
    }
    __shared__ float ws[4], ws2[4];
    int w = tid >> 5;
    if ((tid & 31) == 0) { ws[w] = s; ws2[w] = s2; }
    __syncthreads();
    float S  = ws[0] + ws[1] + ws[2] + ws[3];
    float S2 = ws2[0] + ws2[1] + ws2[2] + ws2[3];
    float mu  = S * (1.f/512.f);
    float var = S2 * (1.f/512.f) - mu*mu;
    float rs = rsqrtf(var + 1e-5f);
    float4 ov;
    ov.x = (t0 - mu)*rs*gam[e+0] + bet[e+0];
    ov.y = (t1 - mu)*rs*gam[e+1] + bet[e+1];
    ov.z = (t2 - mu)*rs*gam[e+2] + bet[e+2];
    ov.w = (t3 - mu)*rs*gam[e+3] + bet[e+3];
    *(float4*)&x[(size_t)row*EMB + e] = ov;
}

// ---------------- mean pool + final linear ----------------------------------
__global__ __launch_bounds__(512)
void pool_head_kernel(const float* __restrict__ x, const float* __restrict__ Wc,
                      const float* __restrict__ bc, float* __restrict__ out) {
    const int b = blockIdx.x;
    const int e = threadIdx.x;
    float s = 0.f;
    const float* xp = x + (size_t)b*PSEQ*EMB + e;
    for (int p = 0; p < PSEQ; p++) s += xp[(size_t)p*EMB];
    float pooled = s * (1.f/1024.f);
    __shared__ float red[512];
    red[e] = pooled * Wc[e];
    __syncthreads();
    for (int st = 256; st > 0; st >>= 1) {
        if (e < st) red[e] += red[e + st];
        __syncthreads();
    }
    if (e == 0) out[b] = red[0] + bc[0];
}

// ---------------- driver -----------------------------------------------------
extern "C" void kernel_launch(void* const* d_in, const int* in_sizes, int n_in,
                              void* d_out, int out_size) {
    const float* data   = (const float*)d_in[0];
    const float* conv_w = (const float*)d_in[1];
    const float* conv_b = (const float*)d_in[2];
    const float* lin_w  = (const float*)d_in[3];
    const float* lin_b  = (const float*)d_in[4];
    const float* Wq     = (const float*)d_in[5];
    const float* bq     = (const float*)d_in[6];
    const float* Wk     = (const float*)d_in[7];
    const float* bk     = (const float*)d_in[8];
    const float* Wv     = (const float*)d_in[9];
    const float* bv     = (const float*)d_in[10];
    const float* Wo     = (const float*)d_in[11];
    const float* bo     = (const float*)d_in[12];
    const float* ln1_g  = (const float*)d_in[13];
    const float* ln1_b  = (const float*)d_in[14];
    const float* ln2_g  = (const float*)d_in[15];
    const float* ln2_b  = (const float*)d_in[16];
    const float* W1     = (const float*)d_in[17];
    const float* b1     = (const float*)d_in[18];
    const float* W2     = (const float*)d_in[19];
    const float* b2     = (const float*)d_in[20];
    const float* Wc     = (const float*)d_in[21];
    const float* bc     = (const float*)d_in[22];
    float* out = (float*)d_out;

    float *px, *pq, *pk, *pv, *pa, *pt, *ph, *ppe;
    cudaGetSymbolAddress((void**)&px,  g_x);
    cudaGetSymbolAddress((void**)&pq,  g_q);
    cudaGetSymbolAddress((void**)&pk,  g_k);
    cudaGetSymbolAddress((void**)&pv,  g_v);
    cudaGetSymbolAddress((void**)&pa,  g_a);
    cudaGetSymbolAddress((void**)&pt,  g_t);
    cudaGetSymbolAddress((void**)&ph,  g_h);
    cudaGetSymbolAddress((void**)&ppe, g_pe);

    cudaFuncSetAttribute(gemm_mma<0>, cudaFuncAttributeMaxDynamicSharedMemorySize, GSMEM_BYTES);
    cudaFuncSetAttribute(gemm_mma<1>, cudaFuncAttributeMaxDynamicSharedMemorySize, GSMEM_BYTES);
    cudaFuncSetAttribute(attn_mma,    cudaFuncAttributeMaxDynamicSharedMemorySize, ATT_SMEM_BYTES);

    pe_kernel<<<(PSEQ*EMB + 255)/256, 256>>>(ppe);
    embed_kernel<<<(NTOK*EMB + 255)/256, 256>>>(data, conv_w, conv_b, lin_w, lin_b, ppe, px);

    for (int l = 0; l < NLAYER; l++) {
        const float* wq = Wq + (size_t)l*EMB*EMB;
        const float* wk = Wk + (size_t)l*EMB*EMB;
        const float* wv = Wv + (size_t)l*EMB*EMB;
        const float* wo = Wo + (size_t)l*EMB*EMB;
        const float* w1 = W1 + (size_t)l*FFD*EMB;
        const float* w2 = W2 + (size_t)l*EMB*FFD;

        dim3 gE(EMB/128, NTOK/128);
        dim3 gF(FFD/128, NTOK/128);

        gemm_mma<0><<<gE, 256, GSMEM_BYTES>>>(px, wq, bq + l*EMB, pq, NTOK, EMB, EMB);
        gemm_mma<0><<<gE, 256, GSMEM_BYTES>>>(px, wk, bk + l*EMB, pk, NTOK, EMB, EMB);
        gemm_mma<0><<<gE, 256, GSMEM_BYTES>>>(px, wv, bv + l*EMB, pv, NTOK, EMB, EMB);

        attn_mma<<<dim3(PSEQ/64, NHEAD, BATCH), 128, ATT_SMEM_BYTES>>>(pq, pk, pv, pa);

        gemm_mma<0><<<gE, 256, GSMEM_BYTES>>>(pa, wo, bo + l*EMB, pt, NTOK, EMB, EMB);
        add_ln_kernel<<<NTOK, 128>>>(px, pt, ln1_g + l*EMB, ln1_b + l*EMB);

        gemm_mma<1><<<gF, 256, GSMEM_BYTES>>>(px, w1, b1 + l*FFD, ph, NTOK, FFD, EMB);
        gemm_mma<0><<<gE, 256, GSMEM_BYTES>>>(ph, w2, b2 + l*EMB, pt, NTOK, EMB, FFD);
        add_ln_kernel<<<NTOK, 128>>>(px, pt, ln2_g + l*EMB, ln2_b + l*EMB);
    }

    pool_head_kernel<<<BATCH, 512>>>(px, Wc, bc, out);
}

// round 6
// speedup vs baseline: 2.4403x; 1.2285x over previous
#include <cuda_runtime.h>
#include <cuda_bf16.h>
#include <math.h>
#include <stdint.h>

#define BATCH   16
#define PSEQ    1024
#define NTOK    (BATCH*PSEQ)     // 16384
#define EMB     512
#define FFD     2048
#define NLAYER  4
#define NHEAD   8
#define DKH     64

typedef __nv_bfloat16 bf16;

// ---------------- scratch (static device globals; no runtime alloc) ----------
__device__ float g_x [NTOK*EMB];
__device__ float g_t [NTOK*EMB];
__device__ float g_pe[PSEQ*EMB];
__device__ bf16 g_xh[NTOK*EMB],  g_xl[NTOK*EMB];
__device__ bf16 g_qkvh[NTOK*3*EMB], g_qkvl[NTOK*3*EMB];
__device__ bf16 g_ah[NTOK*EMB],  g_al[NTOK*EMB];
__device__ bf16 g_hh[NTOK*FFD],  g_hl[NTOK*FFD];
__device__ bf16 g_wqkvh[NLAYER*3*EMB*EMB], g_wqkvl[NLAYER*3*EMB*EMB];
__device__ bf16 g_woh[NLAYER*EMB*EMB],     g_wol[NLAYER*EMB*EMB];
__device__ bf16 g_w1h[NLAYER*FFD*EMB],     g_w1l[NLAYER*FFD*EMB];
__device__ bf16 g_w2h[NLAYER*EMB*FFD],     g_w2l[NLAYER*EMB*FFD];
__device__ float g_bqkv[NLAYER*3*EMB];

// ============================================================================
// helpers
// ============================================================================
static __device__ __forceinline__ uint32_t smem_u32(const void* p) {
    uint32_t a;
    asm("{ .reg .u64 t; cvta.to.shared.u64 t, %1; cvt.u32.u64 %0, t; }"
        : "=r"(a) : "l"(p));
    return a;
}
static __device__ __forceinline__ uint32_t pack_hi(float a, float b, float& ra, float& rb) {
    bf16 ha = __float2bfloat16(a);
    bf16 hb = __float2bfloat16(b);
    ra = a - __bfloat162float(ha);
    rb = b - __bfloat162float(hb);
    return (uint32_t)__bfloat16_as_ushort(ha) | ((uint32_t)__bfloat16_as_ushort(hb) << 16);
}
static __device__ __forceinline__ uint32_t pack_lo(float a, float b) {
    return (uint32_t)__bfloat16_as_ushort(__float2bfloat16(a)) |
           ((uint32_t)__bfloat16_as_ushort(__float2bfloat16(b)) << 16);
}

#define MMA_BF16(d, a, b) \
    asm volatile("mma.sync.aligned.m16n8k16.row.col.f32.bf16.bf16.f32 " \
        "{%0,%1,%2,%3}, {%4,%5,%6,%7}, {%8,%9}, {%0,%1,%2,%3};" \
        : "+f"((d)[0]), "+f"((d)[1]), "+f"((d)[2]), "+f"((d)[3]) \
        : "r"((a)[0]), "r"((a)[1]), "r"((a)[2]), "r"((a)[3]), \
          "r"((b)[0]), "r"((b)[1]))

#define LDSM4(r, addr) \
    asm volatile("ldmatrix.sync.aligned.m8n8.x4.shared.b16 {%0,%1,%2,%3}, [%4];" \
        : "=r"((r)[0]), "=r"((r)[1]), "=r"((r)[2]), "=r"((r)[3]) : "r"(addr))

#define LDSM2(r, addr) \
    asm volatile("ldmatrix.sync.aligned.m8n8.x2.shared.b16 {%0,%1}, [%2];" \
        : "=r"((r)[0]), "=r"((r)[1]) : "r"(addr))

static __device__ __forceinline__ void cpa16(uint32_t d, const void* s) {
    asm volatile("cp.async.cg.shared.global [%0], [%1], 16;" :: "r"(d), "l"(s));
}

// swizzled byte offset inside a 128x32-bf16 tile (rows of 64B = 4x16B chunks)
static __device__ __forceinline__ uint32_t swz(int r, int c) {
    return (uint32_t)(r * 64 + ((c ^ ((r >> 1) & 3)) << 4));
}

// ============================================================================
// bf16 HMMA GEMM on pre-split operands: C = (Ah+Al) @ (Wh+Wl)^T + bias
// (3-term: AhWh + AhWl + AlWh).  BM=BN=128, BK=32, 4-stage cp.async pipeline.
// 256 threads = 4(M) x 2(N) warps; warp tile 32x64.
// SPLIT=1: write bf16 hi/lo pair outputs; else fp32.
// ============================================================================
#define GSTAGE 32768
#define GSMEM_BYTES (4*GSTAGE)   // 131072

template<int RELU, int SPLIT>
__global__ __launch_bounds__(256)
void gemm_bf(const bf16* __restrict__ Ah, const bf16* __restrict__ Al,
             const bf16* __restrict__ Wh, const bf16* __restrict__ Wl,
             const float* __restrict__ bias,
             float* __restrict__ Cf, bf16* __restrict__ Ch, bf16* __restrict__ Cl,
             int M, int N, int K) {
    extern __shared__ __align__(16) char dsm[];
    const uint32_t sb = smem_u32(dsm);
    const int tid = threadIdx.x, lane = tid & 31, wid = tid >> 5;
    const int wm = wid & 3, wn = wid >> 2;
    const int bx = blockIdx.x, by = blockIdx.y;
    const int KT = K >> 5;

    float acc[2][8][4];
#pragma unroll
    for (int i = 0; i < 2; i++)
#pragma unroll
        for (int j = 0; j < 8; j++)
#pragma unroll
            for (int q = 0; q < 4; q++) acc[i][j][q] = 0.f;

    // cp.async mapping: thread -> chunks tid (r=tid>>2,c=tid&3) and tid+256 (r+64)
    const int cr = tid >> 2, cc = tid & 3;
    const size_t aoff = (size_t)(by*128 + cr)*K + cc*8;
    const size_t woff = (size_t)(bx*128 + cr)*K + cc*8;
    const uint32_t so0 = swz(cr, cc), so1 = swz(cr + 64, cc);

    // ldmatrix offsets
    const int l16 = lane & 15;
    uint32_t offA[2][2], offB[4][2];
#pragma unroll
    for (int mt = 0; mt < 2; mt++)
#pragma unroll
        for (int ks = 0; ks < 2; ks++)
            offA[mt][ks] = swz(wm*32 + mt*16 + l16, ks*2 + (lane >> 4));
    const int rB = (lane & 7) + ((lane >> 4) << 3);
    const int cB = (lane >> 3) & 1;
#pragma unroll
    for (int ntp = 0; ntp < 4; ntp++)
#pragma unroll
        for (int ks = 0; ks < 2; ks++)
            offB[ntp][ks] = swz(wn*64 + ntp*16 + rB, ks*2 + cB);

#define G_ISSUE(ktn) do {                                                   \
    if ((ktn) < KT) {                                                       \
        const uint32_t stb = sb + (uint32_t)((ktn) & 3) * GSTAGE;           \
        const int ko = (ktn) * 32;                                          \
        cpa16(stb + so0,           Ah + aoff + ko);                         \
        cpa16(stb + so1,           Ah + aoff + (size_t)64*K + ko);          \
        cpa16(stb + 8192u + so0,   Al + aoff + ko);                         \
        cpa16(stb + 8192u + so1,   Al + aoff + (size_t)64*K + ko);          \
        cpa16(stb + 16384u + so0,  Wh + woff + ko);                         \
        cpa16(stb + 16384u + so1,  Wh + woff + (size_t)64*K + ko);          \
        cpa16(stb + 24576u + so0,  Wl + woff + ko);                         \
        cpa16(stb + 24576u + so1,  Wl + woff + (size_t)64*K + ko);          \
    }                                                                       \
    asm volatile("cp.async.commit_group;" ::: "memory");                    \
} while (0)

    G_ISSUE(0); G_ISSUE(1); G_ISSUE(2);

    for (int kt = 0; kt < KT; kt++) {
        asm volatile("cp.async.wait_group 2;" ::: "memory");
        __syncthreads();
        G_ISSUE(kt + 3);

        const uint32_t stb = sb + (uint32_t)(kt & 3) * GSTAGE;
#pragma unroll
        for (int ks = 0; ks < 2; ks++) {
            uint32_t ah[2][4], al[2][4];
#pragma unroll
            for (int mt = 0; mt < 2; mt++) {
                LDSM4(ah[mt], stb + offA[mt][ks]);
                LDSM4(al[mt], stb + 8192u + offA[mt][ks]);
            }
#pragma unroll
            for (int ntp = 0; ntp < 4; ntp++) {
                uint32_t bh[4], bl[4];
                LDSM4(bh, stb + 16384u + offB[ntp][ks]);
                LDSM4(bl, stb + 24576u + offB[ntp][ks]);
#pragma unroll
                for (int mt = 0; mt < 2; mt++) {
                    MMA_BF16(acc[mt][2*ntp],   ah[mt], bh);
                    MMA_BF16(acc[mt][2*ntp],   ah[mt], bl);
                    MMA_BF16(acc[mt][2*ntp],   al[mt], bh);
                    MMA_BF16(acc[mt][2*ntp+1], ah[mt], &bh[2]);
                    MMA_BF16(acc[mt][2*ntp+1], ah[mt], &bl[2]);
                    MMA_BF16(acc[mt][2*ntp+1], al[mt], &bh[2]);
                }
            }
        }
    }

    const int rbase = by*128 + wm*32 + (lane >> 2);
    const int cbase = bx*128 + wn*64 + 2*(lane & 3);
#pragma unroll
    for (int mt = 0; mt < 2; mt++) {
#pragma unroll
        for (int nt = 0; nt < 8; nt++) {
            const int row = rbase + mt*16;
            const int col = cbase + nt*8;
            const float b0 = bias[col], b1 = bias[col+1];
            float v0x = acc[mt][nt][0] + b0, v0y = acc[mt][nt][1] + b1;
            float v1x = acc[mt][nt][2] + b0, v1y = acc[mt][nt][3] + b1;
            if (RELU) {
                v0x = fmaxf(v0x, 0.f); v0y = fmaxf(v0y, 0.f);
                v1x = fmaxf(v1x, 0.f); v1y = fmaxf(v1y, 0.f);
            }
            if (SPLIT) {
                float rx, ry;
                uint32_t h = pack_hi(v0x, v0y, rx, ry);
                uint32_t l = pack_lo(rx, ry);
                *(uint32_t*)(Ch + (size_t)row*N + col) = h;
                *(uint32_t*)(Cl + (size_t)row*N + col) = l;
                h = pack_hi(v1x, v1y, rx, ry);
                l = pack_lo(rx, ry);
                *(uint32_t*)(Ch + (size_t)(row+8)*N + col) = h;
                *(uint32_t*)(Cl + (size_t)(row+8)*N + col) = l;
            } else {
                float2 a = {v0x, v0y}, b = {v1x, v1y};
                *(float2*)(Cf + (size_t)row*N + col)     = a;
                *(float2*)(Cf + (size_t)(row+8)*N + col) = b;
            }
        }
    }
}

// ============================================================================
// HMMA flash attention on pre-split combined QKV [tok][1536] (hi/lo).
// grid (P/64, NH, B), 128 threads = 4 warps; output split a (hi/lo).
// ============================================================================
#define AST 72
#define ATT_SMEM_BYTES (6*64*AST*2)  // 55296

__global__ __launch_bounds__(128)
void attn_mma(const bf16* __restrict__ QKVh, const bf16* __restrict__ QKVl,
              bf16* __restrict__ Ah, bf16* __restrict__ Al) {
    extern __shared__ __align__(16) char smx[];
    bf16* bsm = (bf16*)smx;
    const uint32_t sb = smem_u32(smx);
    // byte offsets: Qh 0, Ql 9216, Kh 18432, Kl 27648, Vth 36864, Vtl 46080

    const int tid = threadIdx.x;
    const int lane = tid & 31;
    const int wid = tid >> 5;
    const int l16 = lane & 15;
    const int qt = blockIdx.x, hh = blockIdx.y, bb = blockIdx.z;
    const int nbase = bb * PSEQ;
    const int hoff  = hh * DKH;

    // ---- Q tile: straight 16B copies ----
#pragma unroll
    for (int it = 0; it < 4; it++) {
        int idx = tid + it*128;
        int r = idx >> 3;
        int c8 = (idx & 7) * 8;
        const size_t go = (size_t)(nbase + qt*64 + r)*(3*EMB) + hoff + c8;
        *(uint4*)(smx + r*144 + c8*2)          = *(const uint4*)(QKVh + go);
        *(uint4*)(smx + 9216 + r*144 + c8*2)   = *(const uint4*)(QKVl + go);
    }

    float o_acc[8][4];
#pragma unroll
    for (int i = 0; i < 8; i++)
#pragma unroll
        for (int j = 0; j < 4; j++) o_acc[i][j] = 0.f;
    float m_g = -1e30f, m_g8 = -1e30f, l_g = 0.f, l_g8 = 0.f;

    uint32_t qh[4][4], ql[4][4];
    const uint32_t offA = (uint32_t)(((wid*16 + l16) * AST + (lane >> 4) * 8) * 2);
    const uint32_t offBr = (uint32_t)((((l16 & 7)) * AST + ((l16 >> 3)) * 8) * 2);

    for (int kc = 0; kc < 16; kc++) {
        __syncthreads();
        // ---- K natural copy, V transposed scatter ----
#pragma unroll
        for (int it = 0; it < 4; it++) {
            int idx = tid + it*128;
            int r = idx >> 3;
            int c8 = (idx & 7) * 8;
            const size_t go = (size_t)(nbase + kc*64 + r)*(3*EMB) + hoff + c8;
            *(uint4*)(smx + 18432 + r*144 + c8*2) = *(const uint4*)(QKVh + 512 + go);
            *(uint4*)(smx + 27648 + r*144 + c8*2) = *(const uint4*)(QKVl + 512 + go);
            uint4 vh = *(const uint4*)(QKVh + 1024 + go);
            uint4 vl = *(const uint4*)(QKVl + 1024 + go);
            const bf16* ph = (const bf16*)&vh;
            const bf16* pl = (const bf16*)&vl;
#pragma unroll
            for (int i = 0; i < 8; i++) {
                bsm[18432 + (c8+i)*AST + r] = ph[i];
                bsm[23040 + (c8+i)*AST + r] = pl[i];
            }
        }
        __syncthreads();

        if (kc == 0) {
#pragma unroll
            for (int ks = 0; ks < 4; ks++) {
                LDSM4(qh[ks], sb + offA + (uint32_t)(ks*32));
                LDSM4(ql[ks], sb + 9216u + offA + (uint32_t)(ks*32));
            }
        }

        // ---- S = Q @ K^T ----
        float s[8][4];
#pragma unroll
        for (int nt = 0; nt < 8; nt++)
#pragma unroll
            for (int j = 0; j < 4; j++) s[nt][j] = 0.f;
#pragma unroll
        for (int nt = 0; nt < 8; nt++) {
#pragma unroll
            for (int ks = 0; ks < 4; ks++) {
                uint32_t bh[2], bl[2];
                const uint32_t bo = offBr + (uint32_t)(nt*8*AST*2 + ks*32);
                LDSM2(bh, sb + 18432u + bo);
                LDSM2(bl, sb + 27648u + bo);
                MMA_BF16(s[nt], qh[ks], bh);
                MMA_BF16(s[nt], ql[ks], bh);
                MMA_BF16(s[nt], qh[ks], bl);
            }
        }
        // scale 1/sqrt(64)
#pragma unroll
        for (int nt = 0; nt < 8; nt++) {
            s[nt][0] *= 0.125f; s[nt][1] *= 0.125f;
            s[nt][2] *= 0.125f; s[nt][3] *= 0.125f;
        }

        // ---- online softmax ----
        float cmg = -1e30f, cmg8 = -1e30f;
#pragma unroll
        for (int nt = 0; nt < 8; nt++) {
            cmg  = fmaxf(cmg,  fmaxf(s[nt][0], s[nt][1]));
            cmg8 = fmaxf(cmg8, fmaxf(s[nt][2], s[nt][3]));
        }
        cmg  = fmaxf(cmg,  __shfl_xor_sync(0xffffffffu, cmg, 1));
        cmg  = fmaxf(cmg,  __shfl_xor_sync(0xffffffffu, cmg, 2));
        cmg8 = fmaxf(cmg8, __shfl_xor_sync(0xffffffffu, cmg8, 1));
        cmg8 = fmaxf(cmg8, __shfl_xor_sync(0xffffffffu, cmg8, 2));
        const float mn  = fmaxf(m_g,  cmg);
        const float mn8 = fmaxf(m_g8, cmg8);
        const float alg  = __expf(m_g  - mn);
        const float alg8 = __expf(m_g8 - mn8);
        m_g = mn; m_g8 = mn8;
        float sum = 0.f, sum8 = 0.f;
#pragma unroll
        for (int nt = 0; nt < 8; nt++) {
            s[nt][0] = __expf(s[nt][0] - mn);
            s[nt][1] = __expf(s[nt][1] - mn);
            s[nt][2] = __expf(s[nt][2] - mn8);
            s[nt][3] = __expf(s[nt][3] - mn8);
            sum  += s[nt][0] + s[nt][1];
            sum8 += s[nt][2] + s[nt][3];
        }
        sum  += __shfl_xor_sync(0xffffffffu, sum, 1);
        sum  += __shfl_xor_sync(0xffffffffu, sum, 2);
        sum8 += __shfl_xor_sync(0xffffffffu, sum8, 1);
        sum8 += __shfl_xor_sync(0xffffffffu, sum8, 2);
        l_g  = l_g  * alg  + sum;
        l_g8 = l_g8 * alg8 + sum8;
#pragma unroll
        for (int dt = 0; dt < 8; dt++) {
            o_acc[dt][0] *= alg;  o_acc[dt][1] *= alg;
            o_acc[dt][2] *= alg8; o_acc[dt][3] *= alg8;
        }

        // ---- P fragments from S accums ----
        uint32_t ph[4][4], pl[4][4];
#pragma unroll
        for (int ks = 0; ks < 4; ks++) {
            float r0, r1;
            ph[ks][0] = pack_hi(s[2*ks][0],   s[2*ks][1],   r0, r1); pl[ks][0] = pack_lo(r0, r1);
            ph[ks][1] = pack_hi(s[2*ks][2],   s[2*ks][3],   r0, r1); pl[ks][1] = pack_lo(r0, r1);
            ph[ks][2] = pack_hi(s[2*ks+1][0], s[2*ks+1][1], r0, r1); pl[ks][2] = pack_lo(r0, r1);
            ph[ks][3] = pack_hi(s[2*ks+1][2], s[2*ks+1][3], r0, r1); pl[ks][3] = pack_lo(r0, r1);
        }

        // ---- O += P @ V ----
#pragma unroll
        for (int dt = 0; dt < 8; dt++) {
#pragma unroll
            for (int ks = 0; ks < 4; ks++) {
                uint32_t vh2[2], vl2[2];
                const uint32_t vo = offBr + (uint32_t)(dt*8*AST*2 + ks*32);
                LDSM2(vh2, sb + 36864u + vo);
                LDSM2(vl2, sb + 46080u + vo);
                MMA_BF16(o_acc[dt], ph[ks], vh2);
                MMA_BF16(o_acc[dt], pl[ks], vh2);
                MMA_BF16(o_acc[dt], ph[ks], vl2);
            }
        }
    }

    // ---- epilogue: split-write a ----
    const float ig  = 1.f / l_g;
    const float ig8 = 1.f / l_g8;
    const int g = lane >> 2;
    const int r0 = nbase + qt*64 + wid*16 + g;
    const int cb = hoff + 2*(lane & 3);
#pragma unroll
    for (int dt = 0; dt < 8; dt++) {
        float v0x = o_acc[dt][0]*ig,  v0y = o_acc[dt][1]*ig;
        float v1x = o_acc[dt][2]*ig8, v1y = o_acc[dt][3]*ig8;
        float rx, ry;
        uint32_t h = pack_hi(v0x, v0y, rx, ry);
        uint32_t l = pack_lo(rx, ry);
        *(uint32_t*)(Ah + (size_t)r0*EMB + cb + dt*8) = h;
        *(uint32_t*)(Al + (size_t)r0*EMB + cb + dt*8) = l;
        h = pack_hi(v1x, v1y, rx, ry);
        l = pack_lo(rx, ry);
        *(uint32_t*)(Ah + (size_t)(r0+8)*EMB + cb + dt*8) = h;
        *(uint32_t*)(Al + (size_t)(r0+8)*EMB + cb + dt*8) = l;
    }
}

// ---------------- weight split / pack kernels --------------------------------
__global__ void split_w(const float* __restrict__ src, bf16* __restrict__ h,
                        bf16* __restrict__ l, int n_per_layer, int dst_stride,
                        int dst_off) {
    int idx = blockIdx.x * blockDim.x + threadIdx.x;
    if (idx >= NLAYER * n_per_layer) return;
    int layer = idx / n_per_layer;
    int i = idx - layer * n_per_layer;
    float v = src[idx];
    bf16 hv = __float2bfloat16(v);
    size_t d = (size_t)layer * dst_stride + dst_off + i;
    h[d] = hv;
    l[d] = __float2bfloat16(v - __bfloat162float(hv));
}

__global__ void pack_bqkv(const float* __restrict__ bq, const float* __restrict__ bk,
                          const float* __restrict__ bv, float* __restrict__ dst) {
    int idx = blockIdx.x * blockDim.x + threadIdx.x;
    if (idx >= NLAYER * 3 * EMB) return;
    int l = idx / (3*EMB);
    int n = idx - l * 3*EMB;
    float v;
    if (n < EMB)            v = bq[l*EMB + n];
    else if (n < 2*EMB)     v = bk[l*EMB + n - EMB];
    else                    v = bv[l*EMB + n - 2*EMB];
    dst[idx] = v;
}

// ---------------- positional encoding table --------------------------------
__global__ void pe_kernel(float* __restrict__ pe) {
    int idx = blockIdx.x * blockDim.x + threadIdx.x;
    if (idx >= PSEQ*EMB) return;
    int p = idx >> 9;
    int e = idx & 511;
    int i2 = e >> 1;
    float c = (float)(2*i2) * (-0.017988946039015984f);
    float freqf = (float)exp((double)c);
    float angf  = (float)p * freqf;
    double angle = (double)angf;
    pe[idx] = (e & 1) ? (float)cos(angle) : (float)sin(angle);
}

// ---------------- embedding: conv + linear + PE, writes x + split ------------
__global__ void embed_kernel(const float* __restrict__ data,
                             const float* __restrict__ cw,
                             const float* __restrict__ cb,
                             const float* __restrict__ lw,
                             const float* __restrict__ lb,
                             const float* __restrict__ pe,
                             float* __restrict__ x,
                             bf16* __restrict__ xh, bf16* __restrict__ xl) {
    int idx = blockIdx.x * blockDim.x + threadIdx.x;
    if (idx >= NTOK*EMB) return;
    int n = idx >> 9;
    int e = idx & 511;
    int b = n >> 10;
    int p = n & 1023;
    int pi = p >> 5, pj = p & 31;
    const float* dp = data + b*4096 + (pi*2)*64 + pj*2;
    float conv = dp[0]*cw[0] + dp[1]*cw[1] + dp[64]*cw[2] + dp[65]*cw[3] + cb[0];
    float v = conv * lw[e] + lb[e] + pe[p*EMB + e];
    x[idx] = v;
    bf16 h = __float2bfloat16(v);
    xh[idx] = h;
    xl[idx] = __float2bfloat16(v - __bfloat162float(h));
}

// ---------------- residual add + LayerNorm, writes x + split -----------------
__global__ __launch_bounds__(128)
void add_ln_kernel(float* __restrict__ x, const float* __restrict__ y,
                   const float* __restrict__ gam, const float* __restrict__ bet,
                   bf16* __restrict__ xh, bf16* __restrict__ xl) {
    const int row = blockIdx.x;
    const int tid = threadIdx.x;
    const int e = tid * 4;
    float4 xv = *(float4*)&x[(size_t)row*EMB + e];
    float4 yv = *(const float4*)&y[(size_t)row*EMB + e];
    float t0 = xv.x + yv.x, t1 = xv.y + yv.y, t2 = xv.z + yv.z, t3 = xv.w + yv.w;
    float s  = t0 + t1 + t2 + t3;
    float s2 = t0*t0 + t1*t1 + t2*t2 + t3*t3;
#pragma unroll
    for (int off = 16; off > 0; off >>= 1) {
        s  += __shfl_xor_sync(0xffffffffu, s,  off);
        s2 += __shfl_xor_sync(0xffffffffu, s2, off);
    }
    __shared__ float ws[4], ws2[4];
    int w = tid >> 5;
    if ((tid & 31) == 0) { ws[w] = s; ws2[w] = s2; }
    __syncthreads();
    float S  = ws[0] + ws[1] + ws[2] + ws[3];
    float S2 = ws2[0] + ws2[1] + ws2[2] + ws2[3];
    float mu  = S * (1.f/512.f);
    float var = S2 * (1.f/512.f) - mu*mu;
    float rs = rsqrtf(var + 1e-5f);
    float o0 = (t0 - mu)*rs*gam[e+0] + bet[e+0];
    float o1 = (t1 - mu)*rs*gam[e+1] + bet[e+1];
    float o2 = (t2 - mu)*rs*gam[e+2] + bet[e+2];
    float o3 = (t3 - mu)*rs*gam[e+3] + bet[e+3];
    float4 ov = {o0, o1, o2, o3};
    *(float4*)&x[(size_t)row*EMB + e] = ov;
    float rx, ry;
    uint32_t h01 = pack_hi(o0, o1, rx, ry);
    uint32_t l01 = pack_lo(rx, ry);
    uint32_t h23 = pack_hi(o2, o3, rx, ry);
    uint32_t l23 = pack_lo(rx, ry);
    uint2 hv = {h01, h23}, lv = {l01, l23};
    *(uint2*)(xh + (size_t)row*EMB + e) = hv;
    *(uint2*)(xl + (size_t)row*EMB + e) = lv;
}

// ---------------- mean pool + final linear ----------------------------------
__global__ __launch_bounds__(512)
void pool_head_kernel(const float* __restrict__ x, const float* __restrict__ Wc,
                      const float* __restrict__ bc, float* __restrict__ out) {
    const int b = blockIdx.x;
    const int e = threadIdx.x;
    float s = 0.f;
    const float* xp = x + (size_t)b*PSEQ*EMB + e;
    for (int p = 0; p < PSEQ; p++) s += xp[(size_t)p*EMB];
    float pooled = s * (1.f/1024.f);
    __shared__ float red[512];
    red[e] = pooled * Wc[e];
    __syncthreads();
    for (int st = 256; st > 0; st >>= 1) {
        if (e < st) red[e] += red[e + st];
        __syncthreads();
    }
    if (e == 0) out[b] = red[0] + bc[0];
}

// ---------------- driver -----------------------------------------------------
extern "C" void kernel_launch(void* const* d_in, const int* in_sizes, int n_in,
                              void* d_out, int out_size) {
    const float* data   = (const float*)d_in[0];
    const float* conv_w = (const float*)d_in[1];
    const float* conv_b = (const float*)d_in[2];
    const float* lin_w  = (const float*)d_in[3];
    const float* lin_b  = (const float*)d_in[4];
    const float* Wq     = (const float*)d_in[5];
    const float* bq     = (const float*)d_in[6];
    const float* Wk     = (const float*)d_in[7];
    const float* bk     = (const float*)d_in[8];
    const float* Wv     = (const float*)d_in[9];
    const float* bv     = (const float*)d_in[10];
    const float* Wo     = (const float*)d_in[11];
    const float* bo     = (const float*)d_in[12];
    const float* ln1_g  = (const float*)d_in[13];
    const float* ln1_b  = (const float*)d_in[14];
    const float* ln2_g  = (const float*)d_in[15];
    const float* ln2_b  = (const float*)d_in[16];
    const float* W1     = (const float*)d_in[17];
    const float* b1     = (const float*)d_in[18];
    const float* W2     = (const float*)d_in[19];
    const float* b2     = (const float*)d_in[20];
    const float* Wc     = (const float*)d_in[21];
    const float* bc     = (const float*)d_in[22];
    float* out = (float*)d_out;

    float *px, *pt, *ppe, *pbqkv;
    bf16 *pxh, *pxl, *pqkvh, *pqkvl, *pah, *pal, *phh, *phl;
    bf16 *pwqkvh, *pwqkvl, *pwoh, *pwol, *pw1h, *pw1l, *pw2h, *pw2l;
    cudaGetSymbolAddress((void**)&px,  g_x);
    cudaGetSymbolAddress((void**)&pt,  g_t);
    cudaGetSymbolAddress((void**)&ppe, g_pe);
    cudaGetSymbolAddress((void**)&pxh, g_xh);
    cudaGetSymbolAddress((void**)&pxl, g_xl);
    cudaGetSymbolAddress((void**)&pqkvh, g_qkvh);
    cudaGetSymbolAddress((void**)&pqkvl, g_qkvl);
    cudaGetSymbolAddress((void**)&pah, g_ah);
    cudaGetSymbolAddress((void**)&pal, g_al);
    cudaGetSymbolAddress((void**)&phh, g_hh);
    cudaGetSymbolAddress((void**)&phl, g_hl);
    cudaGetSymbolAddress((void**)&pwqkvh, g_wqkvh);
    cudaGetSymbolAddress((void**)&pwqkvl, g_wqkvl);
    cudaGetSymbolAddress((void**)&pwoh, g_woh);
    cudaGetSymbolAddress((void**)&pwol, g_wol);
    cudaGetSymbolAddress((void**)&pw1h, g_w1h);
    cudaGetSymbolAddress((void**)&pw1l, g_w1l);
    cudaGetSymbolAddress((void**)&pw2h, g_w2h);
    cudaGetSymbolAddress((void**)&pw2l, g_w2l);
    cudaGetSymbolAddress((void**)&pbqkv, g_bqkv);

    cudaFuncSetAttribute(gemm_bf<0,0>, cudaFuncAttributeMaxDynamicSharedMemorySize, GSMEM_BYTES);
    cudaFuncSetAttribute(gemm_bf<0,1>, cudaFuncAttributeMaxDynamicSharedMemorySize, GSMEM_BYTES);
    cudaFuncSetAttribute(gemm_bf<1,1>, cudaFuncAttributeMaxDynamicSharedMemorySize, GSMEM_BYTES);
    cudaFuncSetAttribute(attn_mma, cudaFuncAttributeMaxDynamicSharedMemorySize, ATT_SMEM_BYTES);

    // ---- weight/bias packing (once per call) ----
    const int EE = EMB*EMB;          // 262144
    const int FE = FFD*EMB;          // 1048576
    split_w<<<(NLAYER*EE + 255)/256, 256>>>(Wq, pwqkvh, pwqkvl, EE, 3*EE, 0);
    split_w<<<(NLAYER*EE + 255)/256, 256>>>(Wk, pwqkvh, pwqkvl, EE, 3*EE, EE);
    split_w<<<(NLAYER*EE + 255)/256, 256>>>(Wv, pwqkvh, pwqkvl, EE, 3*EE, 2*EE);
    split_w<<<(NLAYER*EE + 255)/256, 256>>>(Wo, pwoh, pwol, EE, EE, 0);
    split_w<<<(NLAYER*FE + 255)/256, 256>>>(W1, pw1h, pw1l, FE, FE, 0);
    split_w<<<(NLAYER*FE + 255)/256, 256>>>(W2, pw2h, pw2l, FE, FE, 0);
    pack_bqkv<<<(NLAYER*3*EMB + 255)/256, 256>>>(bq, bk, bv, pbqkv);

    pe_kernel<<<(PSEQ*EMB + 255)/256, 256>>>(ppe);
    embed_kernel<<<(NTOK*EMB + 255)/256, 256>>>(data, conv_w, conv_b, lin_w, lin_b,
                                                ppe, px, pxh, pxl);

    for (int l = 0; l < NLAYER; l++) {
        // fused QKV: [NTOK,512] @ [1536,512]^T -> split qkv
        gemm_bf<0,1><<<dim3(12,128), 256, GSMEM_BYTES>>>(
            pxh, pxl, pwqkvh + (size_t)l*3*EE, pwqkvl + (size_t)l*3*EE,
            pbqkv + l*3*EMB, nullptr, pqkvh, pqkvl, NTOK, 3*EMB, EMB);

        attn_mma<<<dim3(PSEQ/64, NHEAD, BATCH), 128, ATT_SMEM_BYTES>>>(
            pqkvh, pqkvl, pah, pal);

        gemm_bf<0,0><<<dim3(4,128), 256, GSMEM_BYTES>>>(
            pah, pal, pwoh + (size_t)l*EE, pwol + (size_t)l*EE,
            bo + l*EMB, pt, nullptr, nullptr, NTOK, EMB, EMB);
        add_ln_kernel<<<NTOK, 128>>>(px, pt, ln1_g + l*EMB, ln1_b + l*EMB, pxh, pxl);

        gemm_bf<1,1><<<dim3(16,128), 256, GSMEM_BYTES>>>(
            pxh, pxl, pw1h + (size_t)l*FE, pw1l + (size_t)l*FE,
            b1 + l*FFD, nullptr, phh, phl, NTOK, FFD, EMB);

        gemm_bf<0,0><<<dim3(4,128), 256, GSMEM_BYTES>>>(
            phh, phl, pw2h + (size_t)l*FE, pw2l + (size_t)l*FE,
            b2 + l*EMB, pt, nullptr, nullptr, NTOK, EMB, FFD);
        add_ln_kernel<<<NTOK, 128>>>(px, pt, ln2_g + l*EMB, ln2_b + l*EMB, pxh, pxl);
    }

    pool_head_kernel<<<BATCH, 512>>>(px, Wc, bc, out);
}

// round 8
// speedup vs baseline: 2.5402x; 1.0409x over previous
#include <cuda_runtime.h>
#include <cuda_bf16.h>
#include <math.h>
#include <stdint.h>

#define BATCH   16
#define PSEQ    1024
#define NTOK    (BATCH*PSEQ)     // 16384
#define EMB     512
#define FFD     2048
#define NLAYER  4
#define NHEAD   8
#define DKH     64

typedef __nv_bfloat16 bf16;

// ---------------- scratch (static device globals; no runtime alloc) ----------
__device__ float g_x [NTOK*EMB];
__device__ float g_t [NTOK*EMB];
__device__ float g_pe[PSEQ*EMB];
__device__ bf16 g_xh[NTOK*EMB],  g_xl[NTOK*EMB];
__device__ bf16 g_qkvh[NTOK*3*EMB], g_qkvl[NTOK*3*EMB];
__device__ bf16 g_ah[NTOK*EMB],  g_al[NTOK*EMB];
__device__ bf16 g_hh[NTOK*FFD],  g_hl[NTOK*FFD];
__device__ bf16 g_wqkvh[NLAYER*3*EMB*EMB], g_wqkvl[NLAYER*3*EMB*EMB];
__device__ bf16 g_woh[NLAYER*EMB*EMB],     g_wol[NLAYER*EMB*EMB];
__device__ bf16 g_w1h[NLAYER*FFD*EMB],     g_w1l[NLAYER*FFD*EMB];
__device__ bf16 g_w2h[NLAYER*EMB*FFD],     g_w2l[NLAYER*EMB*FFD];
__device__ float g_bqkv[NLAYER*3*EMB];

// ============================================================================
// helpers
// ============================================================================
static __device__ __forceinline__ uint32_t smem_u32(const void* p) {
    uint32_t a;
    asm("{ .reg .u64 t; cvta.to.shared.u64 t, %1; cvt.u32.u64 %0, t; }"
        : "=r"(a) : "l"(p));
    return a;
}
static __device__ __forceinline__ uint32_t pack_hi(float a, float b, float& ra, float& rb) {
    bf16 ha = __float2bfloat16(a);
    bf16 hb = __float2bfloat16(b);
    ra = a - __bfloat162float(ha);
    rb = b - __bfloat162float(hb);
    return (uint32_t)__bfloat16_as_ushort(ha) | ((uint32_t)__bfloat16_as_ushort(hb) << 16);
}
static __device__ __forceinline__ uint32_t pack_lo(float a, float b) {
    return (uint32_t)__bfloat16_as_ushort(__float2bfloat16(a)) |
           ((uint32_t)__bfloat16_as_ushort(__float2bfloat16(b)) << 16);
}

#define MMA_BF16(d, a, b) \
    asm volatile("mma.sync.aligned.m16n8k16.row.col.f32.bf16.bf16.f32 " \
        "{%0,%1,%2,%3}, {%4,%5,%6,%7}, {%8,%9}, {%0,%1,%2,%3};" \
        : "+f"((d)[0]), "+f"((d)[1]), "+f"((d)[2]), "+f"((d)[3]) \
        : "r"((a)[0]), "r"((a)[1]), "r"((a)[2]), "r"((a)[3]), \
          "r"((b)[0]), "r"((b)[1]))

#define LDSM4(r, addr) \
    asm volatile("ldmatrix.sync.aligned.m8n8.x4.shared.b16 {%0,%1,%2,%3}, [%4];" \
        : "=r"((r)[0]), "=r"((r)[1]), "=r"((r)[2]), "=r"((r)[3]) : "r"(addr))

#define LDSM2(r, addr) \
    asm volatile("ldmatrix.sync.aligned.m8n8.x2.shared.b16 {%0,%1}, [%2];" \
        : "=r"((r)[0]), "=r"((r)[1]) : "r"(addr))

static __device__ __forceinline__ void cpa16(uint32_t d, const void* s) {
    asm volatile("cp.async.cg.shared.global [%0], [%1], 16;" :: "r"(d), "l"(s));
}

// swizzled byte offset inside a 128x64-bf16 tile (rows of 128B = 8x16B chunks)
static __device__ __forceinline__ uint32_t swz64(int r, int c) {
    return (uint32_t)(r * 128 + ((c ^ (r & 7)) << 4));
}

// ============================================================================
// bf16 HMMA GEMM on pre-split operands: C = (Ah+Al) @ (Wh+Wl)^T + bias
// (3-term: AhWh + AhWl + AlWh).  BM=BN=128, BK=64, 3-stage cp.async pipeline.
// 256 threads = 4(M) x 2(N) warps; warp tile 32x64.
// SPLIT=1: write bf16 hi/lo pair outputs; else fp32.
// ============================================================================
#define GSTAGE 65536u
#define GSMEM_BYTES (3*GSTAGE)   // 196608

template<int RELU, int SPLIT>
__global__ __launch_bounds__(256)
void gemm_bf(const bf16* __restrict__ Ah, const bf16* __restrict__ Al,
             const bf16* __restrict__ Wh, const bf16* __restrict__ Wl,
             const float* __restrict__ bias,
             float* __restrict__ Cf, bf16* __restrict__ Ch, bf16* __restrict__ Cl,
             int M, int N, int K) {
    extern __shared__ __align__(16) char dsm[];
    const uint32_t sb = smem_u32(dsm);
    const int tid = threadIdx.x, lane = tid & 31, wid = tid >> 5;
    const int wm = wid & 3, wn = wid >> 2;
    const int bx = blockIdx.x, by = blockIdx.y;
    const int KT = K >> 6;

    float acc[2][8][4];
#pragma unroll
    for (int i = 0; i < 2; i++)
#pragma unroll
        for (int j = 0; j < 8; j++)
#pragma unroll
            for (int q = 0; q < 4; q++) acc[i][j][q] = 0.f;

    // cp.async mapping: tile 128 rows x 8 chunks(16B); thread t -> chunks t+256i
    const int cr = tid >> 3, cc = tid & 7;
    const size_t aoff = (size_t)(by*128 + cr)*K + cc*8;
    const size_t woff = (size_t)(bx*128 + cr)*K + cc*8;
    uint32_t so[4];
#pragma unroll
    for (int i = 0; i < 4; i++) so[i] = swz64(cr + 32*i, cc);

    const int l16 = lane & 15;
    const int rB = (lane & 7) + ((lane >> 4) << 3);
    const int cB = (lane >> 3) & 1;

#define G_ISSUE(ktn) do {                                                     \
    if ((ktn) < KT) {                                                         \
        const uint32_t stb = sb + (uint32_t)((ktn) % 3) * GSTAGE;             \
        const int ko = (ktn) * 64;                                            \
        _Pragma("unroll")                                                     \
        for (int i = 0; i < 4; i++) {                                         \
            const size_t ro = (size_t)(32*i)*K + ko;                          \
            cpa16(stb + so[i],           Ah + aoff + ro);                     \
            cpa16(stb + 16384u + so[i],  Al + aoff + ro);                     \
            cpa16(stb + 32768u + so[i],  Wh + woff + ro);                     \
            cpa16(stb + 49152u + so[i],  Wl + woff + ro);                     \
        }                                                                     \
    }                                                                         \
    asm volatile("cp.async.commit_group;" ::: "memory");                      \
} while (0)

    G_ISSUE(0); G_ISSUE(1);

    for (int kt = 0; kt < KT; kt++) {
        asm volatile("cp.async.wait_group 1;" ::: "memory");
        __syncthreads();
        G_ISSUE(kt + 2);

        const uint32_t stb = sb + (uint32_t)(kt % 3) * GSTAGE;
#pragma unroll
        for (int ks = 0; ks < 4; ks++) {
            uint32_t ah[2][4], al[2][4];
#pragma unroll
            for (int mt = 0; mt < 2; mt++) {
                const int rowA = wm*32 + mt*16 + l16;
                const uint32_t oa = stb + swz64(rowA, ks*2 + (lane >> 4));
                LDSM4(ah[mt], oa);
                LDSM4(al[mt], oa + 16384u);
            }
#pragma unroll
            for (int ntp = 0; ntp < 4; ntp++) {
                const int rowB = wn*64 + ntp*16 + rB;
                const uint32_t ob = stb + 32768u + swz64(rowB, ks*2 + cB);
                uint32_t bh[4], bl[4];
                LDSM4(bh, ob);
                LDSM4(bl, ob + 16384u);
#pragma unroll
                for (int mt = 0; mt < 2; mt++) {
                    MMA_BF16(acc[mt][2*ntp],   ah[mt], bh);
                    MMA_BF16(acc[mt][2*ntp],   ah[mt], bl);
                    MMA_BF16(acc[mt][2*ntp],   al[mt], bh);
                    MMA_BF16(acc[mt][2*ntp+1], ah[mt], &bh[2]);
                    MMA_BF16(acc[mt][2*ntp+1], ah[mt], &bl[2]);
                    MMA_BF16(acc[mt][2*ntp+1], al[mt], &bh[2]);
                }
            }
        }
    }

    const int rbase = by*128 + wm*32 + (lane >> 2);
    const int cbase = bx*128 + wn*64 + 2*(lane & 3);
#pragma unroll
    for (int mt = 0; mt < 2; mt++) {
#pragma unroll
        for (int nt = 0; nt < 8; nt++) {
            const int row = rbase + mt*16;
            const int col = cbase + nt*8;
            const float b0 = bias[col], b1 = bias[col+1];
            float v0x = acc[mt][nt][0] + b0, v0y = acc[mt][nt][1] + b1;
            float v1x = acc[mt][nt][2] + b0, v1y = acc[mt][nt][3] + b1;
            if (RELU) {
                v0x = fmaxf(v0x, 0.f); v0y = fmaxf(v0y, 0.f);
                v1x = fmaxf(v1x, 0.f); v1y = fmaxf(v1y, 0.f);
            }
            if (SPLIT) {
                float rx, ry;
                uint32_t h = pack_hi(v0x, v0y, rx, ry);
                uint32_t l = pack_lo(rx, ry);
                *(uint32_t*)(Ch + (size_t)row*N + col) = h;
                *(uint32_t*)(Cl + (size_t)row*N + col) = l;
                h = pack_hi(v1x, v1y, rx, ry);
                l = pack_lo(rx, ry);
                *(uint32_t*)(Ch + (size_t)(row+8)*N + col) = h;
                *(uint32_t*)(Cl + (size_t)(row+8)*N + col) = l;
            } else {
                float2 a = {v0x, v0y}, b = {v1x, v1y};
                *(float2*)(Cf + (size_t)row*N + col)     = a;
                *(float2*)(Cf + (size_t)(row+8)*N + col) = b;
            }
        }
    }
}

// ============================================================================
// HMMA flash attention, Q-tile 128, pre-split combined QKV [tok][1536].
// grid (P/128, NH, B), 256 threads = 8 warps (16 q-rows each).
// smem bytes: Qh 0, Ql 18432, Kh 36864, Kl 46080, Vth 55296, Vtl 64512.
// ============================================================================
#define AST 72
#define ATT_SMEM_BYTES 73728

__global__ __launch_bounds__(256)
void attn_mma(const bf16* __restrict__ QKVh, const bf16* __restrict__ QKVl,
              bf16* __restrict__ Ah, bf16* __restrict__ Al) {
    extern __shared__ __align__(16) char smx[];
    bf16* bsm = (bf16*)smx;
    const uint32_t sb = smem_u32(smx);

    const int tid = threadIdx.x;
    const int lane = tid & 31;
    const int wid = tid >> 5;          // 0..7
    const int l16 = lane & 15;
    const int qt = blockIdx.x, hh = blockIdx.y, bb = blockIdx.z;
    const int nbase = bb * PSEQ;
    const int hoff  = hh * DKH;

    // ---- Q tile (128x64): straight 16B copies ----
#pragma unroll
    for (int it = 0; it < 4; it++) {
        int idx = tid + it*256;
        int r = idx >> 3;
        int c8 = (idx & 7) * 8;
        const size_t go = (size_t)(nbase + qt*128 + r)*(3*EMB) + hoff + c8;
        *(uint4*)(smx + r*144 + c8*2)           = *(const uint4*)(QKVh + go);
        *(uint4*)(smx + 18432 + r*144 + c8*2)   = *(const uint4*)(QKVl + go);
    }

    float o_acc[8][4];
#pragma unroll
    for (int i = 0; i < 8; i++)
#pragma unroll
        for (int j = 0; j < 4; j++) o_acc[i][j] = 0.f;
    float m_g = -1e30f, m_g8 = -1e30f, l_g = 0.f, l_g8 = 0.f;

    uint32_t qh[4][4], ql[4][4];
    const uint32_t offA = (uint32_t)(((wid*16 + l16) * AST + (lane >> 4) * 8) * 2);
    const uint32_t offBr = (uint32_t)((((l16 & 7)) * AST + ((l16 >> 3)) * 8) * 2);

    for (int kc = 0; kc < 16; kc++) {
        __syncthreads();
        // ---- K natural copy, V transposed scatter (64 rows) ----
#pragma unroll
        for (int it = 0; it < 2; it++) {
            int idx = tid + it*256;
            int r = idx >> 3;
            int c8 = (idx & 7) * 8;
            const size_t go = (size_t)(nbase + kc*64 + r)*(3*EMB) + hoff + c8;
            *(uint4*)(smx + 36864 + r*144 + c8*2) = *(const uint4*)(QKVh + 512 + go);
            *(uint4*)(smx + 46080 + r*144 + c8*2) = *(const uint4*)(QKVl + 512 + go);
            uint4 vh = *(const uint4*)(QKVh + 1024 + go);
            uint4 vl = *(const uint4*)(QKVl + 1024 + go);
            const bf16* ph = (const bf16*)&vh;
            const bf16* pl = (const bf16*)&vl;
#pragma unroll
            for (int i = 0; i < 8; i++) {
                bsm[27648 + (c8+i)*AST + r] = ph[i];
                bsm[32256 + (c8+i)*AST + r] = pl[i];
            }
        }
        __syncthreads();

        if (kc == 0) {
#pragma unroll
            for (int ks = 0; ks < 4; ks++) {
                LDSM4(qh[ks], sb + offA + (uint32_t)(ks*32));
                LDSM4(ql[ks], sb + 18432u + offA + (uint32_t)(ks*32));
            }
        }

        // ---- S = Q @ K^T ----
        float s[8][4];
#pragma unroll
        for (int nt = 0; nt < 8; nt++)
#pragma unroll
            for (int j = 0; j < 4; j++) s[nt][j] = 0.f;
#pragma unroll
        for (int nt = 0; nt < 8; nt++) {
#pragma unroll
            for (int ks = 0; ks < 4; ks++) {
                uint32_t bh[2], bl[2];
                const uint32_t bo = offBr + (uint32_t)(nt*8*AST*2 + ks*32);
                LDSM2(bh, sb + 36864u + bo);
                LDSM2(bl, sb + 46080u + bo);
                MMA_BF16(s[nt], qh[ks], bh);
                MMA_BF16(s[nt], ql[ks], bh);
                MMA_BF16(s[nt], qh[ks], bl);
            }
        }
#pragma unroll
        for (int nt = 0; nt < 8; nt++) {
            s[nt][0] *= 0.125f; s[nt][1] *= 0.125f;
            s[nt][2] *= 0.125f; s[nt][3] *= 0.125f;
        }

        // ---- online softmax ----
        float cmg = -1e30f, cmg8 = -1e30f;
#pragma unroll
        for (int nt = 0; nt < 8; nt++) {
            cmg  = fmaxf(cmg,  fmaxf(s[nt][0], s[nt][1]));
            cmg8 = fmaxf(cmg8, fmaxf(s[nt][2], s[nt][3]));
        }
        cmg  = fmaxf(cmg,  __shfl_xor_sync(0xffffffffu, cmg, 1));
        cmg  = fmaxf(cmg,  __shfl_xor_sync(0xffffffffu, cmg, 2));
        cmg8 = fmaxf(cmg8, __shfl_xor_sync(0xffffffffu, cmg8, 1));
        cmg8 = fmaxf(cmg8, __shfl_xor_sync(0xffffffffu, cmg8, 2));
        const float mn  = fmaxf(m_g,  cmg);
        const float mn8 = fmaxf(m_g8, cmg8);
        const float alg  = __expf(m_g  - mn);
        const float alg8 = __expf(m_g8 - mn8);
        m_g = mn; m_g8 = mn8;
        float sum = 0.f, sum8 = 0.f;
#pragma unroll
        for (int nt = 0; nt < 8; nt++) {
            s[nt][0] = __expf(s[nt][0] - mn);
            s[nt][1] = __expf(s[nt][1] - mn);
            s[nt][2] = __expf(s[nt][2] - mn8);
            s[nt][3] = __expf(s[nt][3] - mn8);
            sum  += s[nt][0] + s[nt][1];
            sum8 += s[nt][2] + s[nt][3];
        }
        sum  += __shfl_xor_sync(0xffffffffu, sum, 1);
        sum  += __shfl_xor_sync(0xffffffffu, sum, 2);
        sum8 += __shfl_xor_sync(0xffffffffu, sum8, 1);
        sum8 += __shfl_xor_sync(0xffffffffu, sum8, 2);
        l_g  = l_g  * alg  + sum;
        l_g8 = l_g8 * alg8 + sum8;
#pragma unroll
        for (int dt = 0; dt < 8; dt++) {
            o_acc[dt][0] *= alg;  o_acc[dt][1] *= alg;
            o_acc[dt][2] *= alg8; o_acc[dt][3] *= alg8;
        }

        // ---- P fragments from S accums ----
        uint32_t ph[4][4], pl[4][4];
#pragma unroll
        for (int ks = 0; ks < 4; ks++) {
            float r0, r1;
            ph[ks][0] = pack_hi(s[2*ks][0],   s[2*ks][1],   r0, r1); pl[ks][0] = pack_lo(r0, r1);
            ph[ks][1] = pack_hi(s[2*ks][2],   s[2*ks][3],   r0, r1); pl[ks][1] = pack_lo(r0, r1);
            ph[ks][2] = pack_hi(s[2*ks+1][0], s[2*ks+1][1], r0, r1); pl[ks][2] = pack_lo(r0, r1);
            ph[ks][3] = pack_hi(s[2*ks+1][2], s[2*ks+1][3], r0, r1); pl[ks][3] = pack_lo(r0, r1);
        }

        // ---- O += P @ V ----
#pragma unroll
        for (int dt = 0; dt < 8; dt++) {
#pragma unroll
            for (int ks = 0; ks < 4; ks++) {
                uint32_t vh2[2], vl2[2];
                const uint32_t vo = offBr + (uint32_t)(dt*8*AST*2 + ks*32);
                LDSM2(vh2, sb + 55296u + vo);
                LDSM2(vl2, sb + 64512u + vo);
                MMA_BF16(o_acc[dt], ph[ks], vh2);
                MMA_BF16(o_acc[dt], pl[ks], vh2);
                MMA_BF16(o_acc[dt], ph[ks], vl2);
            }
        }
    }

    // ---- epilogue: split-write a ----
    const float ig  = 1.f / l_g;
    const float ig8 = 1.f / l_g8;
    const int g = lane >> 2;
    const int r0 = nbase + qt*128 + wid*16 + g;
    const int cb = hoff + 2*(lane & 3);
#pragma unroll
    for (int dt = 0; dt < 8; dt++) {
        float v0x = o_acc[dt][0]*ig,  v0y = o_acc[dt][1]*ig;
        float v1x = o_acc[dt][2]*ig8, v1y = o_acc[dt][3]*ig8;
        float rx, ry;
        uint32_t h = pack_hi(v0x, v0y, rx, ry);
        uint32_t l = pack_lo(rx, ry);
        *(uint32_t*)(Ah + (size_t)r0*EMB + cb + dt*8) = h;
        *(uint32_t*)(Al + (size_t)r0*EMB + cb + dt*8) = l;
        h = pack_hi(v1x, v1y, rx, ry);
        l = pack_lo(rx, ry);
        *(uint32_t*)(Ah + (size_t)(r0+8)*EMB + cb + dt*8) = h;
        *(uint32_t*)(Al + (size_t)(r0+8)*EMB + cb + dt*8) = l;
    }
}

// ---------------- weight split / pack kernels --------------------------------
__global__ void split_w4(const float* __restrict__ src, bf16* __restrict__ h,
                         bf16* __restrict__ l, int n_per_layer, int dst_stride,
                         int dst_off) {
    int idx = blockIdx.x * blockDim.x + threadIdx.x;
    int total4 = (NLAYER * n_per_layer) >> 2;
    if (idx >= total4) return;
    int base = idx * 4;
    int layer = base / n_per_layer;
    int i = base - layer * n_per_layer;
    float4 v = *(const float4*)(src + base);
    float rx, ry;
    uint32_t h01 = pack_hi(v.x, v.y, rx, ry);
    uint32_t l01 = pack_lo(rx, ry);
    uint32_t h23 = pack_hi(v.z, v.w, rx, ry);
    uint32_t l23 = pack_lo(rx, ry);
    size_t d = (size_t)layer * dst_stride + dst_off + i;
    uint2 hv = {h01, h23}, lv = {l01, l23};
    *(uint2*)(h + d) = hv;
    *(uint2*)(l + d) = lv;
}

__global__ void pack_bqkv(const float* __restrict__ bq, const float* __restrict__ bk,
                          const float* __restrict__ bv, float* __restrict__ dst) {
    int idx = blockIdx.x * blockDim.x + threadIdx.x;
    if (idx >= NLAYER * 3 * EMB) return;
    int l = idx / (3*EMB);
    int n = idx - l * 3*EMB;
    float v;
    if (n < EMB)            v = bq[l*EMB + n];
    else if (n < 2*EMB)     v = bk[l*EMB + n - EMB];
    else                    v = bv[l*EMB + n - 2*EMB];
    dst[idx] = v;
}

// ---------------- positional encoding table --------------------------------
__global__ void pe_kernel(float* __restrict__ pe) {
    int idx = blockIdx.x * blockDim.x + threadIdx.x;
    if (idx >= PSEQ*EMB) return;
    int p = idx >> 9;
    int e = idx & 511;
    int i2 = e >> 1;
    float c = (float)(2*i2) * (-0.017988946039015984f);
    float freqf = (float)exp((double)c);
    float angf  = (float)p * freqf;
    double angle = (double)angf;
    pe[idx] = (e & 1) ? (float)cos(angle) : (float)sin(angle);
}

// ---------------- embedding: conv + linear + PE, writes x + split ------------
__global__ void embed_kernel(const float* __restrict__ data,
                             const float* __restrict__ cw,
                             const float* __restrict__ cb,
                             const float* __restrict__ lw,
                             const float* __restrict__ lb,
                             const float* __restrict__ pe,
                             float* __restrict__ x,
                             bf16* __restrict__ xh, bf16* __restrict__ xl) {
    int idx = blockIdx.x * blockDim.x + threadIdx.x;
    if (idx >= NTOK*EMB) return;
    int n = idx >> 9;
    int e = idx & 511;
    int b = n >> 10;
    int p = n & 1023;
    int pi = p >> 5, pj = p & 31;
    const float* dp = data + b*4096 + (pi*2)*64 + pj*2;
    float conv = dp[0]*cw[0] + dp[1]*cw[1] + dp[64]*cw[2] + dp[65]*cw[3] + cb[0];
    float v = conv * lw[e] + lb[e] + pe[p*EMB + e];
    x[idx] = v;
    bf16 h = __float2bfloat16(v);
    xh[idx] = h;
    xl[idx] = __float2bfloat16(v - __bfloat162float(h));
}

// ---------------- residual add + LayerNorm, writes x + split -----------------
__global__ __launch_bounds__(128)
void add_ln_kernel(float* __restrict__ x, const float* __restrict__ y,
                   const float* __restrict__ gam, const float* __restrict__ bet,
                   bf16* __restrict__ xh, bf16* __restrict__ xl) {
    const int row = blockIdx.x;
    const int tid = threadIdx.x;
    const int e = tid * 4;
    float4 xv = *(float4*)&x[(size_t)row*EMB + e];
    float4 yv = *(const float4*)&y[(size_t)row*EMB + e];
    float t0 = xv.x + yv.x, t1 = xv.y + yv.y, t2 = xv.z + yv.z, t3 = xv.w + yv.w;
    float s  = t0 + t1 + t2 + t3;
    float s2 = t0*t0 + t1*t1 + t2*t2 + t3*t3;
#pragma unroll
    for (int off = 16; off > 0; off >>= 1) {
        s  += __shfl_xor_sync(0xffffffffu, s,  off);
        s2 += __shfl_xor_sync(0xffffffffu, s2, off);
    }
    __shared__ float ws[4], ws2[4];
    int w = tid >> 5;
    if ((tid & 31) == 0) { ws[w] = s; ws2[w] = s2; }
    __syncthreads();
    float S  = ws[0] + ws[1] + ws[2] + ws[3];
    float S2 = ws2[0] + ws2[1] + ws2[2] + ws2[3];
    float mu  = S * (1.f/512.f);
    float var = S2 * (1.f/512.f) - mu*mu;
    float rs = rsqrtf(var + 1e-5f);
    float o0 = (t0 - mu)*rs*gam[e+0] + bet[e+0];
    float o1 = (t1 - mu)*rs*gam[e+1] + bet[e+1];
    float o2 = (t2 - mu)*rs*gam[e+2] + bet[e+2];
    float o3 = (t3 - mu)*rs*gam[e+3] + bet[e+3];
    float4 ov = {o0, o1, o2, o3};
    *(float4*)&x[(size_t)row*EMB + e] = ov;
    float rx, ry;
    uint32_t h01 = pack_hi(o0, o1, rx, ry);
    uint32_t l01 = pack_lo(rx, ry);
    uint32_t h23 = pack_hi(o2, o3, rx, ry);
    uint32_t l23 = pack_lo(rx, ry);
    uint2 hv = {h01, h23}, lv = {l01, l23};
    *(uint2*)(xh + (size_t)row*EMB + e) = hv;
    *(uint2*)(xl + (size_t)row*EMB + e) = lv;
}

// ---------------- mean pool + final linear ----------------------------------
__global__ __launch_bounds__(512)
void pool_head_kernel(const float* __restrict__ x, const float* __restrict__ Wc,
                      const float* __restrict__ bc, float* __restrict__ out) {
    const int b = blockIdx.x;
    const int e = threadIdx.x;
    float s = 0.f;
    const float* xp = x + (size_t)b*PSEQ*EMB + e;
    for (int p = 0; p < PSEQ; p++) s += xp[(size_t)p*EMB];
    float pooled = s * (1.f/1024.f);
    __shared__ float red[512];
    red[e] = pooled * Wc[e];
    __syncthreads();
    for (int st = 256; st > 0; st >>= 1) {
        if (e < st) red[e] += red[e + st];
        __syncthreads();
    }
    if (e == 0) out[b] = red[0] + bc[0];
}

// ---------------- driver -----------------------------------------------------
extern "C" void kernel_launch(void* const* d_in, const int* in_sizes, int n_in,
                              void* d_out, int out_size) {
    const float* data   = (const float*)d_in[0];
    const float* conv_w = (const float*)d_in[1];
    const float* conv_b = (const float*)d_in[2];
    const float* lin_w  = (const float*)d_in[3];
    const float* lin_b  = (const float*)d_in[4];
    const float* Wq     = (const float*)d_in[5];
    const float* bq     = (const float*)d_in[6];
    const float* Wk     = (const float*)d_in[7];
    const float* bk     = (const float*)d_in[8];
    const float* Wv     = (const float*)d_in[9];
    const float* bv     = (const float*)d_in[10];
    const float* Wo     = (const float*)d_in[11];
    const float* bo     = (const float*)d_in[12];
    const float* ln1_g  = (const float*)d_in[13];
    const float* ln1_b  = (const float*)d_in[14];
    const float* ln2_g  = (const float*)d_in[15];
    const float* ln2_b  = (const float*)d_in[16];
    const float* W1     = (const float*)d_in[17];
    const float* b1     = (const float*)d_in[18];
    const float* W2     = (const float*)d_in[19];
    const float* b2     = (const float*)d_in[20];
    const float* Wc     = (const float*)d_in[21];
    const float* bc     = (const float*)d_in[22];
    float* out = (float*)d_out;

    float *px, *pt, *ppe, *pbqkv;
    bf16 *pxh, *pxl, *pqkvh, *pqkvl, *pah, *pal, *phh, *phl;
    bf16 *pwqkvh, *pwqkvl, *pwoh, *pwol, *pw1h, *pw1l, *pw2h, *pw2l;
    cudaGetSymbolAddress((void**)&px,  g_x);
    cudaGetSymbolAddress((void**)&pt,  g_t);
    cudaGetSymbolAddress((void**)&ppe, g_pe);
    cudaGetSymbolAddress((void**)&pxh, g_xh);
    cudaGetSymbolAddress((void**)&pxl, g_xl);
    cudaGetSymbolAddress((void**)&pqkvh, g_qkvh);
    cudaGetSymbolAddress((void**)&pqkvl, g_qkvl);
    cudaGetSymbolAddress((void**)&pah, g_ah);
    cudaGetSymbolAddress((void**)&pal, g_al);
    cudaGetSymbolAddress((void**)&phh, g_hh);
    cudaGetSymbolAddress((void**)&phl, g_hl);
    cudaGetSymbolAddress((void**)&pwqkvh, g_wqkvh);
    cudaGetSymbolAddress((void**)&pwqkvl, g_wqkvl);
    cudaGetSymbolAddress((void**)&pwoh, g_woh);
    cudaGetSymbolAddress((void**)&pwol, g_wol);
    cudaGetSymbolAddress((void**)&pw1h, g_w1h);
    cudaGetSymbolAddress((void**)&pw1l, g_w1l);
    cudaGetSymbolAddress((void**)&pw2h, g_w2h);
    cudaGetSymbolAddress((void**)&pw2l, g_w2l);
    cudaGetSymbolAddress((void**)&pbqkv, g_bqkv);

    cudaFuncSetAttribute(gemm_bf<0,0>, cudaFuncAttributeMaxDynamicSharedMemorySize, GSMEM_BYTES);
    cudaFuncSetAttribute(gemm_bf<0,1>, cudaFuncAttributeMaxDynamicSharedMemorySize, GSMEM_BYTES);
    cudaFuncSetAttribute(gemm_bf<1,1>, cudaFuncAttributeMaxDynamicSharedMemorySize, GSMEM_BYTES);
    cudaFuncSetAttribute(attn_mma, cudaFuncAttributeMaxDynamicSharedMemorySize, ATT_SMEM_BYTES);

    // ---- weight/bias packing (once per call) ----
    const int EE = EMB*EMB;          // 262144
    const int FE = FFD*EMB;          // 1048576
    split_w4<<<(NLAYER*EE/4 + 255)/256, 256>>>(Wq, pwqkvh, pwqkvl, EE, 3*EE, 0);
    split_w4<<<(NLAYER*EE/4 + 255)/256, 256>>>(Wk, pwqkvh, pwqkvl, EE, 3*EE, EE);
    split_w4<<<(NLAYER*EE/4 + 255)/256, 256>>>(Wv, pwqkvh, pwqkvl, EE, 3*EE, 2*EE);
    split_w4<<<(NLAYER*EE/4 + 255)/256, 256>>>(Wo, pwoh, pwol, EE, EE, 0);
    split_w4<<<(NLAYER*FE/4 + 255)/256, 256>>>(W1, pw1h, pw1l, FE, FE, 0);
    split_w4<<<(NLAYER*FE/4 + 255)/256, 256>>>(W2, pw2h, pw2l, FE, FE, 0);
    pack_bqkv<<<(NLAYER*3*EMB + 255)/256, 256>>>(bq, bk, bv, pbqkv);

    pe_kernel<<<(PSEQ*EMB + 255)/256, 256>>>(ppe);
    embed_kernel<<<(NTOK*EMB + 255)/256, 256>>>(data, conv_w, conv_b, lin_w, lin_b,
                                                ppe, px, pxh, pxl);

    for (int l = 0; l < NLAYER; l++) {
        // fused QKV: [NTOK,512] @ [1536,512]^T -> split qkv
        gemm_bf<0,1><<<dim3(12,128), 256, GSMEM_BYTES>>>(
            pxh, pxl, pwqkvh + (size_t)l*3*EE, pwqkvl + (size_t)l*3*EE,
            pbqkv + l*3*EMB, nullptr, pqkvh, pqkvl, NTOK, 3*EMB, EMB);

        attn_mma<<<dim3(PSEQ/128, NHEAD, BATCH), 256, ATT_SMEM_BYTES>>>(
            pqkvh, pqkvl, pah, pal);

        gemm_bf<0,0><<<dim3(4,128), 256, GSMEM_BYTES>>>(
            pah, pal, pwoh + (size_t)l*EE, pwol + (size_t)l*EE,
            bo + l*EMB, pt, nullptr, nullptr, NTOK, EMB, EMB);
        add_ln_kernel<<<NTOK, 128>>>(px, pt, ln1_g + l*EMB, ln1_b + l*EMB, pxh, pxl);

        gemm_bf<1,1><<<dim3(16,128), 256, GSMEM_BYTES>>>(
            pxh, pxl, pw1h + (size_t)l*FE, pw1l + (size_t)l*FE,
            b1 + l*FFD, nullptr, phh, phl, NTOK, FFD, EMB);

        gemm_bf<0,0><<<dim3(4,128), 256, GSMEM_BYTES>>>(
            phh, phl, pw2h + (size_t)l*FE, pw2l + (size_t)l*FE,
            b2 + l*EMB, pt, nullptr, nullptr, NTOK, EMB, FFD);
        add_ln_kernel<<<NTOK, 128>>>(px, pt, ln2_g + l*EMB, ln2_b + l*EMB, pxh, pxl);
    }

    pool_head_kernel<<<BATCH, 512>>>(px, Wc, bc, out);
}

// round 9
// speedup vs baseline: 2.8961x; 1.1401x over previous
#include <cuda_runtime.h>
#include <cuda_bf16.h>
#include <math.h>
#include <stdint.h>

#define BATCH   16
#define PSEQ    1024
#define NTOK    (BATCH*PSEQ)     // 16384
#define EMB     512
#define FFD     2048
#define NLAYER  4
#define NHEAD   8
#define DKH     64

typedef __nv_bfloat16 bf16;

// ---------------- scratch (static device globals; no runtime alloc) ----------
__device__ float g_x [NTOK*EMB];
__device__ float g_t [NTOK*EMB];
__device__ float g_pe[PSEQ*EMB];
__device__ bf16 g_xh[NTOK*EMB],  g_xl[NTOK*EMB];
__device__ bf16 g_qkvh[NTOK*3*EMB], g_qkvl[NTOK*3*EMB];
__device__ bf16 g_ah[NTOK*EMB],  g_al[NTOK*EMB];
__device__ bf16 g_hh[NTOK*FFD],  g_hl[NTOK*FFD];
__device__ bf16 g_wqkvh[NLAYER*3*EMB*EMB], g_wqkvl[NLAYER*3*EMB*EMB];
__device__ bf16 g_woh[NLAYER*EMB*EMB],     g_wol[NLAYER*EMB*EMB];
__device__ bf16 g_w1h[NLAYER*FFD*EMB],     g_w1l[NLAYER*FFD*EMB];
__device__ bf16 g_w2h[NLAYER*EMB*FFD],     g_w2l[NLAYER*EMB*FFD];
__device__ float g_bqkv[NLAYER*3*EMB];

// ============================================================================
// helpers
// ============================================================================
static __device__ __forceinline__ uint32_t smem_u32(const void* p) {
    uint32_t a;
    asm("{ .reg .u64 t; cvta.to.shared.u64 t, %1; cvt.u32.u64 %0, t; }"
        : "=r"(a) : "l"(p));
    return a;
}
static __device__ __forceinline__ uint32_t pack_hi(float a, float b, float& ra, float& rb) {
    bf16 ha = __float2bfloat16(a);
    bf16 hb = __float2bfloat16(b);
    ra = a - __bfloat162float(ha);
    rb = b - __bfloat162float(hb);
    return (uint32_t)__bfloat16_as_ushort(ha) | ((uint32_t)__bfloat16_as_ushort(hb) << 16);
}
static __device__ __forceinline__ uint32_t pack_lo(float a, float b) {
    return (uint32_t)__bfloat16_as_ushort(__float2bfloat16(a)) |
           ((uint32_t)__bfloat16_as_ushort(__float2bfloat16(b)) << 16);
}

#define MMA_BF16(d, a, b) \
    asm volatile("mma.sync.aligned.m16n8k16.row.col.f32.bf16.bf16.f32 " \
        "{%0,%1,%2,%3}, {%4,%5,%6,%7}, {%8,%9}, {%0,%1,%2,%3};" \
        : "+f"((d)[0]), "+f"((d)[1]), "+f"((d)[2]), "+f"((d)[3]) \
        : "r"((a)[0]), "r"((a)[1]), "r"((a)[2]), "r"((a)[3]), \
          "r"((b)[0]), "r"((b)[1]))

#define LDSM4(r, addr) \
    asm volatile("ldmatrix.sync.aligned.m8n8.x4.shared.b16 {%0,%1,%2,%3}, [%4];" \
        : "=r"((r)[0]), "=r"((r)[1]), "=r"((r)[2]), "=r"((r)[3]) : "r"(addr))

#define LDSM4T(r, addr) \
    asm volatile("ldmatrix.sync.aligned.m8n8.x4.trans.shared.b16 {%0,%1,%2,%3}, [%4];" \
        : "=r"((r)[0]), "=r"((r)[1]), "=r"((r)[2]), "=r"((r)[3]) : "r"(addr))

#define LDSM2(r, addr) \
    asm volatile("ldmatrix.sync.aligned.m8n8.x2.shared.b16 {%0,%1}, [%2];" \
        : "=r"((r)[0]), "=r"((r)[1]) : "r"(addr))

static __device__ __forceinline__ void cpa16(uint32_t d, const void* s) {
    asm volatile("cp.async.cg.shared.global [%0], [%1], 16;" :: "r"(d), "l"(s));
}

// swizzled byte offset inside a 128x32-bf16 tile (rows of 64B = 4x16B chunks)
static __device__ __forceinline__ uint32_t swz32(int r, int c) {
    return (uint32_t)(r * 64 + ((c ^ ((r >> 1) & 3)) << 4));
}

// ============================================================================
// bf16 HMMA GEMM on pre-split operands: C = (Ah+Al) @ (Wh+Wl)^T + bias
// (3-term: AhWh + AhWl + AlWh).  BM=BN=128, BK=32, 2-stage cp.async,
// 2 CTAs/SM (64KB smem, <=128 regs). 256 threads = 4(M) x 2(N) warps.
// SPLIT=1: write bf16 hi/lo pair outputs; else fp32.
// ============================================================================
#define GSTAGE 32768u
#define GSMEM_BYTES (2*GSTAGE)   // 65536

template<int RELU, int SPLIT>
__global__ __launch_bounds__(256, 2)
void gemm_bf(const bf16* __restrict__ Ah, const bf16* __restrict__ Al,
             const bf16* __restrict__ Wh, const bf16* __restrict__ Wl,
             const float* __restrict__ bias,
             float* __restrict__ Cf, bf16* __restrict__ Ch, bf16* __restrict__ Cl,
             int M, int N, int K) {
    extern __shared__ __align__(16) char dsm[];
    const uint32_t sb = smem_u32(dsm);
    const int tid = threadIdx.x, lane = tid & 31, wid = tid >> 5;
    const int wm = wid & 3, wn = wid >> 2;
    const int bx = blockIdx.x, by = blockIdx.y;
    const int KT = K >> 5;

    float acc[2][8][4];
#pragma unroll
    for (int i = 0; i < 2; i++)
#pragma unroll
        for (int j = 0; j < 8; j++)
#pragma unroll
            for (int q = 0; q < 4; q++) acc[i][j][q] = 0.f;

    // cp.async mapping: tile 128 rows x 4 chunks(16B); thread -> rows tid>>2, +64
    const int cr = tid >> 2, cc = tid & 3;
    const size_t aoff = (size_t)(by*128 + cr)*K + cc*8;
    const size_t woff = (size_t)(bx*128 + cr)*K + cc*8;
    const uint32_t so0 = swz32(cr, cc), so1 = swz32(cr + 64, cc);

    const int l16 = lane & 15;
    const int rB = (lane & 7) + ((lane >> 4) << 3);
    const int cB = (lane >> 3) & 1;

#define G_ISSUE(ktn) do {                                                     \
    if ((ktn) < KT) {                                                         \
        const uint32_t stb = sb + (uint32_t)((ktn) & 1) * GSTAGE;             \
        const int ko = (ktn) * 32;                                            \
        cpa16(stb + so0,           Ah + aoff + ko);                           \
        cpa16(stb + so1,           Ah + aoff + (size_t)64*K + ko);            \
        cpa16(stb + 8192u + so0,   Al + aoff + ko);                           \
        cpa16(stb + 8192u + so1,   Al + aoff + (size_t)64*K + ko);            \
        cpa16(stb + 16384u + so0,  Wh + woff + ko);                           \
        cpa16(stb + 16384u + so1,  Wh + woff + (size_t)64*K + ko);            \
        cpa16(stb + 24576u + so0,  Wl + woff + ko);                           \
        cpa16(stb + 24576u + so1,  Wl + woff + (size_t)64*K + ko);            \
    }                                                                         \
    asm volatile("cp.async.commit_group;" ::: "memory");                      \
} while (0)

    G_ISSUE(0);

    for (int kt = 0; kt < KT; kt++) {
        G_ISSUE(kt + 1);
        asm volatile("cp.async.wait_group 1;" ::: "memory");
        __syncthreads();

        const uint32_t stb = sb + (uint32_t)(kt & 1) * GSTAGE;
#pragma unroll
        for (int ks = 0; ks < 2; ks++) {
            uint32_t ah[2][4], al[2][4];
#pragma unroll
            for (int mt = 0; mt < 2; mt++) {
                const uint32_t oa = stb + swz32(wm*32 + mt*16 + l16, ks*2 + (lane >> 4));
                LDSM4(ah[mt], oa);
                LDSM4(al[mt], oa + 8192u);
            }
#pragma unroll
            for (int ntp = 0; ntp < 4; ntp++) {
                const uint32_t ob = stb + 16384u + swz32(wn*64 + ntp*16 + rB, ks*2 + cB);
                uint32_t bh[4], bl[4];
                LDSM4(bh, ob);
                LDSM4(bl, ob + 8192u);
#pragma unroll
                for (int mt = 0; mt < 2; mt++) {
                    MMA_BF16(acc[mt][2*ntp],   ah[mt], bh);
                    MMA_BF16(acc[mt][2*ntp],   ah[mt], bl);
                    MMA_BF16(acc[mt][2*ntp],   al[mt], bh);
                    MMA_BF16(acc[mt][2*ntp+1], ah[mt], &bh[2]);
                    MMA_BF16(acc[mt][2*ntp+1], ah[mt], &bl[2]);
                    MMA_BF16(acc[mt][2*ntp+1], al[mt], &bh[2]);
                }
            }
        }
        __syncthreads();   // reads of buffer kt&1 done before it is re-filled
    }

    const int rbase = by*128 + wm*32 + (lane >> 2);
    const int cbase = bx*128 + wn*64 + 2*(lane & 3);
#pragma unroll
    for (int mt = 0; mt < 2; mt++) {
#pragma unroll
        for (int nt = 0; nt < 8; nt++) {
            const int row = rbase + mt*16;
            const int col = cbase + nt*8;
            const float b0 = bias[col], b1 = bias[col+1];
            float v0x = acc[mt][nt][0] + b0, v0y = acc[mt][nt][1] + b1;
            float v1x = acc[mt][nt][2] + b0, v1y = acc[mt][nt][3] + b1;
            if (RELU) {
                v0x = fmaxf(v0x, 0.f); v0y = fmaxf(v0y, 0.f);
                v1x = fmaxf(v1x, 0.f); v1y = fmaxf(v1y, 0.f);
            }
            if (SPLIT) {
                float rx, ry;
                uint32_t h = pack_hi(v0x, v0y, rx, ry);
                uint32_t l = pack_lo(rx, ry);
                *(uint32_t*)(Ch + (size_t)row*N + col) = h;
                *(uint32_t*)(Cl + (size_t)row*N + col) = l;
                h = pack_hi(v1x, v1y, rx, ry);
                l = pack_lo(rx, ry);
                *(uint32_t*)(Ch + (size_t)(row+8)*N + col) = h;
                *(uint32_t*)(Cl + (size_t)(row+8)*N + col) = l;
            } else {
                float2 a = {v0x, v0y}, b = {v1x, v1y};
                *(float2*)(Cf + (size_t)row*N + col)     = a;
                *(float2*)(Cf + (size_t)(row+8)*N + col) = b;
            }
        }
    }
}

// ============================================================================
// HMMA flash attention, Q-tile 128, pre-split combined QKV [tok][1536].
// grid (P/128, NH, B), 256 threads = 8 warps (16 q-rows each).
// V stored naturally [key][d]; P@V B-fragments via ldmatrix.trans.
// smem bytes: Qh 0, Ql 18432, Kh 36864, Kl 46080, Vh 55296, Vl 64512.
// ============================================================================
#define AST 72
#define ATT_SMEM_BYTES 73728

__global__ __launch_bounds__(256)
void attn_mma(const bf16* __restrict__ QKVh, const bf16* __restrict__ QKVl,
              bf16* __restrict__ Ah, bf16* __restrict__ Al) {
    extern __shared__ __align__(16) char smx[];
    const uint32_t sb = smem_u32(smx);

    const int tid = threadIdx.x;
    const int lane = tid & 31;
    const int wid = tid >> 5;          // 0..7
    const int l16 = lane & 15;
    const int qt = blockIdx.x, hh = blockIdx.y, bb = blockIdx.z;
    const int nbase = bb * PSEQ;
    const int hoff  = hh * DKH;

    // ---- Q tile (128x64): straight 16B copies ----
#pragma unroll
    for (int it = 0; it < 4; it++) {
        int idx = tid + it*256;
        int r = idx >> 3;
        int c8 = (idx & 7) * 8;
        const size_t go = (size_t)(nbase + qt*128 + r)*(3*EMB) + hoff + c8;
        *(uint4*)(smx + r*144 + c8*2)           = *(const uint4*)(QKVh + go);
        *(uint4*)(smx + 18432 + r*144 + c8*2)   = *(const uint4*)(QKVl + go);
    }

    float o_acc[8][4];
#pragma unroll
    for (int i = 0; i < 8; i++)
#pragma unroll
        for (int j = 0; j < 4; j++) o_acc[i][j] = 0.f;
    float m_g = -1e30f, m_g8 = -1e30f, l_g = 0.f, l_g8 = 0.f;

    uint32_t qh[4][4], ql[4][4];
    const uint32_t offA = (uint32_t)(((wid*16 + l16) * AST + (lane >> 4) * 8) * 2);
    const uint32_t offBr = (uint32_t)((((l16 & 7)) * AST + ((l16 >> 3)) * 8) * 2);
    // trans-V per-lane address: row = (lane&7) + ((lane>>3)&1)*8, colblk = (lane>>4)*8
    const uint32_t offVt = (uint32_t)((((lane & 7) + ((lane >> 3) & 1) * 8)) * AST * 2
                                      + ((lane >> 4) * 8) * 2);

    for (int kc = 0; kc < 16; kc++) {
        __syncthreads();
        // ---- K and V: straight 16B copies (64 rows each) ----
#pragma unroll
        for (int it = 0; it < 2; it++) {
            int idx = tid + it*256;
            int r = idx >> 3;
            int c8 = (idx & 7) * 8;
            const size_t go = (size_t)(nbase + kc*64 + r)*(3*EMB) + hoff + c8;
            *(uint4*)(smx + 36864 + r*144 + c8*2) = *(const uint4*)(QKVh + 512 + go);
            *(uint4*)(smx + 46080 + r*144 + c8*2) = *(const uint4*)(QKVl + 512 + go);
            *(uint4*)(smx + 55296 + r*144 + c8*2) = *(const uint4*)(QKVh + 1024 + go);
            *(uint4*)(smx + 64512 + r*144 + c8*2) = *(const uint4*)(QKVl + 1024 + go);
        }
        __syncthreads();

        if (kc == 0) {
#pragma unroll
            for (int ks = 0; ks < 4; ks++) {
                LDSM4(qh[ks], sb + offA + (uint32_t)(ks*32));
                LDSM4(ql[ks], sb + 18432u + offA + (uint32_t)(ks*32));
            }
        }

        // ---- S = Q @ K^T ----
        float s[8][4];
#pragma unroll
        for (int nt = 0; nt < 8; nt++)
#pragma unroll
            for (int j = 0; j < 4; j++) s[nt][j] = 0.f;
#pragma unroll
        for (int nt = 0; nt < 8; nt++) {
#pragma unroll
            for (int ks = 0; ks < 4; ks++) {
                uint32_t bh[2], bl[2];
                const uint32_t bo = offBr + (uint32_t)(nt*8*AST*2 + ks*32);
                LDSM2(bh, sb + 36864u + bo);
                LDSM2(bl, sb + 46080u + bo);
                MMA_BF16(s[nt], qh[ks], bh);
                MMA_BF16(s[nt], ql[ks], bh);
                MMA_BF16(s[nt], qh[ks], bl);
            }
        }
#pragma unroll
        for (int nt = 0; nt < 8; nt++) {
            s[nt][0] *= 0.125f; s[nt][1] *= 0.125f;
            s[nt][2] *= 0.125f; s[nt][3] *= 0.125f;
        }

        // ---- online softmax ----
        float cmg = -1e30f, cmg8 = -1e30f;
#pragma unroll
        for (int nt = 0; nt < 8; nt++) {
            cmg  = fmaxf(cmg,  fmaxf(s[nt][0], s[nt][1]));
            cmg8 = fmaxf(cmg8, fmaxf(s[nt][2], s[nt][3]));
        }
        cmg  = fmaxf(cmg,  __shfl_xor_sync(0xffffffffu, cmg, 1));
        cmg  = fmaxf(cmg,  __shfl_xor_sync(0xffffffffu, cmg, 2));
        cmg8 = fmaxf(cmg8, __shfl_xor_sync(0xffffffffu, cmg8, 1));
        cmg8 = fmaxf(cmg8, __shfl_xor_sync(0xffffffffu, cmg8, 2));
        const float mn  = fmaxf(m_g,  cmg);
        const float mn8 = fmaxf(m_g8, cmg8);
        const float alg  = __expf(m_g  - mn);
        const float alg8 = __expf(m_g8 - mn8);
        m_g = mn; m_g8 = mn8;
        float sum = 0.f, sum8 = 0.f;
#pragma unroll
        for (int nt = 0; nt < 8; nt++) {
            s[nt][0] = __expf(s[nt][0] - mn);
            s[nt][1] = __expf(s[nt][1] - mn);
            s[nt][2] = __expf(s[nt][2] - mn8);
            s[nt][3] = __expf(s[nt][3] - mn8);
            sum  += s[nt][0] + s[nt][1];
            sum8 += s[nt][2] + s[nt][3];
        }
        sum  += __shfl_xor_sync(0xffffffffu, sum, 1);
        sum  += __shfl_xor_sync(0xffffffffu, sum, 2);
        sum8 += __shfl_xor_sync(0xffffffffu, sum8, 1);
        sum8 += __shfl_xor_sync(0xffffffffu, sum8, 2);
        l_g  = l_g  * alg  + sum;
        l_g8 = l_g8 * alg8 + sum8;
#pragma unroll
        for (int dt = 0; dt < 8; dt++) {
            o_acc[dt][0] *= alg;  o_acc[dt][1] *= alg;
            o_acc[dt][2] *= alg8; o_acc[dt][3] *= alg8;
        }

        // ---- P fragments from S accums ----
        uint32_t ph[4][4], pl[4][4];
#pragma unroll
        for (int ks = 0; ks < 4; ks++) {
            float r0, r1;
            ph[ks][0] = pack_hi(s[2*ks][0],   s[2*ks][1],   r0, r1); pl[ks][0] = pack_lo(r0, r1);
            ph[ks][1] = pack_hi(s[2*ks][2],   s[2*ks][3],   r0, r1); pl[ks][1] = pack_lo(r0, r1);
            ph[ks][2] = pack_hi(s[2*ks+1][0], s[2*ks+1][1], r0, r1); pl[ks][2] = pack_lo(r0, r1);
            ph[ks][3] = pack_hi(s[2*ks+1][2], s[2*ks+1][3], r0, r1); pl[ks][3] = pack_lo(r0, r1);
        }

        // ---- O += P @ V  (trans ldmatrix on natural V) ----
#pragma unroll
        for (int dt2 = 0; dt2 < 4; dt2++) {
#pragma unroll
            for (int ks = 0; ks < 4; ks++) {
                const uint32_t va = sb + 55296u + offVt
                    + (uint32_t)(ks*16*AST*2 + dt2*32);
                uint32_t vh4[4], vl4[4];
                LDSM4T(vh4, va);
                LDSM4T(vl4, va + 9216u);
                MMA_BF16(o_acc[2*dt2],   ph[ks], vh4);
                MMA_BF16(o_acc[2*dt2],   pl[ks], vh4);
                MMA_BF16(o_acc[2*dt2],   ph[ks], vl4);
                MMA_BF16(o_acc[2*dt2+1], ph[ks], &vh4[2]);
                MMA_BF16(o_acc[2*dt2+1], pl[ks], &vh4[2]);
                MMA_BF16(o_acc[2*dt2+1], ph[ks], &vl4[2]);
            }
        }
    }

    // ---- epilogue: split-write a ----
    const float ig  = 1.f / l_g;
    const float ig8 = 1.f / l_g8;
    const int g = lane >> 2;
    const int r0 = nbase + qt*128 + wid*16 + g;
    const int cb = hoff + 2*(lane & 3);
#pragma unroll
    for (int dt = 0; dt < 8; dt++) {
        float v0x = o_acc[dt][0]*ig,  v0y = o_acc[dt][1]*ig;
        float v1x = o_acc[dt][2]*ig8, v1y = o_acc[dt][3]*ig8;
        float rx, ry;
        uint32_t h = pack_hi(v0x, v0y, rx, ry);
        uint32_t l = pack_lo(rx, ry);
        *(uint32_t*)(Ah + (size_t)r0*EMB + cb + dt*8) = h;
        *(uint32_t*)(Al + (size_t)r0*EMB + cb + dt*8) = l;
        h = pack_hi(v1x, v1y, rx, ry);
        l = pack_lo(rx, ry);
        *(uint32_t*)(Ah + (size_t)(r0+8)*EMB + cb + dt*8) = h;
        *(uint32_t*)(Al + (size_t)(r0+8)*EMB + cb + dt*8) = l;
    }
}

// ---------------- weight split / pack kernels --------------------------------
__global__ void split_w4(const float* __restrict__ src, bf16* __restrict__ h,
                         bf16* __restrict__ l, int n_per_layer, int dst_stride,
                         int dst_off) {
    int idx = blockIdx.x * blockDim.x + threadIdx.x;
    int total4 = (NLAYER * n_per_layer) >> 2;
    if (idx >= total4) return;
    int base = idx * 4;
    int layer = base / n_per_layer;
    int i = base - layer * n_per_layer;
    float4 v = *(const float4*)(src + base);
    float rx, ry;
    uint32_t h01 = pack_hi(v.x, v.y, rx, ry);
    uint32_t l01 = pack_lo(rx, ry);
    uint32_t h23 = pack_hi(v.z, v.w, rx, ry);
    uint32_t l23 = pack_lo(rx, ry);
    size_t d = (size_t)layer * dst_stride + dst_off + i;
    uint2 hv = {h01, h23}, lv = {l01, l23};
    *(uint2*)(h + d) = hv;
    *(uint2*)(l + d) = lv;
}

__global__ void pack_bqkv(const float* __restrict__ bq, const float* __restrict__ bk,
                          const float* __restrict__ bv, float* __restrict__ dst) {
    int idx = blockIdx.x * blockDim.x + threadIdx.x;
    if (idx >= NLAYER * 3 * EMB) return;
    int l = idx / (3*EMB);
    int n = idx - l * 3*EMB;
    float v;
    if (n < EMB)            v = bq[l*EMB + n];
    else if (n < 2*EMB)     v = bk[l*EMB + n - EMB];
    else                    v = bv[l*EMB + n - 2*EMB];
    dst[idx] = v;
}

// ---------------- positional encoding table --------------------------------
__global__ void pe_kernel(float* __restrict__ pe) {
    int idx = blockIdx.x * blockDim.x + threadIdx.x;
    if (idx >= PSEQ*EMB) return;
    int p = idx >> 9;
    int e = idx & 511;
    int i2 = e >> 1;
    float c = (float)(2*i2) * (-0.017988946039015984f);
    float freqf = (float)exp((double)c);
    float angf  = (float)p * freqf;
    double angle = (double)angf;
    pe[idx] = (e & 1) ? (float)cos(angle) : (float)sin(angle);
}

// ---------------- embedding: conv + linear + PE, writes x + split ------------
__global__ void embed_kernel(const float* __restrict__ data,
                             const float* __restrict__ cw,
                             const float* __restrict__ cb,
                             const float* __restrict__ lw,
                             const float* __restrict__ lb,
                             const float* __restrict__ pe,
                             float* __restrict__ x,
                             bf16* __restrict__ xh, bf16* __restrict__ xl) {
    int idx = blockIdx.x * blockDim.x + threadIdx.x;
    if (idx >= NTOK*EMB) return;
    int n = idx >> 9;
    int e = idx & 511;
    int b = n >> 10;
    int p = n & 1023;
    int pi = p >> 5, pj = p & 31;
    const float* dp = data + b*4096 + (pi*2)*64 + pj*2;
    float conv = dp[0]*cw[0] + dp[1]*cw[1] + dp[64]*cw[2] + dp[65]*cw[3] + cb[0];
    float v = conv * lw[e] + lb[e] + pe[p*EMB + e];
    x[idx] = v;
    bf16 h = __float2bfloat16(v);
    xh[idx] = h;
    xl[idx] = __float2bfloat16(v - __bfloat162float(h));
}

// ---------------- residual add + LayerNorm, writes x + split -----------------
__global__ __launch_bounds__(128)
void add_ln_kernel(float* __restrict__ x, const float* __restrict__ y,
                   const float* __restrict__ gam, const float* __restrict__ bet,
                   bf16* __restrict__ xh, bf16* __restrict__ xl) {
    const int row = blockIdx.x;
    const int tid = threadIdx.x;
    const int e = tid * 4;
    float4 xv = *(float4*)&x[(size_t)row*EMB + e];
    float4 yv = *(const float4*)&y[(size_t)row*EMB + e];
    float t0 = xv.x + yv.x, t1 = xv.y + yv.y, t2 = xv.z + yv.z, t3 = xv.w + yv.w;
    float s  = t0 + t1 + t2 + t3;
    float s2 = t0*t0 + t1*t1 + t2*t2 + t3*t3;
#pragma unroll
    for (int off = 16; off > 0; off >>= 1) {
        s  += __shfl_xor_sync(0xffffffffu, s,  off);
        s2 += __shfl_xor_sync(0xffffffffu, s2, off);
    }
    __shared__ float ws[4], ws2[4];
    int w = tid >> 5;
    if ((tid & 31) == 0) { ws[w] = s; ws2[w] = s2; }
    __syncthreads();
    float S  = ws[0] + ws[1] + ws[2] + ws[3];
    float S2 = ws2[0] + ws2[1] + ws2[2] + ws2[3];
    float mu  = S * (1.f/512.f);
    float var = S2 * (1.f/512.f) - mu*mu;
    float rs = rsqrtf(var + 1e-5f);
    float o0 = (t0 - mu)*rs*gam[e+0] + bet[e+0];
    float o1 = (t1 - mu)*rs*gam[e+1] + bet[e+1];
    float o2 = (t2 - mu)*rs*gam[e+2] + bet[e+2];
    float o3 = (t3 - mu)*rs*gam[e+3] + bet[e+3];
    float4 ov = {o0, o1, o2, o3};
    *(float4*)&x[(size_t)row*EMB + e] = ov;
    float rx, ry;
    uint32_t h01 = pack_hi(o0, o1, rx, ry);
    uint32_t l01 = pack_lo(rx, ry);
    uint32_t h23 = pack_hi(o2, o3, rx, ry);
    uint32_t l23 = pack_lo(rx, ry);
    uint2 hv = {h01, h23}, lv = {l01, l23};
    *(uint2*)(xh + (size_t)row*EMB + e) = hv;
    *(uint2*)(xl + (size_t)row*EMB + e) = lv;
}

// ---------------- mean pool + final linear ----------------------------------
__global__ __launch_bounds__(512)
void pool_head_kernel(const float* __restrict__ x, const float* __restrict__ Wc,
                      const float* __restrict__ bc, float* __restrict__ out) {
    const int b = blockIdx.x;
    const int e = threadIdx.x;
    float s = 0.f;
    const float* xp = x + (size_t)b*PSEQ*EMB + e;
    for (int p = 0; p < PSEQ; p++) s += xp[(size_t)p*EMB];
    float pooled = s * (1.f/1024.f);
    __shared__ float red[512];
    red[e] = pooled * Wc[e];
    __syncthreads();
    for (int st = 256; st > 0; st >>= 1) {
        if (e < st) red[e] += red[e + st];
        __syncthreads();
    }
    if (e == 0) out[b] = red[0] + bc[0];
}

// ---------------- driver -----------------------------------------------------
extern "C" void kernel_launch(void* const* d_in, const int* in_sizes, int n_in,
                              void* d_out, int out_size) {
    const float* data   = (const float*)d_in[0];
    const float* conv_w = (const float*)d_in[1];
    const float* conv_b = (const float*)d_in[2];
    const float* lin_w  = (const float*)d_in[3];
    const float* lin_b  = (const float*)d_in[4];
    const float* Wq     = (const float*)d_in[5];
    const float* bq     = (const float*)d_in[6];
    const float* Wk     = (const float*)d_in[7];
    const float* bk     = (const float*)d_in[8];
    const float* Wv     = (const float*)d_in[9];
    const float* bv     = (const float*)d_in[10];
    const float* Wo     = (const float*)d_in[11];
    const float* bo     = (const float*)d_in[12];
    const float* ln1_g  = (const float*)d_in[13];
    const float* ln1_b  = (const float*)d_in[14];
    const float* ln2_g  = (const float*)d_in[15];
    const float* ln2_b  = (const float*)d_in[16];
    const float* W1     = (const float*)d_in[17];
    const float* b1     = (const float*)d_in[18];
    const float* W2     = (const float*)d_in[19];
    const float* b2     = (const float*)d_in[20];
    const float* Wc     = (const float*)d_in[21];
    const float* bc     = (const float*)d_in[22];
    float* out = (float*)d_out;

    float *px, *pt, *ppe, *pbqkv;
    bf16 *pxh, *pxl, *pqkvh, *pqkvl, *pah, *pal, *phh, *phl;
    bf16 *pwqkvh, *pwqkvl, *pwoh, *pwol, *pw1h, *pw1l, *pw2h, *pw2l;
    cudaGetSymbolAddress((void**)&px,  g_x);
    cudaGetSymbolAddress((void**)&pt,  g_t);
    cudaGetSymbolAddress((void**)&ppe, g_pe);
    cudaGetSymbolAddress((void**)&pxh, g_xh);
    cudaGetSymbolAddress((void**)&pxl, g_xl);
    cudaGetSymbolAddress((void**)&pqkvh, g_qkvh);
    cudaGetSymbolAddress((void**)&pqkvl, g_qkvl);
    cudaGetSymbolAddress((void**)&pah, g_ah);
    cudaGetSymbolAddress((void**)&pal, g_al);
    cudaGetSymbolAddress((void**)&phh, g_hh);
    cudaGetSymbolAddress((void**)&phl, g_hl);
    cudaGetSymbolAddress((void**)&pwqkvh, g_wqkvh);
    cudaGetSymbolAddress((void**)&pwqkvl, g_wqkvl);
    cudaGetSymbolAddress((void**)&pwoh, g_woh);
    cudaGetSymbolAddress((void**)&pwol, g_wol);
    cudaGetSymbolAddress((void**)&pw1h, g_w1h);
    cudaGetSymbolAddress((void**)&pw1l, g_w1l);
    cudaGetSymbolAddress((void**)&pw2h, g_w2h);
    cudaGetSymbolAddress((void**)&pw2l, g_w2l);
    cudaGetSymbolAddress((void**)&pbqkv, g_bqkv);

    cudaFuncSetAttribute(gemm_bf<0,0>, cudaFuncAttributeMaxDynamicSharedMemorySize, GSMEM_BYTES);
    cudaFuncSetAttribute(gemm_bf<0,1>, cudaFuncAttributeMaxDynamicSharedMemorySize, GSMEM_BYTES);
    cudaFuncSetAttribute(gemm_bf<1,1>, cudaFuncAttributeMaxDynamicSharedMemorySize, GSMEM_BYTES);
    cudaFuncSetAttribute(attn_mma, cudaFuncAttributeMaxDynamicSharedMemorySize, ATT_SMEM_BYTES);

    // ---- weight/bias packing (once per call) ----
    const int EE = EMB*EMB;          // 262144
    const int FE = FFD*EMB;          // 1048576
    split_w4<<<(NLAYER*EE/4 + 255)/256, 256>>>(Wq, pwqkvh, pwqkvl, EE, 3*EE, 0);
    split_w4<<<(NLAYER*EE/4 + 255)/256, 256>>>(Wk, pwqkvh, pwqkvl, EE, 3*EE, EE);
    split_w4<<<(NLAYER*EE/4 + 255)/256, 256>>>(Wv, pwqkvh, pwqkvl, EE, 3*EE, 2*EE);
    split_w4<<<(NLAYER*EE/4 + 255)/256, 256>>>(Wo, pwoh, pwol, EE, EE, 0);
    split_w4<<<(NLAYER*FE/4 + 255)/256, 256>>>(W1, pw1h, pw1l, FE, FE, 0);
    split_w4<<<(NLAYER*FE/4 + 255)/256, 256>>>(W2, pw2h, pw2l, FE, FE, 0);
    pack_bqkv<<<(NLAYER*3*EMB + 255)/256, 256>>>(bq, bk, bv, pbqkv);

    pe_kernel<<<(PSEQ*EMB + 255)/256, 256>>>(ppe);
    embed_kernel<<<(NTOK*EMB + 255)/256, 256>>>(data, conv_w, conv_b, lin_w, lin_b,
                                                ppe, px, pxh, pxl);

    for (int l = 0; l < NLAYER; l++) {
        // fused QKV: [NTOK,512] @ [1536,512]^T -> split qkv
        gemm_bf<0,1><<<dim3(12,128), 256, GSMEM_BYTES>>>(
            pxh, pxl, pwqkvh + (size_t)l*3*EE, pwqkvl + (size_t)l*3*EE,
            pbqkv + l*3*EMB, nullptr, pqkvh, pqkvl, NTOK, 3*EMB, EMB);

        attn_mma<<<dim3(PSEQ/128, NHEAD, BATCH), 256, ATT_SMEM_BYTES>>>(
            pqkvh, pqkvl, pah, pal);

        gemm_bf<0,0><<<dim3(4,128), 256, GSMEM_BYTES>>>(
            pah, pal, pwoh + (size_t)l*EE, pwol + (size_t)l*EE,
            bo + l*EMB, pt, nullptr, nullptr, NTOK, EMB, EMB);
        add_ln_kernel<<<NTOK, 128>>>(px, pt, ln1_g + l*EMB, ln1_b + l*EMB, pxh, pxl);

        gemm_bf<1,1><<<dim3(16,128), 256, GSMEM_BYTES>>>(
            pxh, pxl, pw1h + (size_t)l*FE, pw1l + (size_t)l*FE,
            b1 + l*FFD, nullptr, phh, phl, NTOK, FFD, EMB);

        gemm_bf<0,0><<<dim3(4,128), 256, GSMEM_BYTES>>>(
            phh, phl, pw2h + (size_t)l*FE, pw2l + (size_t)l*FE,
            b2 + l*EMB, pt, nullptr, nullptr, NTOK, EMB, FFD);
        add_ln_kernel<<<NTOK, 128>>>(px, pt, ln2_g + l*EMB, ln2_b + l*EMB, pxh, pxl);
    }

    pool_head_kernel<<<BATCH, 512>>>(px, Wc, bc, out);
}

// round 10
// speedup vs baseline: 2.9931x; 1.0335x over previous
#include <cuda_runtime.h>
#include <cuda_bf16.h>
#include <math.h>
#include <stdint.h>

#define BATCH   16
#define PSEQ    1024
#define NTOK    (BATCH*PSEQ)     // 16384
#define EMB     512
#define FFD     2048
#define NLAYER  4
#define NHEAD   8
#define DKH     64

typedef __nv_bfloat16 bf16;

// ---------------- scratch (static device globals; no runtime alloc) ----------
__device__ float g_x [NTOK*EMB];
__device__ float g_t [NTOK*EMB];
__device__ float g_pe[PSEQ*EMB];
__device__ bf16 g_xh[NTOK*EMB],  g_xl[NTOK*EMB];
__device__ bf16 g_qkvh[NTOK*3*EMB], g_qkvl[NTOK*3*EMB];
__device__ bf16 g_ah[NTOK*EMB],  g_al[NTOK*EMB];
__device__ bf16 g_hh[NTOK*FFD],  g_hl[NTOK*FFD];
__device__ bf16 g_wqkvh[NLAYER*3*EMB*EMB], g_wqkvl[NLAYER*3*EMB*EMB];
__device__ bf16 g_woh[NLAYER*EMB*EMB],     g_wol[NLAYER*EMB*EMB];
__device__ bf16 g_w1h[NLAYER*FFD*EMB],     g_w1l[NLAYER*FFD*EMB];
__device__ bf16 g_w2h[NLAYER*EMB*FFD],     g_w2l[NLAYER*EMB*FFD];
__device__ float g_bqkv[NLAYER*3*EMB];

// ============================================================================
// helpers
// ============================================================================
static __device__ __forceinline__ uint32_t smem_u32(const void* p) {
    uint32_t a;
    asm("{ .reg .u64 t; cvta.to.shared.u64 t, %1; cvt.u32.u64 %0, t; }"
        : "=r"(a) : "l"(p));
    return a;
}
static __device__ __forceinline__ uint32_t pack_hi(float a, float b, float& ra, float& rb) {
    bf16 ha = __float2bfloat16(a);
    bf16 hb = __float2bfloat16(b);
    ra = a - __bfloat162float(ha);
    rb = b - __bfloat162float(hb);
    return (uint32_t)__bfloat16_as_ushort(ha) | ((uint32_t)__bfloat16_as_ushort(hb) << 16);
}
static __device__ __forceinline__ uint32_t pack_lo(float a, float b) {
    return (uint32_t)__bfloat16_as_ushort(__float2bfloat16(a)) |
           ((uint32_t)__bfloat16_as_ushort(__float2bfloat16(b)) << 16);
}

#define MMA_BF16(d, a, b) \
    asm volatile("mma.sync.aligned.m16n8k16.row.col.f32.bf16.bf16.f32 " \
        "{%0,%1,%2,%3}, {%4,%5,%6,%7}, {%8,%9}, {%0,%1,%2,%3};" \
        : "+f"((d)[0]), "+f"((d)[1]), "+f"((d)[2]), "+f"((d)[3]) \
        : "r"((a)[0]), "r"((a)[1]), "r"((a)[2]), "r"((a)[3]), \
          "r"((b)[0]), "r"((b)[1]))

#define LDSM4(r, addr) \
    asm volatile("ldmatrix.sync.aligned.m8n8.x4.shared.b16 {%0,%1,%2,%3}, [%4];" \
        : "=r"((r)[0]), "=r"((r)[1]), "=r"((r)[2]), "=r"((r)[3]) : "r"(addr))

#define LDSM4T(r, addr) \
    asm volatile("ldmatrix.sync.aligned.m8n8.x4.trans.shared.b16 {%0,%1,%2,%3}, [%4];" \
        : "=r"((r)[0]), "=r"((r)[1]), "=r"((r)[2]), "=r"((r)[3]) : "r"(addr))

#define LDSM2(r, addr) \
    asm volatile("ldmatrix.sync.aligned.m8n8.x2.shared.b16 {%0,%1}, [%2];" \
        : "=r"((r)[0]), "=r"((r)[1]) : "r"(addr))

static __device__ __forceinline__ void cpa16(uint32_t d, const void* s) {
    asm volatile("cp.async.cg.shared.global [%0], [%1], 16;" :: "r"(d), "l"(s));
}

// swizzled byte offset inside a 128x32-bf16 tile (rows of 64B = 4x16B chunks)
static __device__ __forceinline__ uint32_t swz32(int r, int c) {
    return (uint32_t)(r * 64 + ((c ^ ((r >> 1) & 3)) << 4));
}

// ============================================================================
// bf16 HMMA GEMM on pre-split operands: C = (Ah+Al) @ (Wh+Wl)^T + bias
// (3-term: AhWh + AhWl + AlWh).  BM=BN=128, BK=32, 2-stage cp.async,
// 2 CTAs/SM (64KB smem, <=128 regs). 256 threads = 4(M) x 2(N) warps.
// SPLIT=1: write bf16 hi/lo pair outputs; else fp32.
// ============================================================================
#define GSTAGE 32768u
#define GSMEM_BYTES (2*GSTAGE)   // 65536

template<int RELU, int SPLIT>
__global__ __launch_bounds__(256, 2)
void gemm_bf(const bf16* __restrict__ Ah, const bf16* __restrict__ Al,
             const bf16* __restrict__ Wh, const bf16* __restrict__ Wl,
             const float* __restrict__ bias,
             float* __restrict__ Cf, bf16* __restrict__ Ch, bf16* __restrict__ Cl,
             int M, int N, int K) {
    extern __shared__ __align__(16) char dsm[];
    const uint32_t sb = smem_u32(dsm);
    const int tid = threadIdx.x, lane = tid & 31, wid = tid >> 5;
    const int wm = wid & 3, wn = wid >> 2;
    const int bx = blockIdx.x, by = blockIdx.y;
    const int KT = K >> 5;

    float acc[2][8][4];
#pragma unroll
    for (int i = 0; i < 2; i++)
#pragma unroll
        for (int j = 0; j < 8; j++)
#pragma unroll
            for (int q = 0; q < 4; q++) acc[i][j][q] = 0.f;

    const int cr = tid >> 2, cc = tid & 3;
    const size_t aoff = (size_t)(by*128 + cr)*K + cc*8;
    const size_t woff = (size_t)(bx*128 + cr)*K + cc*8;
    const uint32_t so0 = swz32(cr, cc), so1 = swz32(cr + 64, cc);

    const int l16 = lane & 15;
    const int rB = (lane & 7) + ((lane >> 4) << 3);
    const int cB = (lane >> 3) & 1;

#define G_ISSUE(ktn) do {                                                     \
    if ((ktn) < KT) {                                                         \
        const uint32_t stb = sb + (uint32_t)((ktn) & 1) * GSTAGE;             \
        const int ko = (ktn) * 32;                                            \
        cpa16(stb + so0,           Ah + aoff + ko);                           \
        cpa16(stb + so1,           Ah + aoff + (size_t)64*K + ko);            \
        cpa16(stb + 8192u + so0,   Al + aoff + ko);                           \
        cpa16(stb + 8192u + so1,   Al + aoff + (size_t)64*K + ko);            \
        cpa16(stb + 16384u + so0,  Wh + woff + ko);                           \
        cpa16(stb + 16384u + so1,  Wh + woff + (size_t)64*K + ko);            \
        cpa16(stb + 24576u + so0,  Wl + woff + ko);                           \
        cpa16(stb + 24576u + so1,  Wl + woff + (size_t)64*K + ko);            \
    }                                                                         \
    asm volatile("cp.async.commit_group;" ::: "memory");                      \
} while (0)

    G_ISSUE(0);

    for (int kt = 0; kt < KT; kt++) {
        G_ISSUE(kt + 1);
        asm volatile("cp.async.wait_group 1;" ::: "memory");
        __syncthreads();

        const uint32_t stb = sb + (uint32_t)(kt & 1) * GSTAGE;
#pragma unroll
        for (int ks = 0; ks < 2; ks++) {
            uint32_t ah[2][4], al[2][4];
#pragma unroll
            for (int mt = 0; mt < 2; mt++) {
                const uint32_t oa = stb + swz32(wm*32 + mt*16 + l16, ks*2 + (lane >> 4));
                LDSM4(ah[mt], oa);
                LDSM4(al[mt], oa + 8192u);
            }
#pragma unroll
            for (int ntp = 0; ntp < 4; ntp++) {
                const uint32_t ob = stb + 16384u + swz32(wn*64 + ntp*16 + rB, ks*2 + cB);
                uint32_t bh[4], bl[4];
                LDSM4(bh, ob);
                LDSM4(bl, ob + 8192u);
#pragma unroll
                for (int mt = 0; mt < 2; mt++) {
                    MMA_BF16(acc[mt][2*ntp],   ah[mt], bh);
                    MMA_BF16(acc[mt][2*ntp],   ah[mt], bl);
                    MMA_BF16(acc[mt][2*ntp],   al[mt], bh);
                    MMA_BF16(acc[mt][2*ntp+1], ah[mt], &bh[2]);
                    MMA_BF16(acc[mt][2*ntp+1], ah[mt], &bl[2]);
                    MMA_BF16(acc[mt][2*ntp+1], al[mt], &bh[2]);
                }
            }
        }
        __syncthreads();   // reads of buffer kt&1 done before it is re-filled
    }

    const int rbase = by*128 + wm*32 + (lane >> 2);
    const int cbase = bx*128 + wn*64 + 2*(lane & 3);
#pragma unroll
    for (int mt = 0; mt < 2; mt++) {
#pragma unroll
        for (int nt = 0; nt < 8; nt++) {
            const int row = rbase + mt*16;
            const int col = cbase + nt*8;
            const float b0 = bias[col], b1 = bias[col+1];
            float v0x = acc[mt][nt][0] + b0, v0y = acc[mt][nt][1] + b1;
            float v1x = acc[mt][nt][2] + b0, v1y = acc[mt][nt][3] + b1;
            if (RELU) {
                v0x = fmaxf(v0x, 0.f); v0y = fmaxf(v0y, 0.f);
                v1x = fmaxf(v1x, 0.f); v1y = fmaxf(v1y, 0.f);
            }
            if (SPLIT) {
                float rx, ry;
                uint32_t h = pack_hi(v0x, v0y, rx, ry);
                uint32_t l = pack_lo(rx, ry);
                *(uint32_t*)(Ch + (size_t)row*N + col) = h;
                *(uint32_t*)(Cl + (size_t)row*N + col) = l;
                h = pack_hi(v1x, v1y, rx, ry);
                l = pack_lo(rx, ry);
                *(uint32_t*)(Ch + (size_t)(row+8)*N + col) = h;
                *(uint32_t*)(Cl + (size_t)(row+8)*N + col) = l;
            } else {
                float2 a = {v0x, v0y}, b = {v1x, v1y};
                *(float2*)(Cf + (size_t)row*N + col)     = a;
                *(float2*)(Cf + (size_t)(row+8)*N + col) = b;
            }
        }
    }
}

// ============================================================================
// HMMA flash attention, Q-tile 128, cp.async double-buffered K/V.
// grid (P/128, NH, B), 256 threads = 8 warps (16 q-rows each).
// smem: Qh 0, Ql 18432; stage s (s=0,1) at 36864+s*36864:
//       Kh +0, Kl +9216, Vh +18432, Vl +27648.
// ============================================================================
#define AST 72
#define KVSTG 36864u
#define ATT_SMEM_BYTES (36864 + 2*36864)   // 110592

__global__ __launch_bounds__(256)
void attn_mma(const bf16* __restrict__ QKVh, const bf16* __restrict__ QKVl,
              bf16* __restrict__ Ah, bf16* __restrict__ Al) {
    extern __shared__ __align__(16) char smx[];
    const uint32_t sb = smem_u32(smx);

    const int tid = threadIdx.x;
    const int lane = tid & 31;
    const int wid = tid >> 5;          // 0..7
    const int l16 = lane & 15;
    const int qt = blockIdx.x, hh = blockIdx.y, bb = blockIdx.z;
    const int nbase = bb * PSEQ;
    const int hoff  = hh * DKH;

#define KV_ISSUE(kcn) do {                                                    \
    if ((kcn) < 16) {                                                         \
        const uint32_t B = sb + 36864u + (uint32_t)((kcn) & 1) * KVSTG;       \
        _Pragma("unroll")                                                     \
        for (int it = 0; it < 2; it++) {                                      \
            int idx = tid + it*256;                                           \
            int r = idx >> 3;                                                 \
            int c8 = (idx & 7) * 8;                                           \
            const size_t go = (size_t)(nbase + (kcn)*64 + r)*(3*EMB) + hoff + c8; \
            const uint32_t o = (uint32_t)(r*144 + c8*2);                      \
            cpa16(B + o,           QKVh + 512 + go);                          \
            cpa16(B + 9216u + o,   QKVl + 512 + go);                          \
            cpa16(B + 18432u + o,  QKVh + 1024 + go);                         \
            cpa16(B + 27648u + o,  QKVl + 1024 + go);                         \
        }                                                                     \
    }                                                                         \
    asm volatile("cp.async.commit_group;" ::: "memory");                      \
} while (0)

    // ---- Q tile (128x64) via cp.async; grouped with KV chunk 0 ----
#pragma unroll
    for (int it = 0; it < 4; it++) {
        int idx = tid + it*256;
        int r = idx >> 3;
        int c8 = (idx & 7) * 8;
        const size_t go = (size_t)(nbase + qt*128 + r)*(3*EMB) + hoff + c8;
        const uint32_t o = (uint32_t)(r*144 + c8*2);
        cpa16(sb + o,           QKVh + go);
        cpa16(sb + 18432u + o,  QKVl + go);
    }
    KV_ISSUE(0);      // commits group0 = {Q, KV0}
    KV_ISSUE(1);      // group1 = {KV1}

    float o_acc[8][4];
#pragma unroll
    for (int i = 0; i < 8; i++)
#pragma unroll
        for (int j = 0; j < 4; j++) o_acc[i][j] = 0.f;
    float m_g = -1e30f, m_g8 = -1e30f, l_g = 0.f, l_g8 = 0.f;

    uint32_t qh[4][4], ql[4][4];
    const uint32_t offA = (uint32_t)(((wid*16 + l16) * AST + (lane >> 4) * 8) * 2);
    const uint32_t offBr = (uint32_t)((((l16 & 7)) * AST + ((l16 >> 3)) * 8) * 2);
    const uint32_t offVt = (uint32_t)((((lane & 7) + ((lane >> 3) & 1) * 8)) * AST * 2
                                      + ((lane >> 4) * 8) * 2);

    for (int kc = 0; kc < 16; kc++) {
        asm volatile("cp.async.wait_group 1;" ::: "memory");
        __syncthreads();
        const uint32_t stB = sb + 36864u + (uint32_t)(kc & 1) * KVSTG;

        if (kc == 0) {
#pragma unroll
            for (int ks = 0; ks < 4; ks++) {
                LDSM4(qh[ks], sb + offA + (uint32_t)(ks*32));
                LDSM4(ql[ks], sb + 18432u + offA + (uint32_t)(ks*32));
            }
        }

        // ---- S = Q @ K^T ----
        float s[8][4];
#pragma unroll
        for (int nt = 0; nt < 8; nt++)
#pragma unroll
            for (int j = 0; j < 4; j++) s[nt][j] = 0.f;
#pragma unroll
        for (int nt = 0; nt < 8; nt++) {
#pragma unroll
            for (int ks = 0; ks < 4; ks++) {
                uint32_t bh[2], bl[2];
                const uint32_t bo = offBr + (uint32_t)(nt*8*AST*2 + ks*32);
                LDSM2(bh, stB + bo);
                LDSM2(bl, stB + 9216u + bo);
                MMA_BF16(s[nt], qh[ks], bh);
                MMA_BF16(s[nt], ql[ks], bh);
                MMA_BF16(s[nt], qh[ks], bl);
            }
        }
#pragma unroll
        for (int nt = 0; nt < 8; nt++) {
            s[nt][0] *= 0.125f; s[nt][1] *= 0.125f;
            s[nt][2] *= 0.125f; s[nt][3] *= 0.125f;
        }

        // ---- online softmax ----
        float cmg = -1e30f, cmg8 = -1e30f;
#pragma unroll
        for (int nt = 0; nt < 8; nt++) {
            cmg  = fmaxf(cmg,  fmaxf(s[nt][0], s[nt][1]));
            cmg8 = fmaxf(cmg8, fmaxf(s[nt][2], s[nt][3]));
        }
        cmg  = fmaxf(cmg,  __shfl_xor_sync(0xffffffffu, cmg, 1));
        cmg  = fmaxf(cmg,  __shfl_xor_sync(0xffffffffu, cmg, 2));
        cmg8 = fmaxf(cmg8, __shfl_xor_sync(0xffffffffu, cmg8, 1));
        cmg8 = fmaxf(cmg8, __shfl_xor_sync(0xffffffffu, cmg8, 2));
        const float mn  = fmaxf(m_g,  cmg);
        const float mn8 = fmaxf(m_g8, cmg8);
        const float alg  = __expf(m_g  - mn);
        const float alg8 = __expf(m_g8 - mn8);
        m_g = mn; m_g8 = mn8;
        float sum = 0.f, sum8 = 0.f;
#pragma unroll
        for (int nt = 0; nt < 8; nt++) {
            s[nt][0] = __expf(s[nt][0] - mn);
            s[nt][1] = __expf(s[nt][1] - mn);
            s[nt][2] = __expf(s[nt][2] - mn8);
            s[nt][3] = __expf(s[nt][3] - mn8);
            sum  += s[nt][0] + s[nt][1];
            sum8 += s[nt][2] + s[nt][3];
        }
        sum  += __shfl_xor_sync(0xffffffffu, sum, 1);
        sum  += __shfl_xor_sync(0xffffffffu, sum, 2);
        sum8 += __shfl_xor_sync(0xffffffffu, sum8, 1);
        sum8 += __shfl_xor_sync(0xffffffffu, sum8, 2);
        l_g  = l_g  * alg  + sum;
        l_g8 = l_g8 * alg8 + sum8;
#pragma unroll
        for (int dt = 0; dt < 8; dt++) {
            o_acc[dt][0] *= alg;  o_acc[dt][1] *= alg;
            o_acc[dt][2] *= alg8; o_acc[dt][3] *= alg8;
        }

        // ---- P fragments from S accums ----
        uint32_t ph[4][4], pl[4][4];
#pragma unroll
        for (int ks = 0; ks < 4; ks++) {
            float r0, r1;
            ph[ks][0] = pack_hi(s[2*ks][0],   s[2*ks][1],   r0, r1); pl[ks][0] = pack_lo(r0, r1);
            ph[ks][1] = pack_hi(s[2*ks][2],   s[2*ks][3],   r0, r1); pl[ks][1] = pack_lo(r0, r1);
            ph[ks][2] = pack_hi(s[2*ks+1][0], s[2*ks+1][1], r0, r1); pl[ks][2] = pack_lo(r0, r1);
            ph[ks][3] = pack_hi(s[2*ks+1][2], s[2*ks+1][3], r0, r1); pl[ks][3] = pack_lo(r0, r1);
        }

        // ---- O += P @ V  (trans ldmatrix on natural V) ----
#pragma unroll
        for (int dt2 = 0; dt2 < 4; dt2++) {
#pragma unroll
            for (int ks = 0; ks < 4; ks++) {
                const uint32_t va = stB + 18432u + offVt
                    + (uint32_t)(ks*16*AST*2 + dt2*32);
                uint32_t vh4[4], vl4[4];
                LDSM4T(vh4, va);
                LDSM4T(vl4, va + 9216u);
                MMA_BF16(o_acc[2*dt2],   ph[ks], vh4);
                MMA_BF16(o_acc[2*dt2],   pl[ks], vh4);
                MMA_BF16(o_acc[2*dt2],   ph[ks], vl4);
                MMA_BF16(o_acc[2*dt2+1], ph[ks], &vh4[2]);
                MMA_BF16(o_acc[2*dt2+1], pl[ks], &vh4[2]);
                MMA_BF16(o_acc[2*dt2+1], ph[ks], &vl4[2]);
            }
        }
        __syncthreads();   // all reads of stage kc&1 done before refill
        KV_ISSUE(kc + 2);
    }

    // ---- epilogue: split-write a ----
    const float ig  = 1.f / l_g;
    const float ig8 = 1.f / l_g8;
    const int g = lane >> 2;
    const int r0 = nbase + qt*128 + wid*16 + g;
    const int cb = hoff + 2*(lane & 3);
#pragma unroll
    for (int dt = 0; dt < 8; dt++) {
        float v0x = o_acc[dt][0]*ig,  v0y = o_acc[dt][1]*ig;
        float v1x = o_acc[dt][2]*ig8, v1y = o_acc[dt][3]*ig8;
        float rx, ry;
        uint32_t h = pack_hi(v0x, v0y, rx, ry);
        uint32_t l = pack_lo(rx, ry);
        *(uint32_t*)(Ah + (size_t)r0*EMB + cb + dt*8) = h;
        *(uint32_t*)(Al + (size_t)r0*EMB + cb + dt*8) = l;
        h = pack_hi(v1x, v1y, rx, ry);
        l = pack_lo(rx, ry);
        *(uint32_t*)(Ah + (size_t)(r0+8)*EMB + cb + dt*8) = h;
        *(uint32_t*)(Al + (size_t)(r0+8)*EMB + cb + dt*8) = l;
    }
}

// ---------------- weight split / pack kernels --------------------------------
__global__ void split_w4(const float* __restrict__ src, bf16* __restrict__ h,
                         bf16* __restrict__ l, int n_per_layer, int dst_stride,
                         int dst_off) {
    int idx = blockIdx.x * blockDim.x + threadIdx.x;
    int total4 = (NLAYER * n_per_layer) >> 2;
    if (idx >= total4) return;
    int base = idx * 4;
    int layer = base / n_per_layer;
    int i = base - layer * n_per_layer;
    float4 v = *(const float4*)(src + base);
    float rx, ry;
    uint32_t h01 = pack_hi(v.x, v.y, rx, ry);
    uint32_t l01 = pack_lo(rx, ry);
    uint32_t h23 = pack_hi(v.z, v.w, rx, ry);
    uint32_t l23 = pack_lo(rx, ry);
    size_t d = (size_t)layer * dst_stride + dst_off + i;
    uint2 hv = {h01, h23}, lv = {l01, l23};
    *(uint2*)(h + d) = hv;
    *(uint2*)(l + d) = lv;
}

__global__ void pack_bqkv(const float* __restrict__ bq, const float* __restrict__ bk,
                          const float* __restrict__ bv, float* __restrict__ dst) {
    int idx = blockIdx.x * blockDim.x + threadIdx.x;
    if (idx >= NLAYER * 3 * EMB) return;
    int l = idx / (3*EMB);
    int n = idx - l * 3*EMB;
    float v;
    if (n < EMB)            v = bq[l*EMB + n];
    else if (n < 2*EMB)     v = bk[l*EMB + n - EMB];
    else                    v = bv[l*EMB + n - 2*EMB];
    dst[idx] = v;
}

// ---------------- positional encoding table --------------------------------
__global__ void pe_kernel(float* __restrict__ pe) {
    int idx = blockIdx.x * blockDim.x + threadIdx.x;
    if (idx >= PSEQ*EMB) return;
    int p = idx >> 9;
    int e = idx & 511;
    int i2 = e >> 1;
    float c = (float)(2*i2) * (-0.017988946039015984f);
    float freqf = (float)exp((double)c);
    float angf  = (float)p * freqf;
    double angle = (double)angf;
    pe[idx] = (e & 1) ? (float)cos(angle) : (float)sin(angle);
}

// ---------------- embedding: conv + linear + PE, writes x + split ------------
__global__ void embed_kernel(const float* __restrict__ data,
                             const float* __restrict__ cw,
                             const float* __restrict__ cb,
                             const float* __restrict__ lw,
                             const float* __restrict__ lb,
                             const float* __restrict__ pe,
                             float* __restrict__ x,
                             bf16* __restrict__ xh, bf16* __restrict__ xl) {
    int idx = blockIdx.x * blockDim.x + threadIdx.x;
    if (idx >= NTOK*EMB) return;
    int n = idx >> 9;
    int e = idx & 511;
    int b = n >> 10;
    int p = n & 1023;
    int pi = p >> 5, pj = p & 31;
    const float* dp = data + b*4096 + (pi*2)*64 + pj*2;
    float conv = dp[0]*cw[0] + dp[1]*cw[1] + dp[64]*cw[2] + dp[65]*cw[3] + cb[0];
    float v = conv * lw[e] + lb[e] + pe[p*EMB + e];
    x[idx] = v;
    bf16 h = __float2bfloat16(v);
    xh[idx] = h;
    xl[idx] = __float2bfloat16(v - __bfloat162float(h));
}

// ---------------- residual add + LayerNorm, writes x + split -----------------
__global__ __launch_bounds__(128)
void add_ln_kernel(float* __restrict__ x, const float* __restrict__ y,
                   const float* __restrict__ gam, const float* __restrict__ bet,
                   bf16* __restrict__ xh, bf16* __restrict__ xl) {
    const int row = blockIdx.x;
    const int tid = threadIdx.x;
    const int e = tid * 4;
    float4 xv = *(float4*)&x[(size_t)row*EMB + e];
    float4 yv = *(const float4*)&y[(size_t)row*EMB + e];
    float t0 = xv.x + yv.x, t1 = xv.y + yv.y, t2 = xv.z + yv.z, t3 = xv.w + yv.w;
    float s  = t0 + t1 + t2 + t3;
    float s2 = t0*t0 + t1*t1 + t2*t2 + t3*t3;
#pragma unroll
    for (int off = 16; off > 0; off >>= 1) {
        s  += __shfl_xor_sync(0xffffffffu, s,  off);
        s2 += __shfl_xor_sync(0xffffffffu, s2, off);
    }
    __shared__ float ws[4], ws2[4];
    int w = tid >> 5;
    if ((tid & 31) == 0) { ws[w] = s; ws2[w] = s2; }
    __syncthreads();
    float S  = ws[0] + ws[1] + ws[2] + ws[3];
    float S2 = ws2[0] + ws2[1] + ws2[2] + ws2[3];
    float mu  = S * (1.f/512.f);
    float var = S2 * (1.f/512.f) - mu*mu;
    float rs = rsqrtf(var + 1e-5f);
    float o0 = (t0 - mu)*rs*gam[e+0] + bet[e+0];
    float o1 = (t1 - mu)*rs*gam[e+1] + bet[e+1];
    float o2 = (t2 - mu)*rs*gam[e+2] + bet[e+2];
    float o3 = (t3 - mu)*rs*gam[e+3] + bet[e+3];
    float4 ov = {o0, o1, o2, o3};
    *(float4*)&x[(size_t)row*EMB + e] = ov;
    float rx, ry;
    uint32_t h01 = pack_hi(o0, o1, rx, ry);
    uint32_t l01 = pack_lo(rx, ry);
    uint32_t h23 = pack_hi(o2, o3, rx, ry);
    uint32_t l23 = pack_lo(rx, ry);
    uint2 hv = {h01, h23}, lv = {l01, l23};
    *(uint2*)(xh + (size_t)row*EMB + e) = hv;
    *(uint2*)(xl + (size_t)row*EMB + e) = lv;
}

// ---------------- mean pool + final linear ----------------------------------
__global__ __launch_bounds__(512)
void pool_head_kernel(const float* __restrict__ x, const float* __restrict__ Wc,
                      const float* __restrict__ bc, float* __restrict__ out) {
    const int b = blockIdx.x;
    const int e = threadIdx.x;
    float s = 0.f;
    const float* xp = x + (size_t)b*PSEQ*EMB + e;
    for (int p = 0; p < PSEQ; p++) s += xp[(size_t)p*EMB];
    float pooled = s * (1.f/1024.f);
    __shared__ float red[512];
    red[e] = pooled * Wc[e];
    __syncthreads();
    for (int st = 256; st > 0; st >>= 1) {
        if (e < st) red[e] += red[e + st];
        __syncthreads();
    }
    if (e == 0) out[b] = red[0] + bc[0];
}

// ---------------- driver -----------------------------------------------------
extern "C" void kernel_launch(void* const* d_in, const int* in_sizes, int n_in,
                              void* d_out, int out_size) {
    const float* data   = (const float*)d_in[0];
    const float* conv_w = (const float*)d_in[1];
    const float* conv_b = (const float*)d_in[2];
    const float* lin_w  = (const float*)d_in[3];
    const float* lin_b  = (const float*)d_in[4];
    const float* Wq     = (const float*)d_in[5];
    const float* bq     = (const float*)d_in[6];
    const float* Wk     = (const float*)d_in[7];
    const float* bk     = (const float*)d_in[8];
    const float* Wv     = (const float*)d_in[9];
    const float* bv     = (const float*)d_in[10];
    const float* Wo     = (const float*)d_in[11];
    const float* bo     = (const float*)d_in[12];
    const float* ln1_g  = (const float*)d_in[13];
    const float* ln1_b  = (const float*)d_in[14];
    const float* ln2_g  = (const float*)d_in[15];
    const float* ln2_b  = (const float*)d_in[16];
    const float* W1     = (const float*)d_in[17];
    const float* b1     = (const float*)d_in[18];
    const float* W2     = (const float*)d_in[19];
    const float* b2     = (const float*)d_in[20];
    const float* Wc     = (const float*)d_in[21];
    const float* bc     = (const float*)d_in[22];
    float* out = (float*)d_out;

    float *px, *pt, *ppe, *pbqkv;
    bf16 *pxh, *pxl, *pqkvh, *pqkvl, *pah, *pal, *phh, *phl;
    bf16 *pwqkvh, *pwqkvl, *pwoh, *pwol, *pw1h, *pw1l, *pw2h, *pw2l;
    cudaGetSymbolAddress((void**)&px,  g_x);
    cudaGetSymbolAddress((void**)&pt,  g_t);
    cudaGetSymbolAddress((void**)&ppe, g_pe);
    cudaGetSymbolAddress((void**)&pxh, g_xh);
    cudaGetSymbolAddress((void**)&pxl, g_xl);
    cudaGetSymbolAddress((void**)&pqkvh, g_qkvh);
    cudaGetSymbolAddress((void**)&pqkvl, g_qkvl);
    cudaGetSymbolAddress((void**)&pah, g_ah);
    cudaGetSymbolAddress((void**)&pal, g_al);
    cudaGetSymbolAddress((void**)&phh, g_hh);
    cudaGetSymbolAddress((void**)&phl, g_hl);
    cudaGetSymbolAddress((void**)&pwqkvh, g_wqkvh);
    cudaGetSymbolAddress((void**)&pwqkvl, g_wqkvl);
    cudaGetSymbolAddress((void**)&pwoh, g_woh);
    cudaGetSymbolAddress((void**)&pwol, g_wol);
    cudaGetSymbolAddress((void**)&pw1h, g_w1h);
    cudaGetSymbolAddress((void**)&pw1l, g_w1l);
    cudaGetSymbolAddress((void**)&pw2h, g_w2h);
    cudaGetSymbolAddress((void**)&pw2l, g_w2l);
    cudaGetSymbolAddress((void**)&pbqkv, g_bqkv);

    cudaFuncSetAttribute(gemm_bf<0,0>, cudaFuncAttributeMaxDynamicSharedMemorySize, GSMEM_BYTES);
    cudaFuncSetAttribute(gemm_bf<0,1>, cudaFuncAttributeMaxDynamicSharedMemorySize, GSMEM_BYTES);
    cudaFuncSetAttribute(gemm_bf<1,1>, cudaFuncAttributeMaxDynamicSharedMemorySize, GSMEM_BYTES);
    cudaFuncSetAttribute(attn_mma, cudaFuncAttributeMaxDynamicSharedMemorySize, ATT_SMEM_BYTES);

    // ---- weight/bias packing (once per call) ----
    const int EE = EMB*EMB;          // 262144
    const int FE = FFD*EMB;          // 1048576
    split_w4<<<(NLAYER*EE/4 + 255)/256, 256>>>(Wq, pwqkvh, pwqkvl, EE, 3*EE, 0);
    split_w4<<<(NLAYER*EE/4 + 255)/256, 256>>>(Wk, pwqkvh, pwqkvl, EE, 3*EE, EE);
    split_w4<<<(NLAYER*EE/4 + 255)/256, 256>>>(Wv, pwqkvh, pwqkvl, EE, 3*EE, 2*EE);
    split_w4<<<(NLAYER*EE/4 + 255)/256, 256>>>(Wo, pwoh, pwol, EE, EE, 0);
    split_w4<<<(NLAYER*FE/4 + 255)/256, 256>>>(W1, pw1h, pw1l, FE, FE, 0);
    split_w4<<<(NLAYER*FE/4 + 255)/256, 256>>>(W2, pw2h, pw2l, FE, FE, 0);
    pack_bqkv<<<(NLAYER*3*EMB + 255)/256, 256>>>(bq, bk, bv, pbqkv);

    pe_kernel<<<(PSEQ*EMB + 255)/256, 256>>>(ppe);
    embed_kernel<<<(NTOK*EMB + 255)/256, 256>>>(data, conv_w, conv_b, lin_w, lin_b,
                                                ppe, px, pxh, pxl);

    for (int l = 0; l < NLAYER; l++) {
        // fused QKV: [NTOK,512] @ [1536,512]^T -> split qkv
        gemm_bf<0,1><<<dim3(12,128), 256, GSMEM_BYTES>>>(
            pxh, pxl, pwqkvh + (size_t)l*3*EE, pwqkvl + (size_t)l*3*EE,
            pbqkv + l*3*EMB, nullptr, pqkvh, pqkvl, NTOK, 3*EMB, EMB);

        attn_mma<<<dim3(PSEQ/128, NHEAD, BATCH), 256, ATT_SMEM_BYTES>>>(
            pqkvh, pqkvl, pah, pal);

        gemm_bf<0,0><<<dim3(4,128), 256, GSMEM_BYTES>>>(
            pah, pal, pwoh + (size_t)l*EE, pwol + (size_t)l*EE,
            bo + l*EMB, pt, nullptr, nullptr, NTOK, EMB, EMB);
        add_ln_kernel<<<NTOK, 128>>>(px, pt, ln1_g + l*EMB, ln1_b + l*EMB, pxh, pxl);

        gemm_bf<1,1><<<dim3(16,128), 256, GSMEM_BYTES>>>(
            pxh, pxl, pw1h + (size_t)l*FE, pw1l + (size_t)l*FE,
            b1 + l*FFD, nullptr, phh, phl, NTOK, FFD, EMB);

        gemm_bf<0,0><<<dim3(4,128), 256, GSMEM_BYTES>>>(
            phh, phl, pw2h + (size_t)l*FE, pw2l + (size_t)l*FE,
            b2 + l*EMB, pt, nullptr, nullptr, NTOK, EMB, FFD);
        add_ln_kernel<<<NTOK, 128>>>(px, pt, ln2_g + l*EMB, ln2_b + l*EMB, pxh, pxl);
    }

    pool_head_kernel<<<BATCH, 512>>>(px, Wc, bc, out);
}